// round 1
// baseline (speedup 1.0000x reference)
#include <cuda_runtime.h>
#include <math.h>

#define BB 4
#define TT 2048
#define DD 1024
#define HH 8
#define DHH 128
#define TEE 2048
#define MM (BB*TT)          // 8192 rows
#define NCHUNK 16

// ---------------- device scratch (allocation-free) ----------------
__device__ float g_xn[MM*DD];
__device__ float g_q [MM*DD];
__device__ float g_k [MM*DD];
__device__ float g_v [MM*DD];
__device__ float g_y [MM*DD];
__device__ float g_act[MM*DD];
__device__ float g_att_part[NCHUNK*BB*HH*DHH*DHH];
__device__ float g_att[BB*HH*DHH*DHH];
__device__ float g_emb_act[BB*TEE];
__device__ float g_embout[BB*2*DD];

// ---------------- LayerNorm (pre-norm) ----------------
__global__ __launch_bounds__(256) void ln_kernel(const float* __restrict__ x,
                                                 const float* __restrict__ w,
                                                 const float* __restrict__ b,
                                                 float* __restrict__ out)
{
    int row = blockIdx.x;
    int tid = threadIdx.x;
    const float4* xr = (const float4*)(x + (size_t)row*DD);
    float4 v = xr[tid];
    float s  = v.x+v.y+v.z+v.w;
    float ss = v.x*v.x+v.y*v.y+v.z*v.z+v.w*v.w;
    #pragma unroll
    for (int o=16;o>0;o>>=1){ s += __shfl_down_sync(0xffffffffu,s,o); ss += __shfl_down_sync(0xffffffffu,ss,o); }
    __shared__ float sm[8], sm2[8];
    int wid = tid>>5, lane = tid&31;
    if (lane==0){ sm[wid]=s; sm2[wid]=ss; }
    __syncthreads();
    if (tid==0){
        float a=0.f, c=0.f;
        #pragma unroll
        for (int i=0;i<8;i++){ a+=sm[i]; c+=sm2[i]; }
        float mean = a*(1.0f/DD);
        float var  = c*(1.0f/DD) - mean*mean;
        sm[0]=mean; sm2[0]=rsqrtf(var+1e-5f);
    }
    __syncthreads();
    float mean=sm[0], rinv=sm2[0];
    float4 wv=((const float4*)w)[tid];
    float4 bv=((const float4*)b)[tid];
    float4 o;
    o.x=(v.x-mean)*rinv*wv.x+bv.x;
    o.y=(v.y-mean)*rinv*wv.y+bv.y;
    o.z=(v.z-mean)*rinv*wv.z+bv.z;
    o.w=(v.w-mean)*rinv*wv.w+bv.w;
    ((float4*)(out + (size_t)row*DD))[tid]=o;
}

// ---------------- SGEMM 128x128x16 tiles, fused epilogues ----------------
// mode 0: C = A@W + bias                     (Q)
// mode 1: C = A@W + bias + (1-mask)*(-1e6)   (K logits)
// mode 2: C = (A@W + bias) * mask            (V)
// mode 3: C = A@W + bias + resid             (OUT + residual x)
__global__ __launch_bounds__(256) void sgemm_k(const float* __restrict__ A,
                                               const float* __restrict__ W,
                                               const float* __restrict__ bias,
                                               const float* __restrict__ mask,
                                               const float* __restrict__ resid,
                                               float* __restrict__ C, int mode)
{
    const int Ndim=DD, Kdim=DD;
    __shared__ float As[16][132];   // transposed A tile: As[k][row]
    __shared__ float Bs[16][128];   // Bs[k][col]
    int tid = threadIdx.x;
    int tx = tid & 15, ty = tid >> 4;
    int m0 = blockIdx.y * 128;
    int n0 = blockIdx.x * 128;
    float acc[8][8];
    #pragma unroll
    for (int i=0;i<8;i++)
        #pragma unroll
        for (int j=0;j<8;j++) acc[i][j]=0.f;

    for (int k0=0;k0<Kdim;k0+=16){
        #pragma unroll
        for (int q=0;q<2;q++){
            int f  = tid*2+q;
            int r  = f >> 2;          // 0..127 (row)
            int kq = f & 3;           // 0..3 (k quad)
            float4 av = *(const float4*)(A + (size_t)(m0+r)*Kdim + k0 + kq*4);
            As[kq*4+0][r]=av.x; As[kq*4+1][r]=av.y; As[kq*4+2][r]=av.z; As[kq*4+3][r]=av.w;
        }
        #pragma unroll
        for (int q=0;q<2;q++){
            int f  = tid*2+q;
            int r  = f >> 5;          // 0..15
            int c4 = f & 31;
            *(float4*)&Bs[r][c4*4] = *(const float4*)(W + (size_t)(k0+r)*Ndim + n0 + c4*4);
        }
        __syncthreads();
        #pragma unroll
        for (int kk=0;kk<16;kk++){
            float a[8], bb[8];
            #pragma unroll
            for (int i=0;i<8;i++) a[i]=As[kk][ty*8+i];
            #pragma unroll
            for (int j=0;j<8;j++) bb[j]=Bs[kk][tx*8+j];
            #pragma unroll
            for (int i=0;i<8;i++)
                #pragma unroll
                for (int j=0;j<8;j++)
                    acc[i][j] = fmaf(a[i], bb[j], acc[i][j]);
        }
        __syncthreads();
    }
    #pragma unroll
    for (int i=0;i<8;i++){
        int row = m0 + ty*8 + i;
        float mrow = (mode==1 || mode==2) ? mask[row] : 0.f;
        #pragma unroll
        for (int j=0;j<8;j++){
            int col = n0 + tx*8 + j;
            float vv = acc[i][j] + bias[col];
            if (mode==1)      vv += (1.0f - mrow) * (-1000000.0f);
            else if (mode==2) vv *= mrow;
            else if (mode==3) vv += resid[(size_t)row*Ndim + col];
            C[(size_t)row*Ndim + col] = vv;
        }
    }
}

// ---------------- softmax over dh (one warp per (b,t,h)) ----------------
__global__ __launch_bounds__(256) void qsoftmax_k(float* __restrict__ q)
{
    int idx  = blockIdx.x*8 + (threadIdx.x>>5);   // (b*T+t)*H + h
    int lane = threadIdx.x & 31;
    float4* p = (float4*)(q + (size_t)idx*DHH);
    float4 v = p[lane];
    float m = fmaxf(fmaxf(v.x,v.y), fmaxf(v.z,v.w));
    #pragma unroll
    for (int o=16;o>0;o>>=1) m = fmaxf(m, __shfl_xor_sync(0xffffffffu,m,o));
    v.x=expf(v.x-m); v.y=expf(v.y-m); v.z=expf(v.z-m); v.w=expf(v.w-m);
    float s = v.x+v.y+v.z+v.w;
    #pragma unroll
    for (int o=16;o>0;o>>=1) s += __shfl_xor_sync(0xffffffffu,s,o);
    float r = 1.0f/s;
    v.x*=r; v.y*=r; v.z*=r; v.w*=r;
    p[lane]=v;
}

// ---------------- softmax over time (per (b, channel)) ----------------
// block (32,8): 32 consecutive channels (coalesced), 8 t-strips
__global__ void ksoftmax_k(float* __restrict__ k)
{
    int b = blockIdx.x >> 5;
    int g = blockIdx.x & 31;
    int tx = threadIdx.x, ty = threadIdx.y;
    int d = g*32 + tx;
    float m = -INFINITY, s = 0.f;
    for (int t=ty; t<TT; t+=8){
        float val = k[((size_t)b*TT + t)*DD + d];
        float nm = fmaxf(m, val);
        s = s*expf(m-nm) + expf(val-nm);
        m = nm;
    }
    __shared__ float smax[8][32], ssum[8][32];
    smax[ty][tx]=m; ssum[ty][tx]=s;
    __syncthreads();
    if (ty==0){
        float M=smax[0][tx], S=ssum[0][tx];
        #pragma unroll
        for (int i=1;i<8;i++){
            float m2=smax[i][tx], s2=ssum[i][tx];
            float nm=fmaxf(M,m2);
            S = S*expf(M-nm) + s2*expf(m2-nm);
            M = nm;
        }
        smax[0][tx]=M; ssum[0][tx]=1.0f/S;
    }
    __syncthreads();
    float M=smax[0][tx], R=ssum[0][tx];
    for (int t=ty; t<TT; t+=8){
        size_t i = ((size_t)b*TT + t)*DD + d;
        k[i] = expf(k[i]-M)*R;
    }
}

// ---------------- att partial: K^T V over a T-chunk ----------------
__global__ __launch_bounds__(256) void att_partial_k(const float* __restrict__ k,
                                                     const float* __restrict__ v,
                                                     float* __restrict__ part)
{
    int chunk = blockIdx.x;           // 0..15
    int bh    = blockIdx.y;           // 0..31
    int b = bh >> 3, h = bh & 7;
    int t0 = chunk*128;
    __shared__ float ks[16][128];
    __shared__ float vs[16][128];
    int tid=threadIdx.x, tx=tid&15, ty=tid>>4;
    float acc[8][8];
    #pragma unroll
    for (int i=0;i<8;i++)
        #pragma unroll
        for (int j=0;j<8;j++) acc[i][j]=0.f;

    for (int tt=0;tt<128;tt+=16){
        #pragma unroll
        for (int q=0;q<2;q++){
            int f=tid*2+q; int r=f>>5; int c4=f&31;
            size_t base = ((size_t)(b*TT + t0+tt + r))*DD + h*DHH + c4*4;
            *(float4*)&ks[r][c4*4] = *(const float4*)(k + base);
            *(float4*)&vs[r][c4*4] = *(const float4*)(v + base);
        }
        __syncthreads();
        #pragma unroll
        for (int kk=0;kk<16;kk++){
            float a[8], bb[8];
            #pragma unroll
            for (int i=0;i<8;i++) a[i]=ks[kk][ty*8+i];
            #pragma unroll
            for (int j=0;j<8;j++) bb[j]=vs[kk][tx*8+j];
            #pragma unroll
            for (int i=0;i<8;i++)
                #pragma unroll
                for (int j=0;j<8;j++)
                    acc[i][j] = fmaf(a[i], bb[j], acc[i][j]);
        }
        __syncthreads();
    }
    float* dst = part + ((size_t)chunk*(BB*HH) + bh)*DHH*DHH;
    #pragma unroll
    for (int i=0;i<8;i++)
        #pragma unroll
        for (int j=0;j<8;j++)
            dst[(ty*8+i)*DHH + tx*8+j] = acc[i][j];
}

__global__ void att_reduce_k(const float* __restrict__ part, float* __restrict__ att)
{
    int i = blockIdx.x*256 + threadIdx.x;   // < 524288
    float s = 0.f;
    #pragma unroll
    for (int c=0;c<NCHUNK;c++) s += part[(size_t)c*(BB*HH*DHH*DHH) + i];
    att[i]=s;
}

// ---------------- y = Q @ att ----------------
__global__ __launch_bounds__(256) void y_gemm_k(const float* __restrict__ q,
                                                const float* __restrict__ att,
                                                float* __restrict__ y)
{
    int tch = blockIdx.x;   // 0..15
    int bh  = blockIdx.y;   // 0..31
    int b = bh >> 3, h = bh & 7;
    int t0 = tch*128;
    __shared__ float qs[32][132];   // transposed: qs[d][t]
    __shared__ float as[32][128];   // as[d][l]
    int tid=threadIdx.x, tx=tid&15, ty=tid>>4;
    float acc[8][8];
    #pragma unroll
    for (int i=0;i<8;i++)
        #pragma unroll
        for (int j=0;j<8;j++) acc[i][j]=0.f;

    for (int d0=0; d0<DHH; d0+=32){
        #pragma unroll
        for (int qq=0;qq<4;qq++){
            int f = tid*4+qq;
            int r = f>>3;           // t row 0..127
            int c4 = f&7;           // d quad
            float4 v4 = *(const float4*)(q + ((size_t)(b*TT)+t0+r)*DD + h*DHH + d0 + c4*4);
            qs[c4*4+0][r]=v4.x; qs[c4*4+1][r]=v4.y; qs[c4*4+2][r]=v4.z; qs[c4*4+3][r]=v4.w;
        }
        #pragma unroll
        for (int qq=0;qq<4;qq++){
            int f = tid*4+qq;
            int r = f>>5; int c4=f&31;
            *(float4*)&as[r][c4*4] = *(const float4*)(att + ((size_t)bh*DHH + d0 + r)*DHH + c4*4);
        }
        __syncthreads();
        #pragma unroll
        for (int kk=0;kk<32;kk++){
            float a[8], bb[8];
            #pragma unroll
            for (int i=0;i<8;i++) a[i]=qs[kk][ty*8+i];
            #pragma unroll
            for (int j=0;j<8;j++) bb[j]=as[kk][tx*8+j];
            #pragma unroll
            for (int i=0;i<8;i++)
                #pragma unroll
                for (int j=0;j<8;j++)
                    acc[i][j] = fmaf(a[i], bb[j], acc[i][j]);
        }
        __syncthreads();
    }
    #pragma unroll
    for (int i=0;i<8;i++)
        #pragma unroll
        for (int j=0;j<8;j++)
            y[((size_t)(b*TT)+t0+ty*8+i)*DD + h*DHH + tx*8+j] = acc[i][j];
}

// ---------------- emb path ----------------
__global__ void silu_emb_k(const float* __restrict__ emb, float* __restrict__ out)
{
    int i = blockIdx.x*256 + threadIdx.x;   // < 8192
    float e = emb[i];
    out[i] = e / (1.0f + expf(-e));
}

__global__ __launch_bounds__(256) void emb_gemm_k(const float* __restrict__ ea,
                                                  const float* __restrict__ W,
                                                  const float* __restrict__ bias,
                                                  float* __restrict__ out)
{
    int n = blockIdx.x*256 + threadIdx.x;   // 0..2047
    int b = blockIdx.y;
    const float* e = ea + b*TEE;
    float acc = 0.f;
    #pragma unroll 8
    for (int t=0;t<TEE;t++)
        acc = fmaf(e[t], W[(size_t)t*(2*DD) + n], acc);
    out[b*(2*DD) + n] = acc + bias[n];
}

// ---------------- LN2 + FiLM + SiLU ----------------
__global__ __launch_bounds__(256) void film_k(const float* __restrict__ y,
                                              const float* __restrict__ w2,
                                              const float* __restrict__ b2,
                                              const float* __restrict__ embout,
                                              float* __restrict__ act)
{
    int row = blockIdx.x;            // b*T + t
    int b = row / TT;
    int tid = threadIdx.x;
    const float4* yr = (const float4*)(y + (size_t)row*DD);
    float4 v = yr[tid];
    float s  = v.x+v.y+v.z+v.w;
    float ss = v.x*v.x+v.y*v.y+v.z*v.z+v.w*v.w;
    #pragma unroll
    for (int o=16;o>0;o>>=1){ s += __shfl_down_sync(0xffffffffu,s,o); ss += __shfl_down_sync(0xffffffffu,ss,o); }
    __shared__ float sm[8], sm2[8];
    int wid = tid>>5, lane = tid&31;
    if (lane==0){ sm[wid]=s; sm2[wid]=ss; }
    __syncthreads();
    if (tid==0){
        float a=0.f, c=0.f;
        #pragma unroll
        for (int i=0;i<8;i++){ a+=sm[i]; c+=sm2[i]; }
        float mean = a*(1.0f/DD);
        float var  = c*(1.0f/DD) - mean*mean;
        sm[0]=mean; sm2[0]=rsqrtf(var+1e-5f);
    }
    __syncthreads();
    float mean=sm[0], rinv=sm2[0];
    float4 wv=((const float4*)w2)[tid];
    float4 bv=((const float4*)b2)[tid];
    float4 sc=((const float4*)(embout + (size_t)b*(2*DD)))[tid];
    float4 sh=((const float4*)(embout + (size_t)b*(2*DD) + DD))[tid];
    float4 o;
    float h;
    h=(v.x-mean)*rinv*wv.x+bv.x; h=h*(1.0f+sc.x)+sh.x; o.x=h/(1.0f+expf(-h));
    h=(v.y-mean)*rinv*wv.y+bv.y; h=h*(1.0f+sc.y)+sh.y; o.y=h/(1.0f+expf(-h));
    h=(v.z-mean)*rinv*wv.z+bv.z; h=h*(1.0f+sc.z)+sh.z; o.z=h/(1.0f+expf(-h));
    h=(v.w-mean)*rinv*wv.w+bv.w; h=h*(1.0f+sc.w)+sh.w; o.w=h/(1.0f+expf(-h));
    ((float4*)(act + (size_t)row*DD))[tid]=o;
}

// ---------------- launch ----------------
extern "C" void kernel_launch(void* const* d_in, const int* in_sizes, int n_in,
                              void* d_out, int out_size)
{
    (void)in_sizes; (void)n_in; (void)out_size;
    const float* x     = (const float*)d_in[0];
    const float* emb   = (const float*)d_in[1];
    const float* mask  = (const float*)d_in[2];
    const float* ln_w  = (const float*)d_in[4];
    const float* ln_b  = (const float*)d_in[5];
    const float* Wq    = (const float*)d_in[6];
    const float* bq    = (const float*)d_in[7];
    const float* Wk    = (const float*)d_in[8];
    const float* bk    = (const float*)d_in[9];
    const float* Wv    = (const float*)d_in[10];
    const float* bv    = (const float*)d_in[11];
    const float* W_emb = (const float*)d_in[12];
    const float* b_emb = (const float*)d_in[13];
    const float* ln2_w = (const float*)d_in[14];
    const float* ln2_b = (const float*)d_in[15];
    const float* W_out = (const float*)d_in[16];
    const float* b_out = (const float*)d_in[17];
    float* out = (float*)d_out;

    float *p_xn, *p_q, *p_k, *p_v, *p_y, *p_act, *p_attp, *p_att, *p_emba, *p_embout;
    cudaGetSymbolAddress((void**)&p_xn,     g_xn);
    cudaGetSymbolAddress((void**)&p_q,      g_q);
    cudaGetSymbolAddress((void**)&p_k,      g_k);
    cudaGetSymbolAddress((void**)&p_v,      g_v);
    cudaGetSymbolAddress((void**)&p_y,      g_y);
    cudaGetSymbolAddress((void**)&p_act,    g_act);
    cudaGetSymbolAddress((void**)&p_attp,   g_att_part);
    cudaGetSymbolAddress((void**)&p_att,    g_att);
    cudaGetSymbolAddress((void**)&p_emba,   g_emb_act);
    cudaGetSymbolAddress((void**)&p_embout, g_embout);

    ln_kernel<<<MM, 256>>>(x, ln_w, ln_b, p_xn);
    silu_emb_k<<<(BB*TEE)/256, 256>>>(emb, p_emba);

    sgemm_k<<<dim3(DD/128, MM/128), 256>>>(p_xn, Wq, bq, nullptr, nullptr, p_q, 0);
    sgemm_k<<<dim3(DD/128, MM/128), 256>>>(p_xn, Wk, bk, mask,   nullptr, p_k, 1);
    sgemm_k<<<dim3(DD/128, MM/128), 256>>>(p_xn, Wv, bv, mask,   nullptr, p_v, 2);

    qsoftmax_k<<<(MM*HH)/8, 256>>>(p_q);
    ksoftmax_k<<<BB*32, dim3(32,8)>>>(p_k);

    att_partial_k<<<dim3(NCHUNK, BB*HH), 256>>>(p_k, p_v, p_attp);
    att_reduce_k<<<(BB*HH*DHH*DHH)/256, 256>>>(p_attp, p_att);

    emb_gemm_k<<<dim3((2*DD)/256, BB), 256>>>(p_emba, W_emb, b_emb, p_embout);

    y_gemm_k<<<dim3(TT/128, BB*HH), 256>>>(p_q, p_att, p_y);

    film_k<<<MM, 256>>>(p_y, ln2_w, ln2_b, p_embout, p_act);

    sgemm_k<<<dim3(DD/128, MM/128), 256>>>(p_act, W_out, b_out, nullptr, x, out, 3);
}

// round 3
// speedup vs baseline: 1.8726x; 1.8726x over previous
#include <cuda_runtime.h>
#include <cuda_bf16.h>
#include <math.h>
#include <stdint.h>

#define BB 4
#define TT 2048
#define DD 1024
#define HH 8
#define DHH 128
#define TEE 2048
#define MM (BB*TT)          // 8192 rows
#define NCHUNK 16

__device__ __forceinline__ uint32_t smem_to_u32(const void* p) {
    uint32_t a;
    asm("{ .reg .u64 t; cvta.to.shared.u64 t, %1; cvt.u32.u64 %0, t; }" : "=r"(a) : "l"(p));
    return a;
}

#define LDSM4(R, addr) \
    asm volatile("ldmatrix.sync.aligned.m8n8.x4.shared.b16 {%0,%1,%2,%3}, [%4];" \
        : "=r"((R)[0]), "=r"((R)[1]), "=r"((R)[2]), "=r"((R)[3]) : "r"(addr))

#define MMA_BF16(c, a, b0, b1) \
    asm volatile("mma.sync.aligned.m16n8k16.row.col.f32.bf16.bf16.f32 " \
        "{%0,%1,%2,%3}, {%4,%5,%6,%7}, {%8,%9}, {%0,%1,%2,%3};" \
        : "+f"((c)[0]), "+f"((c)[1]), "+f"((c)[2]), "+f"((c)[3]) \
        : "r"((a)[0]), "r"((a)[1]), "r"((a)[2]), "r"((a)[3]), "r"(b0), "r"(b1))

// ======================= device scratch =======================
__device__ __nv_bfloat16 g_xnhi[MM*DD];
__device__ __nv_bfloat16 g_xnlo[MM*DD];
__device__ __nv_bfloat16 g_acthi[MM*DD];
__device__ __nv_bfloat16 g_actlo[MM*DD];
__device__ __nv_bfloat16 g_wthi[4][DD*DD];
__device__ __nv_bfloat16 g_wtlo[4][DD*DD];
__device__ float g_q [MM*DD];
__device__ float g_k [MM*DD];
__device__ float g_v [MM*DD];
__device__ float g_y [MM*DD];
__device__ float g_att_part[NCHUNK*BB*HH*DHH*DHH];
__device__ float g_att[BB*HH*DHH*DHH];
__device__ float g_emb_act[BB*TEE];
__device__ float g_embout[BB*2*DD];

__device__ __forceinline__ void split_store4(__nv_bfloat16* ph, __nv_bfloat16* pl, float4 v) {
    __nv_bfloat162 h0 = __floats2bfloat162_rn(v.x, v.y);
    __nv_bfloat162 h1 = __floats2bfloat162_rn(v.z, v.w);
    float rx = v.x - __bfloat162float(h0.x);
    float ry = v.y - __bfloat162float(h0.y);
    float rz = v.z - __bfloat162float(h1.x);
    float rw = v.w - __bfloat162float(h1.y);
    __nv_bfloat162 l0 = __floats2bfloat162_rn(rx, ry);
    __nv_bfloat162 l1 = __floats2bfloat162_rn(rz, rw);
    uint2 uh; uh.x = *(uint32_t*)&h0; uh.y = *(uint32_t*)&h1;
    uint2 ul; ul.x = *(uint32_t*)&l0; ul.y = *(uint32_t*)&l1;
    *(uint2*)ph = uh;
    *(uint2*)pl = ul;
}

// ======================= LayerNorm -> bf16 hi/lo =======================
__global__ __launch_bounds__(256) void ln_kernel(const float* __restrict__ x,
                                                 const float* __restrict__ w,
                                                 const float* __restrict__ b,
                                                 __nv_bfloat16* __restrict__ outh,
                                                 __nv_bfloat16* __restrict__ outl)
{
    int row = blockIdx.x;
    int tid = threadIdx.x;
    const float4* xr = (const float4*)(x + (size_t)row*DD);
    float4 v = xr[tid];
    float s  = v.x+v.y+v.z+v.w;
    float ss = v.x*v.x+v.y*v.y+v.z*v.z+v.w*v.w;
    #pragma unroll
    for (int o=16;o>0;o>>=1){ s += __shfl_down_sync(0xffffffffu,s,o); ss += __shfl_down_sync(0xffffffffu,ss,o); }
    __shared__ float sm[8], sm2[8];
    int wid = tid>>5, lane = tid&31;
    if (lane==0){ sm[wid]=s; sm2[wid]=ss; }
    __syncthreads();
    if (tid==0){
        float a=0.f, c=0.f;
        #pragma unroll
        for (int i=0;i<8;i++){ a+=sm[i]; c+=sm2[i]; }
        float mean = a*(1.0f/DD);
        float var  = c*(1.0f/DD) - mean*mean;
        sm[0]=mean; sm2[0]=rsqrtf(var+1e-5f);
    }
    __syncthreads();
    float mean=sm[0], rinv=sm2[0];
    float4 wv=((const float4*)w)[tid];
    float4 bv=((const float4*)b)[tid];
    float4 o;
    o.x=(v.x-mean)*rinv*wv.x+bv.x;
    o.y=(v.y-mean)*rinv*wv.y+bv.y;
    o.z=(v.z-mean)*rinv*wv.z+bv.z;
    o.w=(v.w-mean)*rinv*wv.w+bv.w;
    split_store4(outh + (size_t)row*DD + tid*4, outl + (size_t)row*DD + tid*4, o);
}

// ======================= weight transpose + bf16 split =======================
__global__ __launch_bounds__(1024) void wsplit_k(const float* __restrict__ W,
                                                 __nv_bfloat16* __restrict__ Thi,
                                                 __nv_bfloat16* __restrict__ Tlo)
{
    __shared__ float t[32][33];
    int tx = threadIdx.x, ty = threadIdx.y;
    t[ty][tx] = W[(size_t)(blockIdx.y*32+ty)*DD + blockIdx.x*32+tx];
    __syncthreads();
    int n = blockIdx.x*32 + ty;
    int k = blockIdx.y*32 + tx;
    float v = t[tx][ty];
    __nv_bfloat16 h = __float2bfloat16(v);
    Thi[(size_t)n*DD + k] = h;
    Tlo[(size_t)n*DD + k] = __float2bfloat16(v - __bfloat162float(h));
}

// ======================= HMMA GEMM: C[8192x1024] = A @ W (+ epilogue) =======
// A as bf16 hi/lo [M,K] row-major; W pre-transposed bf16 hi/lo [N,K].
// mode 0: +bias | 1: +bias+(1-mask)*-1e6 | 2: (+bias)*mask | 3: +bias+resid
#define LDSE   40                       // smem row stride in elements (80 B)
#define TILE_E (128*LDSE)               // 5120 elems per tile
#define BUF_E  (4*TILE_E)               // Ahi,Alo,Bhi,Blo
#define HG_SMEM (2*BUF_E*2)             // bytes = 81920

__global__ __launch_bounds__(512, 1) void hgemm_k(
        const __nv_bfloat16* __restrict__ Ahi, const __nv_bfloat16* __restrict__ Alo,
        const __nv_bfloat16* __restrict__ Bhi, const __nv_bfloat16* __restrict__ Blo,
        const float* __restrict__ bias, const float* __restrict__ mask,
        const float* __restrict__ resid, float* __restrict__ C, int mode)
{
    extern __shared__ __nv_bfloat16 smbuf[];
    const int tid  = threadIdx.x;
    const int lane = tid & 31;
    const int w    = tid >> 5;
    const int wm   = w >> 2;        // 0..3
    const int wn   = w & 3;         // 0..3
    const int m0 = blockIdx.y * 128;
    const int n0 = blockIdx.x * 128;

    // loader mapping: each thread loads one 16B chunk from each of 4 tiles
    const int lr = tid >> 2;        // row 0..127
    const int lc = (tid & 3) * 8;   // elem col 0/8/16/24
    const __nv_bfloat16* gsrc0 = Ahi + (size_t)(m0+lr)*DD + lc;
    const __nv_bfloat16* gsrc1 = Alo + (size_t)(m0+lr)*DD + lc;
    const __nv_bfloat16* gsrc2 = Bhi + (size_t)(n0+lr)*DD + lc;
    const __nv_bfloat16* gsrc3 = Blo + (size_t)(n0+lr)*DD + lc;

    const uint32_t smb = smem_to_u32(smbuf);
    const int arow  = wm*32 + (lane & 7) + ((lane >> 3) & 1) * 8;
    const int akoff = ((lane >> 4) & 1) * 8;
    const int brow  = wn*32 + (lane & 7) + ((lane >> 4) & 1) * 8;
    const int bkoff = ((lane >> 3) & 1) * 8;

    float acc[2][4][4];
    #pragma unroll
    for (int i=0;i<2;i++)
        #pragma unroll
        for (int j=0;j<4;j++)
            #pragma unroll
            for (int l=0;l<4;l++) acc[i][j][l]=0.f;

    uint4 pf0, pf1, pf2, pf3;
    pf0 = *(const uint4*)gsrc0; pf1 = *(const uint4*)gsrc1;
    pf2 = *(const uint4*)gsrc2; pf3 = *(const uint4*)gsrc3;
    {
        __nv_bfloat16* d = smbuf + lr*LDSE + lc;
        *(uint4*)(d + 0*TILE_E) = pf0;
        *(uint4*)(d + 1*TILE_E) = pf1;
        *(uint4*)(d + 2*TILE_E) = pf2;
        *(uint4*)(d + 3*TILE_E) = pf3;
    }
    __syncthreads();

    for (int kc = 0; kc < 32; kc++) {
        if (kc < 31) {
            int k0 = (kc+1)*32;
            pf0 = *(const uint4*)(gsrc0 + k0);
            pf1 = *(const uint4*)(gsrc1 + k0);
            pf2 = *(const uint4*)(gsrc2 + k0);
            pf3 = *(const uint4*)(gsrc3 + k0);
        }
        uint32_t base = smb + (kc & 1) * (BUF_E*2);
        #pragma unroll
        for (int ks = 0; ks < 2; ks++) {
            uint32_t ah[2][4], al[2][4];
            #pragma unroll
            for (int mt = 0; mt < 2; mt++) {
                uint32_t ra = base + ((arow + mt*16)*LDSE + ks*16 + akoff) * 2;
                LDSM4(ah[mt], ra);
                LDSM4(al[mt], ra + TILE_E*2);
            }
            uint32_t bh[2][4], bl[2][4];
            #pragma unroll
            for (int nb = 0; nb < 2; nb++) {
                uint32_t rb = base + 2*TILE_E*2 + ((brow + nb*16)*LDSE + ks*16 + bkoff) * 2;
                LDSM4(bh[nb], rb);
                LDSM4(bl[nb], rb + TILE_E*2);
            }
            #pragma unroll
            for (int mt = 0; mt < 2; mt++) {
                #pragma unroll
                for (int nt = 0; nt < 4; nt++) {
                    int nb = nt >> 1, sub = (nt & 1) * 2;
                    MMA_BF16(acc[mt][nt], ah[mt], bh[nb][sub], bh[nb][sub+1]);
                    MMA_BF16(acc[mt][nt], ah[mt], bl[nb][sub], bl[nb][sub+1]);
                    MMA_BF16(acc[mt][nt], al[mt], bh[nb][sub], bh[nb][sub+1]);
                }
            }
        }
        if (kc < 31) {
            __syncthreads();
            __nv_bfloat16* d = smbuf + ((kc+1)&1)*BUF_E + lr*LDSE + lc;
            *(uint4*)(d + 0*TILE_E) = pf0;
            *(uint4*)(d + 1*TILE_E) = pf1;
            *(uint4*)(d + 2*TILE_E) = pf2;
            *(uint4*)(d + 3*TILE_E) = pf3;
            __syncthreads();
        }
    }

    // ---------------- epilogue ----------------
    const int t4 = lane >> 2;
    const int t2 = (lane & 3) * 2;
    #pragma unroll
    for (int mt = 0; mt < 2; mt++) {
        int row0 = m0 + wm*32 + mt*16 + t4;
        int row1 = row0 + 8;
        float m0v = 0.f, m1v = 0.f;
        if (mode == 1 || mode == 2) { m0v = mask[row0]; m1v = mask[row1]; }
        float add0 = (mode==1) ? (1.0f-m0v)*(-1000000.0f) : 0.f;
        float add1 = (mode==1) ? (1.0f-m1v)*(-1000000.0f) : 0.f;
        float mul0 = (mode==2) ? m0v : 1.f;
        float mul1 = (mode==2) ? m1v : 1.f;
        #pragma unroll
        for (int nt = 0; nt < 4; nt++) {
            int col = n0 + wn*32 + nt*8 + t2;
            float2 bi = *(const float2*)(bias + col);
            float a0 = acc[mt][nt][0] + bi.x;
            float a1 = acc[mt][nt][1] + bi.y;
            float a2 = acc[mt][nt][2] + bi.x;
            float a3 = acc[mt][nt][3] + bi.y;
            if (mode == 1) { a0 += add0; a1 += add0; a2 += add1; a3 += add1; }
            else if (mode == 2) { a0 *= mul0; a1 *= mul0; a2 *= mul1; a3 *= mul1; }
            else if (mode == 3) {
                float2 r0 = *(const float2*)(resid + (size_t)row0*DD + col);
                float2 r1 = *(const float2*)(resid + (size_t)row1*DD + col);
                a0 += r0.x; a1 += r0.y; a2 += r1.x; a3 += r1.y;
            }
            float2 o0 = make_float2(a0, a1);
            float2 o1 = make_float2(a2, a3);
            *(float2*)(C + (size_t)row0*DD + col) = o0;
            *(float2*)(C + (size_t)row1*DD + col) = o1;
        }
    }
}

// ======================= softmax over dh =======================
__global__ __launch_bounds__(256) void qsoftmax_k(float* __restrict__ q)
{
    int idx  = blockIdx.x*8 + (threadIdx.x>>5);
    int lane = threadIdx.x & 31;
    float4* p = (float4*)(q + (size_t)idx*DHH);
    float4 v = p[lane];
    float m = fmaxf(fmaxf(v.x,v.y), fmaxf(v.z,v.w));
    #pragma unroll
    for (int o=16;o>0;o>>=1) m = fmaxf(m, __shfl_xor_sync(0xffffffffu,m,o));
    v.x=expf(v.x-m); v.y=expf(v.y-m); v.z=expf(v.z-m); v.w=expf(v.w-m);
    float s = v.x+v.y+v.z+v.w;
    #pragma unroll
    for (int o=16;o>0;o>>=1) s += __shfl_xor_sync(0xffffffffu,s,o);
    float r = 1.0f/s;
    v.x*=r; v.y*=r; v.z*=r; v.w*=r;
    p[lane]=v;
}

// ======================= softmax over time =======================
__global__ void ksoftmax_k(float* __restrict__ k)
{
    int b = blockIdx.x >> 5;
    int g = blockIdx.x & 31;
    int tx = threadIdx.x, ty = threadIdx.y;
    int d = g*32 + tx;
    float m = -INFINITY, s = 0.f;
    for (int t=ty; t<TT; t+=8){
        float val = k[((size_t)b*TT + t)*DD + d];
        float nm = fmaxf(m, val);
        s = s*expf(m-nm) + expf(val-nm);
        m = nm;
    }
    __shared__ float smax[8][32], ssum[8][32];
    smax[ty][tx]=m; ssum[ty][tx]=s;
    __syncthreads();
    if (ty==0){
        float M=smax[0][tx], S=ssum[0][tx];
        #pragma unroll
        for (int i=1;i<8;i++){
            float m2=smax[i][tx], s2=ssum[i][tx];
            float nm=fmaxf(M,m2);
            S = S*expf(M-nm) + s2*expf(m2-nm);
            M = nm;
        }
        smax[0][tx]=M; ssum[0][tx]=1.0f/S;
    }
    __syncthreads();
    float M=smax[0][tx], R=ssum[0][tx];
    for (int t=ty; t<TT; t+=8){
        size_t i = ((size_t)b*TT + t)*DD + d;
        k[i] = expf(k[i]-M)*R;
    }
}

// ======================= att partial: K^T V over a T-chunk =======================
__global__ __launch_bounds__(256) void att_partial_k(const float* __restrict__ k,
                                                     const float* __restrict__ v,
                                                     float* __restrict__ part)
{
    int chunk = blockIdx.x;
    int bh    = blockIdx.y;
    int b = bh >> 3, h = bh & 7;
    int t0 = chunk*128;
    __shared__ float ks[16][128];
    __shared__ float vs[16][128];
    int tid=threadIdx.x, tx=tid&15, ty=tid>>4;
    float acc[8][8];
    #pragma unroll
    for (int i=0;i<8;i++)
        #pragma unroll
        for (int j=0;j<8;j++) acc[i][j]=0.f;

    for (int tt=0;tt<128;tt+=16){
        #pragma unroll
        for (int q=0;q<2;q++){
            int f=tid*2+q; int r=f>>5; int c4=f&31;
            size_t base = ((size_t)(b*TT + t0+tt + r))*DD + h*DHH + c4*4;
            *(float4*)&ks[r][c4*4] = *(const float4*)(k + base);
            *(float4*)&vs[r][c4*4] = *(const float4*)(v + base);
        }
        __syncthreads();
        #pragma unroll
        for (int kk=0;kk<16;kk++){
            float a[8], bb[8];
            #pragma unroll
            for (int i=0;i<8;i++) a[i]=ks[kk][ty*8+i];
            #pragma unroll
            for (int j=0;j<8;j++) bb[j]=vs[kk][tx*8+j];
            #pragma unroll
            for (int i=0;i<8;i++)
                #pragma unroll
                for (int j=0;j<8;j++)
                    acc[i][j] = fmaf(a[i], bb[j], acc[i][j]);
        }
        __syncthreads();
    }
    float* dst = part + ((size_t)chunk*(BB*HH) + bh)*DHH*DHH;
    #pragma unroll
    for (int i=0;i<8;i++)
        #pragma unroll
        for (int j=0;j<8;j++)
            dst[(ty*8+i)*DHH + tx*8+j] = acc[i][j];
}

__global__ void att_reduce_k(const float* __restrict__ part, float* __restrict__ att)
{
    int i = blockIdx.x*256 + threadIdx.x;
    float s = 0.f;
    #pragma unroll
    for (int c=0;c<NCHUNK;c++) s += part[(size_t)c*(BB*HH*DHH*DHH) + i];
    att[i]=s;
}

// ======================= y = Q @ att =======================
__global__ __launch_bounds__(256) void y_gemm_k(const float* __restrict__ q,
                                                const float* __restrict__ att,
                                                float* __restrict__ y)
{
    int tch = blockIdx.x;
    int bh  = blockIdx.y;
    int b = bh >> 3, h = bh & 7;
    int t0 = tch*128;
    __shared__ float qs[32][132];
    __shared__ float as[32][128];
    int tid=threadIdx.x, tx=tid&15, ty=tid>>4;
    float acc[8][8];
    #pragma unroll
    for (int i=0;i<8;i++)
        #pragma unroll
        for (int j=0;j<8;j++) acc[i][j]=0.f;

    for (int d0=0; d0<DHH; d0+=32){
        #pragma unroll
        for (int qq=0;qq<4;qq++){
            int f = tid*4+qq;
            int r = f>>3;
            int c4 = f&7;
            float4 v4 = *(const float4*)(q + ((size_t)(b*TT)+t0+r)*DD + h*DHH + d0 + c4*4);
            qs[c4*4+0][r]=v4.x; qs[c4*4+1][r]=v4.y; qs[c4*4+2][r]=v4.z; qs[c4*4+3][r]=v4.w;
        }
        #pragma unroll
        for (int qq=0;qq<4;qq++){
            int f = tid*4+qq;
            int r = f>>5; int c4=f&31;
            *(float4*)&as[r][c4*4] = *(const float4*)(att + ((size_t)bh*DHH + d0 + r)*DHH + c4*4);
        }
        __syncthreads();
        #pragma unroll
        for (int kk=0;kk<32;kk++){
            float a[8], bb[8];
            #pragma unroll
            for (int i=0;i<8;i++) a[i]=qs[kk][ty*8+i];
            #pragma unroll
            for (int j=0;j<8;j++) bb[j]=as[kk][tx*8+j];
            #pragma unroll
            for (int i=0;i<8;i++)
                #pragma unroll
                for (int j=0;j<8;j++)
                    acc[i][j] = fmaf(a[i], bb[j], acc[i][j]);
        }
        __syncthreads();
    }
    #pragma unroll
    for (int i=0;i<8;i++)
        #pragma unroll
        for (int j=0;j<8;j++)
            y[((size_t)(b*TT)+t0+ty*8+i)*DD + h*DHH + tx*8+j] = acc[i][j];
}

// ======================= emb path =======================
__global__ void silu_emb_k(const float* __restrict__ emb, float* __restrict__ out)
{
    int i = blockIdx.x*256 + threadIdx.x;
    float e = emb[i];
    out[i] = e / (1.0f + expf(-e));
}

__global__ __launch_bounds__(256) void emb_gemm_k(const float* __restrict__ ea,
                                                  const float* __restrict__ W,
                                                  const float* __restrict__ bias,
                                                  float* __restrict__ out)
{
    int n = blockIdx.x*256 + threadIdx.x;
    int b = blockIdx.y;
    const float* e = ea + b*TEE;
    float acc = 0.f;
    #pragma unroll 8
    for (int t=0;t<TEE;t++)
        acc = fmaf(e[t], W[(size_t)t*(2*DD) + n], acc);
    out[b*(2*DD) + n] = acc + bias[n];
}

// ======================= LN2 + FiLM + SiLU -> bf16 hi/lo =======================
__global__ __launch_bounds__(256) void film_k(const float* __restrict__ y,
                                              const float* __restrict__ w2,
                                              const float* __restrict__ b2,
                                              const float* __restrict__ embout,
                                              __nv_bfloat16* __restrict__ acth,
                                              __nv_bfloat16* __restrict__ actl)
{
    int row = blockIdx.x;
    int b = row / TT;
    int tid = threadIdx.x;
    const float4* yr = (const float4*)(y + (size_t)row*DD);
    float4 v = yr[tid];
    float s  = v.x+v.y+v.z+v.w;
    float ss = v.x*v.x+v.y*v.y+v.z*v.z+v.w*v.w;
    #pragma unroll
    for (int o=16;o>0;o>>=1){ s += __shfl_down_sync(0xffffffffu,s,o); ss += __shfl_down_sync(0xffffffffu,ss,o); }
    __shared__ float sm[8], sm2[8];
    int wid = tid>>5, lane = tid&31;
    if (lane==0){ sm[wid]=s; sm2[wid]=ss; }
    __syncthreads();
    if (tid==0){
        float a=0.f, c=0.f;
        #pragma unroll
        for (int i=0;i<8;i++){ a+=sm[i]; c+=sm2[i]; }
        float mean = a*(1.0f/DD);
        float var  = c*(1.0f/DD) - mean*mean;
        sm[0]=mean; sm2[0]=rsqrtf(var+1e-5f);
    }
    __syncthreads();
    float mean=sm[0], rinv=sm2[0];
    float4 wv=((const float4*)w2)[tid];
    float4 bv=((const float4*)b2)[tid];
    float4 sc=((const float4*)(embout + (size_t)b*(2*DD)))[tid];
    float4 sh=((const float4*)(embout + (size_t)b*(2*DD) + DD))[tid];
    float4 o;
    float h;
    h=(v.x-mean)*rinv*wv.x+bv.x; h=h*(1.0f+sc.x)+sh.x; o.x=h/(1.0f+expf(-h));
    h=(v.y-mean)*rinv*wv.y+bv.y; h=h*(1.0f+sc.y)+sh.y; o.y=h/(1.0f+expf(-h));
    h=(v.z-mean)*rinv*wv.z+bv.z; h=h*(1.0f+sc.z)+sh.z; o.z=h/(1.0f+expf(-h));
    h=(v.w-mean)*rinv*wv.w+bv.w; h=h*(1.0f+sc.w)+sh.w; o.w=h/(1.0f+expf(-h));
    split_store4(acth + (size_t)row*DD + tid*4, actl + (size_t)row*DD + tid*4, o);
}

// ======================= launch =======================
extern "C" void kernel_launch(void* const* d_in, const int* in_sizes, int n_in,
                              void* d_out, int out_size)
{
    (void)in_sizes; (void)n_in; (void)out_size;
    const float* x     = (const float*)d_in[0];
    const float* emb   = (const float*)d_in[1];
    const float* mask  = (const float*)d_in[2];
    const float* ln_w  = (const float*)d_in[4];
    const float* ln_b  = (const float*)d_in[5];
    const float* Wq    = (const float*)d_in[6];
    const float* bq    = (const float*)d_in[7];
    const float* Wk    = (const float*)d_in[8];
    const float* bk    = (const float*)d_in[9];
    const float* Wv    = (const float*)d_in[10];
    const float* bv    = (const float*)d_in[11];
    const float* W_emb = (const float*)d_in[12];
    const float* b_emb = (const float*)d_in[13];
    const float* ln2_w = (const float*)d_in[14];
    const float* ln2_b = (const float*)d_in[15];
    const float* W_out = (const float*)d_in[16];
    const float* b_out = (const float*)d_in[17];
    float* out = (float*)d_out;

    __nv_bfloat16 *p_xnh, *p_xnl, *p_acth, *p_actl, *p_wth, *p_wtl;
    float *p_q, *p_k, *p_v, *p_y, *p_attp, *p_att, *p_emba, *p_embout;
    cudaGetSymbolAddress((void**)&p_xnh,    g_xnhi);
    cudaGetSymbolAddress((void**)&p_xnl,    g_xnlo);
    cudaGetSymbolAddress((void**)&p_acth,   g_acthi);
    cudaGetSymbolAddress((void**)&p_actl,   g_actlo);
    cudaGetSymbolAddress((void**)&p_wth,    g_wthi);
    cudaGetSymbolAddress((void**)&p_wtl,    g_wtlo);
    cudaGetSymbolAddress((void**)&p_q,      g_q);
    cudaGetSymbolAddress((void**)&p_k,      g_k);
    cudaGetSymbolAddress((void**)&p_v,      g_v);
    cudaGetSymbolAddress((void**)&p_y,      g_y);
    cudaGetSymbolAddress((void**)&p_attp,   g_att_part);
    cudaGetSymbolAddress((void**)&p_att,    g_att);
    cudaGetSymbolAddress((void**)&p_emba,   g_emb_act);
    cudaGetSymbolAddress((void**)&p_embout, g_embout);

    cudaFuncSetAttribute(hgemm_k, cudaFuncAttributeMaxDynamicSharedMemorySize, HG_SMEM);

    // weight transpose + split (Wq, Wk, Wv, W_out -> [N,K] bf16 hi/lo)
    dim3 tgrid(32, 32), tblk(32, 32);
    wsplit_k<<<tgrid, tblk>>>(Wq,    p_wth + 0*(size_t)DD*DD, p_wtl + 0*(size_t)DD*DD);
    wsplit_k<<<tgrid, tblk>>>(Wk,    p_wth + 1*(size_t)DD*DD, p_wtl + 1*(size_t)DD*DD);
    wsplit_k<<<tgrid, tblk>>>(Wv,    p_wth + 2*(size_t)DD*DD, p_wtl + 2*(size_t)DD*DD);
    wsplit_k<<<tgrid, tblk>>>(W_out, p_wth + 3*(size_t)DD*DD, p_wtl + 3*(size_t)DD*DD);

    ln_kernel<<<MM, 256>>>(x, ln_w, ln_b, p_xnh, p_xnl);
    silu_emb_k<<<(BB*TEE)/256, 256>>>(emb, p_emba);

    dim3 ggrid(DD/128, MM/128);
    hgemm_k<<<ggrid, 512, HG_SMEM>>>(p_xnh, p_xnl, p_wth + 0*(size_t)DD*DD, p_wtl + 0*(size_t)DD*DD,
                                     bq, nullptr, nullptr, p_q, 0);
    hgemm_k<<<ggrid, 512, HG_SMEM>>>(p_xnh, p_xnl, p_wth + 1*(size_t)DD*DD, p_wtl + 1*(size_t)DD*DD,
                                     bk, mask, nullptr, p_k, 1);
    hgemm_k<<<ggrid, 512, HG_SMEM>>>(p_xnh, p_xnl, p_wth + 2*(size_t)DD*DD, p_wtl + 2*(size_t)DD*DD,
                                     bv, mask, nullptr, p_v, 2);

    qsoftmax_k<<<(MM*HH)/8, 256>>>(p_q);
    ksoftmax_k<<<BB*32, dim3(32,8)>>>(p_k);

    att_partial_k<<<dim3(NCHUNK, BB*HH), 256>>>(p_k, p_v, p_attp);
    att_reduce_k<<<(BB*HH*DHH*DHH)/256, 256>>>(p_attp, p_att);

    emb_gemm_k<<<dim3((2*DD)/256, BB), 256>>>(p_emba, W_emb, b_emb, p_embout);

    y_gemm_k<<<dim3(TT/128, BB*HH), 256>>>(p_q, p_att, p_y);

    film_k<<<MM, 256>>>(p_y, ln2_w, ln2_b, p_embout, p_acth, p_actl);

    hgemm_k<<<ggrid, 512, HG_SMEM>>>(p_acth, p_actl, p_wth + 3*(size_t)DD*DD, p_wtl + 3*(size_t)DD*DD,
                                     b_out, nullptr, x, out, 3);
}

// round 4
// speedup vs baseline: 1.9861x; 1.0606x over previous
#include <cuda_runtime.h>
#include <cuda_bf16.h>
#include <math.h>
#include <stdint.h>

#define BB 4
#define TT 2048
#define DD 1024
#define HH 8
#define DHH 128
#define TEE 2048
#define MM (BB*TT)          // 8192 rows
#define NCHUNK 16

__device__ __forceinline__ uint32_t smem_to_u32(const void* p) {
    uint32_t a;
    asm("{ .reg .u64 t; cvta.to.shared.u64 t, %1; cvt.u32.u64 %0, t; }" : "=r"(a) : "l"(p));
    return a;
}

#define LDSM4(R, addr) \
    asm volatile("ldmatrix.sync.aligned.m8n8.x4.shared.b16 {%0,%1,%2,%3}, [%4];" \
        : "=r"((R)[0]), "=r"((R)[1]), "=r"((R)[2]), "=r"((R)[3]) : "r"(addr))

#define MMA_BF16(c, a, b0, b1) \
    asm volatile("mma.sync.aligned.m16n8k16.row.col.f32.bf16.bf16.f32 " \
        "{%0,%1,%2,%3}, {%4,%5,%6,%7}, {%8,%9}, {%0,%1,%2,%3};" \
        : "+f"((c)[0]), "+f"((c)[1]), "+f"((c)[2]), "+f"((c)[3]) \
        : "r"((a)[0]), "r"((a)[1]), "r"((a)[2]), "r"((a)[3]), "r"(b0), "r"(b1))

// ======================= device scratch =======================
__device__ __nv_bfloat16 g_xnhi[MM*DD];
__device__ __nv_bfloat16 g_xnlo[MM*DD];
__device__ __nv_bfloat16 g_acthi[MM*DD];
__device__ __nv_bfloat16 g_actlo[MM*DD];
__device__ __nv_bfloat16 g_wthi[4][DD*DD];
__device__ __nv_bfloat16 g_wtlo[4][DD*DD];
__device__ float g_q [MM*DD];
__device__ float g_k [MM*DD];
__device__ float g_v [MM*DD];
__device__ float g_y [MM*DD];
__device__ __nv_bfloat16 g_qhi[MM*DD];
__device__ __nv_bfloat16 g_qlo[MM*DD];
__device__ __nv_bfloat16 g_kThi[MM*DD];
__device__ __nv_bfloat16 g_kTlo[MM*DD];
__device__ __nv_bfloat16 g_vThi[MM*DD];
__device__ __nv_bfloat16 g_vTlo[MM*DD];
__device__ float g_att_part[NCHUNK*BB*HH*DHH*DHH];
__device__ __nv_bfloat16 g_attThi[BB*HH*DHH*DHH];
__device__ __nv_bfloat16 g_attTlo[BB*HH*DHH*DHH];
__device__ float g_emb_act[BB*TEE];
__device__ float g_embout[BB*2*DD];

__device__ __forceinline__ void split_store4(__nv_bfloat16* ph, __nv_bfloat16* pl, float4 v) {
    __nv_bfloat162 h0 = __floats2bfloat162_rn(v.x, v.y);
    __nv_bfloat162 h1 = __floats2bfloat162_rn(v.z, v.w);
    float rx = v.x - __bfloat162float(h0.x);
    float ry = v.y - __bfloat162float(h0.y);
    float rz = v.z - __bfloat162float(h1.x);
    float rw = v.w - __bfloat162float(h1.y);
    __nv_bfloat162 l0 = __floats2bfloat162_rn(rx, ry);
    __nv_bfloat162 l1 = __floats2bfloat162_rn(rz, rw);
    uint2 uh; uh.x = *(uint32_t*)&h0; uh.y = *(uint32_t*)&h1;
    uint2 ul; ul.x = *(uint32_t*)&l0; ul.y = *(uint32_t*)&l1;
    *(uint2*)ph = uh;
    *(uint2*)pl = ul;
}

// ======================= LayerNorm -> bf16 hi/lo =======================
__global__ __launch_bounds__(256) void ln_kernel(const float* __restrict__ x,
                                                 const float* __restrict__ w,
                                                 const float* __restrict__ b,
                                                 __nv_bfloat16* __restrict__ outh,
                                                 __nv_bfloat16* __restrict__ outl)
{
    int row = blockIdx.x;
    int tid = threadIdx.x;
    const float4* xr = (const float4*)(x + (size_t)row*DD);
    float4 v = xr[tid];
    float s  = v.x+v.y+v.z+v.w;
    float ss = v.x*v.x+v.y*v.y+v.z*v.z+v.w*v.w;
    #pragma unroll
    for (int o=16;o>0;o>>=1){ s += __shfl_down_sync(0xffffffffu,s,o); ss += __shfl_down_sync(0xffffffffu,ss,o); }
    __shared__ float sm[8], sm2[8];
    int wid = tid>>5, lane = tid&31;
    if (lane==0){ sm[wid]=s; sm2[wid]=ss; }
    __syncthreads();
    if (tid==0){
        float a=0.f, c=0.f;
        #pragma unroll
        for (int i=0;i<8;i++){ a+=sm[i]; c+=sm2[i]; }
        float mean = a*(1.0f/DD);
        float var  = c*(1.0f/DD) - mean*mean;
        sm[0]=mean; sm2[0]=rsqrtf(var+1e-5f);
    }
    __syncthreads();
    float mean=sm[0], rinv=sm2[0];
    float4 wv=((const float4*)w)[tid];
    float4 bv=((const float4*)b)[tid];
    float4 o;
    o.x=(v.x-mean)*rinv*wv.x+bv.x;
    o.y=(v.y-mean)*rinv*wv.y+bv.y;
    o.z=(v.z-mean)*rinv*wv.z+bv.z;
    o.w=(v.w-mean)*rinv*wv.w+bv.w;
    split_store4(outh + (size_t)row*DD + tid*4, outl + (size_t)row*DD + tid*4, o);
}

// ======================= weight transpose + bf16 split (4 weights) ==========
__global__ __launch_bounds__(1024) void wsplit4_k(const float* __restrict__ W0,
                                                  const float* __restrict__ W1,
                                                  const float* __restrict__ W2,
                                                  const float* __restrict__ W3,
                                                  __nv_bfloat16* __restrict__ Thi,
                                                  __nv_bfloat16* __restrict__ Tlo)
{
    __shared__ float t[32][33];
    int tx = threadIdx.x, ty = threadIdx.y;
    int wsel = blockIdx.z;
    const float* W = (wsel==0)?W0:(wsel==1)?W1:(wsel==2)?W2:W3;
    t[ty][tx] = W[(size_t)(blockIdx.y*32+ty)*DD + blockIdx.x*32+tx];
    __syncthreads();
    int n = blockIdx.x*32 + ty;
    int k = blockIdx.y*32 + tx;
    float v = t[tx][ty];
    __nv_bfloat16 h = __float2bfloat16(v);
    size_t base = (size_t)wsel*DD*DD;
    Thi[base + (size_t)n*DD + k] = h;
    Tlo[base + (size_t)n*DD + k] = __float2bfloat16(v - __bfloat162float(h));
}

// ======================= HMMA GEMM (projections) ============================
#define LDSE   40
#define TILE_E (128*LDSE)
#define BUF_E  (4*TILE_E)
#define HG_SMEM (2*BUF_E*2)

__global__ __launch_bounds__(512, 1) void hgemm_k(
        const __nv_bfloat16* __restrict__ Ahi, const __nv_bfloat16* __restrict__ Alo,
        const __nv_bfloat16* __restrict__ Bhi, const __nv_bfloat16* __restrict__ Blo,
        const float* __restrict__ bias, const float* __restrict__ mask,
        const float* __restrict__ resid, float* __restrict__ C, int mode)
{
    extern __shared__ __nv_bfloat16 smbuf[];
    const int tid  = threadIdx.x;
    const int lane = tid & 31;
    const int w    = tid >> 5;
    const int wm   = w >> 2;
    const int wn   = w & 3;
    const int m0 = blockIdx.y * 128;
    const int n0 = blockIdx.x * 128;

    const int lr = tid >> 2;
    const int lc = (tid & 3) * 8;
    const __nv_bfloat16* gsrc0 = Ahi + (size_t)(m0+lr)*DD + lc;
    const __nv_bfloat16* gsrc1 = Alo + (size_t)(m0+lr)*DD + lc;
    const __nv_bfloat16* gsrc2 = Bhi + (size_t)(n0+lr)*DD + lc;
    const __nv_bfloat16* gsrc3 = Blo + (size_t)(n0+lr)*DD + lc;

    const uint32_t smb = smem_to_u32(smbuf);
    const int arow  = wm*32 + (lane & 7) + ((lane >> 3) & 1) * 8;
    const int akoff = ((lane >> 4) & 1) * 8;
    const int brow  = wn*32 + (lane & 7) + ((lane >> 4) & 1) * 8;
    const int bkoff = ((lane >> 3) & 1) * 8;

    float acc[2][4][4];
    #pragma unroll
    for (int i=0;i<2;i++)
        #pragma unroll
        for (int j=0;j<4;j++)
            #pragma unroll
            for (int l=0;l<4;l++) acc[i][j][l]=0.f;

    uint4 pf0, pf1, pf2, pf3;
    pf0 = *(const uint4*)gsrc0; pf1 = *(const uint4*)gsrc1;
    pf2 = *(const uint4*)gsrc2; pf3 = *(const uint4*)gsrc3;
    {
        __nv_bfloat16* d = smbuf + lr*LDSE + lc;
        *(uint4*)(d + 0*TILE_E) = pf0;
        *(uint4*)(d + 1*TILE_E) = pf1;
        *(uint4*)(d + 2*TILE_E) = pf2;
        *(uint4*)(d + 3*TILE_E) = pf3;
    }
    __syncthreads();

    for (int kc = 0; kc < 32; kc++) {
        if (kc < 31) {
            int k0 = (kc+1)*32;
            pf0 = *(const uint4*)(gsrc0 + k0);
            pf1 = *(const uint4*)(gsrc1 + k0);
            pf2 = *(const uint4*)(gsrc2 + k0);
            pf3 = *(const uint4*)(gsrc3 + k0);
        }
        uint32_t base = smb + (kc & 1) * (BUF_E*2);
        #pragma unroll
        for (int ks = 0; ks < 2; ks++) {
            uint32_t ah[2][4], al[2][4];
            #pragma unroll
            for (int mt = 0; mt < 2; mt++) {
                uint32_t ra = base + ((arow + mt*16)*LDSE + ks*16 + akoff) * 2;
                LDSM4(ah[mt], ra);
                LDSM4(al[mt], ra + TILE_E*2);
            }
            uint32_t bh[2][4], bl[2][4];
            #pragma unroll
            for (int nb = 0; nb < 2; nb++) {
                uint32_t rb = base + 2*TILE_E*2 + ((brow + nb*16)*LDSE + ks*16 + bkoff) * 2;
                LDSM4(bh[nb], rb);
                LDSM4(bl[nb], rb + TILE_E*2);
            }
            #pragma unroll
            for (int mt = 0; mt < 2; mt++) {
                #pragma unroll
                for (int nt = 0; nt < 4; nt++) {
                    int nb = nt >> 1, sub = (nt & 1) * 2;
                    MMA_BF16(acc[mt][nt], ah[mt], bh[nb][sub], bh[nb][sub+1]);
                    MMA_BF16(acc[mt][nt], ah[mt], bl[nb][sub], bl[nb][sub+1]);
                    MMA_BF16(acc[mt][nt], al[mt], bh[nb][sub], bh[nb][sub+1]);
                }
            }
        }
        if (kc < 31) {
            __syncthreads();
            __nv_bfloat16* d = smbuf + ((kc+1)&1)*BUF_E + lr*LDSE + lc;
            *(uint4*)(d + 0*TILE_E) = pf0;
            *(uint4*)(d + 1*TILE_E) = pf1;
            *(uint4*)(d + 2*TILE_E) = pf2;
            *(uint4*)(d + 3*TILE_E) = pf3;
            __syncthreads();
        }
    }

    const int t4 = lane >> 2;
    const int t2 = (lane & 3) * 2;
    #pragma unroll
    for (int mt = 0; mt < 2; mt++) {
        int row0 = m0 + wm*32 + mt*16 + t4;
        int row1 = row0 + 8;
        float m0v = 0.f, m1v = 0.f;
        if (mode == 1 || mode == 2) { m0v = mask[row0]; m1v = mask[row1]; }
        float add0 = (mode==1) ? (1.0f-m0v)*(-1000000.0f) : 0.f;
        float add1 = (mode==1) ? (1.0f-m1v)*(-1000000.0f) : 0.f;
        float mul0 = (mode==2) ? m0v : 1.f;
        float mul1 = (mode==2) ? m1v : 1.f;
        #pragma unroll
        for (int nt = 0; nt < 4; nt++) {
            int col = n0 + wn*32 + nt*8 + t2;
            float2 bi = *(const float2*)(bias + col);
            float a0 = acc[mt][nt][0] + bi.x;
            float a1 = acc[mt][nt][1] + bi.y;
            float a2 = acc[mt][nt][2] + bi.x;
            float a3 = acc[mt][nt][3] + bi.y;
            if (mode == 1) { a0 += add0; a1 += add0; a2 += add1; a3 += add1; }
            else if (mode == 2) { a0 *= mul0; a1 *= mul0; a2 *= mul1; a3 *= mul1; }
            else if (mode == 3) {
                float2 r0 = *(const float2*)(resid + (size_t)row0*DD + col);
                float2 r1 = *(const float2*)(resid + (size_t)row1*DD + col);
                a0 += r0.x; a1 += r0.y; a2 += r1.x; a3 += r1.y;
            }
            *(float2*)(C + (size_t)row0*DD + col) = make_float2(a0, a1);
            *(float2*)(C + (size_t)row1*DD + col) = make_float2(a2, a3);
        }
    }
}

// ======================= softmax over dh -> bf16 hi/lo ======================
__global__ __launch_bounds__(256) void qsoftmax_k(const float* __restrict__ q,
                                                  __nv_bfloat16* __restrict__ qh,
                                                  __nv_bfloat16* __restrict__ ql)
{
    int idx  = blockIdx.x*8 + (threadIdx.x>>5);
    int lane = threadIdx.x & 31;
    const float4* p = (const float4*)(q + (size_t)idx*DHH);
    float4 v = p[lane];
    float m = fmaxf(fmaxf(v.x,v.y), fmaxf(v.z,v.w));
    #pragma unroll
    for (int o=16;o>0;o>>=1) m = fmaxf(m, __shfl_xor_sync(0xffffffffu,m,o));
    v.x=expf(v.x-m); v.y=expf(v.y-m); v.z=expf(v.z-m); v.w=expf(v.w-m);
    float s = v.x+v.y+v.z+v.w;
    #pragma unroll
    for (int o=16;o>0;o>>=1) s += __shfl_xor_sync(0xffffffffu,s,o);
    float r = 1.0f/s;
    v.x*=r; v.y*=r; v.z*=r; v.w*=r;
    split_store4(qh + (size_t)idx*DHH + lane*4, ql + (size_t)idx*DHH + lane*4, v);
}

// ======================= softmax over time -> transposed bf16 hi/lo =========
// kT layout: [b][h][d_local][t]
__global__ void ksoftmaxT_k(const float* __restrict__ k,
                            __nv_bfloat16* __restrict__ kTh,
                            __nv_bfloat16* __restrict__ kTl)
{
    int b = blockIdx.x >> 5;
    int g = blockIdx.x & 31;
    int tx = threadIdx.x, ty = threadIdx.y;
    int d = g*32 + tx;
    float m = -INFINITY, s = 0.f;
    for (int t=ty; t<TT; t+=8){
        float val = k[((size_t)b*TT + t)*DD + d];
        float nm = fmaxf(m, val);
        s = s*expf(m-nm) + expf(val-nm);
        m = nm;
    }
    __shared__ float smax[8][32], ssum[8][32];
    smax[ty][tx]=m; ssum[ty][tx]=s;
    __syncthreads();
    if (ty==0){
        float M=smax[0][tx], S=ssum[0][tx];
        #pragma unroll
        for (int i=1;i<8;i++){
            float m2=smax[i][tx], s2=ssum[i][tx];
            float nm=fmaxf(M,m2);
            S = S*expf(M-nm) + s2*expf(m2-nm);
            M = nm;
        }
        smax[0][tx]=M; ssum[0][tx]=1.0f/S;
    }
    __syncthreads();
    float M=smax[0][tx], R=ssum[0][tx];
    __syncthreads();

    __shared__ __nv_bfloat16 sh[32][33], sl[32][33];
    int dg0 = g*32;
    int h = dg0 >> 7;
    int dl0 = dg0 & 127;
    size_t kbase = ((size_t)(b*HH + h))*DHH + dl0;

    for (int t0 = 0; t0 < TT; t0 += 32) {
        #pragma unroll
        for (int i = 0; i < 4; i++) {
            int t = t0 + ty + i*8;
            float val = expf(k[((size_t)b*TT + t)*DD + d] - M) * R;
            __nv_bfloat16 hv = __float2bfloat16(val);
            sh[tx][ty + i*8] = hv;
            sl[tx][ty + i*8] = __float2bfloat16(val - __bfloat162float(hv));
        }
        __syncthreads();
        #pragma unroll
        for (int i = 0; i < 4; i++) {
            int row = ty + i*8;
            kTh[(kbase + row)*TT + t0 + tx] = sh[row][tx];
            kTl[(kbase + row)*TT + t0 + tx] = sl[row][tx];
        }
        __syncthreads();
    }
}

// ======================= v transpose + split: v -> vT[b][h][l][t] ==========
__global__ __launch_bounds__(1024) void vsplitT_k(const float* __restrict__ v,
                                                  __nv_bfloat16* __restrict__ vTh,
                                                  __nv_bfloat16* __restrict__ vTl)
{
    __shared__ float t[32][33];
    int tx = threadIdx.x, ty = threadIdx.y;
    int bh = blockIdx.z;
    int b = bh >> 3, h = bh & 7;
    int t0 = blockIdx.x * 32;
    int l0 = blockIdx.y * 32;
    t[ty][tx] = v[((size_t)(b*TT) + t0 + ty)*DD + h*DHH + l0 + tx];
    __syncthreads();
    float val = t[tx][ty];
    __nv_bfloat16 hv = __float2bfloat16(val);
    size_t idx = ((size_t)bh*DHH + l0 + ty)*TT + t0 + tx;
    vTh[idx] = hv;
    vTl[idx] = __float2bfloat16(val - __bfloat162float(hv));
}

// ======================= attention core HMMA ================================
// single-shot K=128 smem tiles, row stride 136 elements
#define LD2    136
#define ATE    (128*LD2)
#define ATT_SMEM (4*ATE*2)   // 139264 bytes

// att1: attT[l][d] partial over t-chunk = sum_t vT[l][t]*kT[d][t]
__global__ __launch_bounds__(512, 1) void att1_k(
        const __nv_bfloat16* __restrict__ vTh, const __nv_bfloat16* __restrict__ vTl,
        const __nv_bfloat16* __restrict__ kTh, const __nv_bfloat16* __restrict__ kTl,
        float* __restrict__ part)
{
    extern __shared__ __nv_bfloat16 smbuf[];
    const int tid  = threadIdx.x;
    const int lane = tid & 31;
    const int w    = tid >> 5;
    const int wm   = w >> 2;
    const int wn   = w & 3;
    const int chunk = blockIdx.x;
    const int bh    = blockIdx.y;
    const int t0 = chunk * 128;

    // load 4 tiles: vTh, vTl, kTh, kTl  (row r, t-cols)
    #pragma unroll
    for (int i = 0; i < 4; i++) {
        int c = tid + i*512;            // 0..2047
        int r = c >> 4;
        int c16 = (c & 15) * 8;
        size_t g = ((size_t)bh*DHH + r)*TT + t0 + c16;
        __nv_bfloat16* d = smbuf + r*LD2 + c16;
        *(uint4*)(d + 0*ATE) = *(const uint4*)(vTh + g);
        *(uint4*)(d + 1*ATE) = *(const uint4*)(vTl + g);
        *(uint4*)(d + 2*ATE) = *(const uint4*)(kTh + g);
        *(uint4*)(d + 3*ATE) = *(const uint4*)(kTl + g);
    }
    __syncthreads();

    const uint32_t smb = smem_to_u32(smbuf);
    const int arow  = wm*32 + (lane & 7) + ((lane >> 3) & 1) * 8;
    const int akoff = ((lane >> 4) & 1) * 8;
    const int brow  = wn*32 + (lane & 7) + ((lane >> 4) & 1) * 8;
    const int bkoff = ((lane >> 3) & 1) * 8;

    float acc[2][4][4];
    #pragma unroll
    for (int i=0;i<2;i++)
        #pragma unroll
        for (int j=0;j<4;j++)
            #pragma unroll
            for (int l=0;l<4;l++) acc[i][j][l]=0.f;

    #pragma unroll
    for (int ks = 0; ks < 8; ks++) {
        uint32_t ah[2][4], al[2][4];
        #pragma unroll
        for (int mt = 0; mt < 2; mt++) {
            uint32_t ra = smb + ((arow + mt*16)*LD2 + ks*16 + akoff) * 2;
            LDSM4(ah[mt], ra);
            LDSM4(al[mt], ra + ATE*2);
        }
        uint32_t bhf[2][4], blf[2][4];
        #pragma unroll
        for (int nb = 0; nb < 2; nb++) {
            uint32_t rb = smb + 2*ATE*2 + ((brow + nb*16)*LD2 + ks*16 + bkoff) * 2;
            LDSM4(bhf[nb], rb);
            LDSM4(blf[nb], rb + ATE*2);
        }
        #pragma unroll
        for (int mt = 0; mt < 2; mt++) {
            #pragma unroll
            for (int nt = 0; nt < 4; nt++) {
                int nb = nt >> 1, sub = (nt & 1) * 2;
                MMA_BF16(acc[mt][nt], ah[mt], bhf[nb][sub], bhf[nb][sub+1]);
                MMA_BF16(acc[mt][nt], ah[mt], blf[nb][sub], blf[nb][sub+1]);
                MMA_BF16(acc[mt][nt], al[mt], bhf[nb][sub], bhf[nb][sub+1]);
            }
        }
    }

    float* dst = part + ((size_t)(chunk*(BB*HH) + bh))*(DHH*DHH);
    const int t4 = lane >> 2;
    const int t2 = (lane & 3) * 2;
    #pragma unroll
    for (int mt = 0; mt < 2; mt++) {
        int row0 = wm*32 + mt*16 + t4;
        int row1 = row0 + 8;
        #pragma unroll
        for (int nt = 0; nt < 4; nt++) {
            int col = wn*32 + nt*8 + t2;
            *(float2*)(dst + row0*DHH + col) = make_float2(acc[mt][nt][0], acc[mt][nt][1]);
            *(float2*)(dst + row1*DHH + col) = make_float2(acc[mt][nt][2], acc[mt][nt][3]);
        }
    }
}

// reduce partials + split to bf16 hi/lo
__global__ void att_reduce_k(const float* __restrict__ part,
                             __nv_bfloat16* __restrict__ ath,
                             __nv_bfloat16* __restrict__ atl)
{
    int i = blockIdx.x*256 + threadIdx.x;
    float s = 0.f;
    #pragma unroll
    for (int c=0;c<NCHUNK;c++) s += part[(size_t)c*(BB*HH*DHH*DHH) + i];
    __nv_bfloat16 h = __float2bfloat16(s);
    ath[i] = h;
    atl[i] = __float2bfloat16(s - __bfloat162float(h));
}

// att2: y[t][l] = sum_d q[t][d]*attT[l][d]
__global__ __launch_bounds__(512, 1) void att2_k(
        const __nv_bfloat16* __restrict__ qh, const __nv_bfloat16* __restrict__ ql,
        const __nv_bfloat16* __restrict__ ath, const __nv_bfloat16* __restrict__ atl,
        float* __restrict__ y)
{
    extern __shared__ __nv_bfloat16 smbuf[];
    const int tid  = threadIdx.x;
    const int lane = tid & 31;
    const int w    = tid >> 5;
    const int wm   = w >> 2;
    const int wn   = w & 3;
    const int m0 = blockIdx.x * 128;
    const int h  = blockIdx.y;
    const int bh = (m0 >> 11) * HH + h;   // TT = 2048

    #pragma unroll
    for (int i = 0; i < 4; i++) {
        int c = tid + i*512;
        int r = c >> 4;
        int c16 = (c & 15) * 8;
        size_t ga = (size_t)(m0 + r)*DD + h*DHH + c16;
        size_t gb = ((size_t)bh*DHH + r)*DHH + c16;
        __nv_bfloat16* d = smbuf + r*LD2 + c16;
        *(uint4*)(d + 0*ATE) = *(const uint4*)(qh + ga);
        *(uint4*)(d + 1*ATE) = *(const uint4*)(ql + ga);
        *(uint4*)(d + 2*ATE) = *(const uint4*)(ath + gb);
        *(uint4*)(d + 3*ATE) = *(const uint4*)(atl + gb);
    }
    __syncthreads();

    const uint32_t smb = smem_to_u32(smbuf);
    const int arow  = wm*32 + (lane & 7) + ((lane >> 3) & 1) * 8;
    const int akoff = ((lane >> 4) & 1) * 8;
    const int brow  = wn*32 + (lane & 7) + ((lane >> 4) & 1) * 8;
    const int bkoff = ((lane >> 3) & 1) * 8;

    float acc[2][4][4];
    #pragma unroll
    for (int i=0;i<2;i++)
        #pragma unroll
        for (int j=0;j<4;j++)
            #pragma unroll
            for (int l=0;l<4;l++) acc[i][j][l]=0.f;

    #pragma unroll
    for (int ks = 0; ks < 8; ks++) {
        uint32_t ah[2][4], al[2][4];
        #pragma unroll
        for (int mt = 0; mt < 2; mt++) {
            uint32_t ra = smb + ((arow + mt*16)*LD2 + ks*16 + akoff) * 2;
            LDSM4(ah[mt], ra);
            LDSM4(al[mt], ra + ATE*2);
        }
        uint32_t bhf[2][4], blf[2][4];
        #pragma unroll
        for (int nb = 0; nb < 2; nb++) {
            uint32_t rb = smb + 2*ATE*2 + ((brow + nb*16)*LD2 + ks*16 + bkoff) * 2;
            LDSM4(bhf[nb], rb);
            LDSM4(blf[nb], rb + ATE*2);
        }
        #pragma unroll
        for (int mt = 0; mt < 2; mt++) {
            #pragma unroll
            for (int nt = 0; nt < 4; nt++) {
                int nb = nt >> 1, sub = (nt & 1) * 2;
                MMA_BF16(acc[mt][nt], ah[mt], bhf[nb][sub], bhf[nb][sub+1]);
                MMA_BF16(acc[mt][nt], ah[mt], blf[nb][sub], blf[nb][sub+1]);
                MMA_BF16(acc[mt][nt], al[mt], bhf[nb][sub], bhf[nb][sub+1]);
            }
        }
    }

    const int t4 = lane >> 2;
    const int t2 = (lane & 3) * 2;
    #pragma unroll
    for (int mt = 0; mt < 2; mt++) {
        int row0 = m0 + wm*32 + mt*16 + t4;
        int row1 = row0 + 8;
        #pragma unroll
        for (int nt = 0; nt < 4; nt++) {
            int col = h*DHH + wn*32 + nt*8 + t2;
            *(float2*)(y + (size_t)row0*DD + col) = make_float2(acc[mt][nt][0], acc[mt][nt][1]);
            *(float2*)(y + (size_t)row1*DD + col) = make_float2(acc[mt][nt][2], acc[mt][nt][3]);
        }
    }
}

// ======================= emb path =======================
__global__ void silu_emb_k(const float* __restrict__ emb, float* __restrict__ out)
{
    int i = blockIdx.x*256 + threadIdx.x;
    float e = emb[i];
    out[i] = e / (1.0f + expf(-e));
}

__global__ __launch_bounds__(256) void emb_gemm_k(const float* __restrict__ ea,
                                                  const float* __restrict__ W,
                                                  const float* __restrict__ bias,
                                                  float* __restrict__ out)
{
    int n = blockIdx.x*256 + threadIdx.x;
    int b = blockIdx.y;
    const float* e = ea + b*TEE;
    float acc = 0.f;
    #pragma unroll 8
    for (int t=0;t<TEE;t++)
        acc = fmaf(e[t], W[(size_t)t*(2*DD) + n], acc);
    out[b*(2*DD) + n] = acc + bias[n];
}

// ======================= LN2 + FiLM + SiLU -> bf16 hi/lo =======================
__global__ __launch_bounds__(256) void film_k(const float* __restrict__ y,
                                              const float* __restrict__ w2,
                                              const float* __restrict__ b2,
                                              const float* __restrict__ embout,
                                              __nv_bfloat16* __restrict__ acth,
                                              __nv_bfloat16* __restrict__ actl)
{
    int row = blockIdx.x;
    int b = row / TT;
    int tid = threadIdx.x;
    const float4* yr = (const float4*)(y + (size_t)row*DD);
    float4 v = yr[tid];
    float s  = v.x+v.y+v.z+v.w;
    float ss = v.x*v.x+v.y*v.y+v.z*v.z+v.w*v.w;
    #pragma unroll
    for (int o=16;o>0;o>>=1){ s += __shfl_down_sync(0xffffffffu,s,o); ss += __shfl_down_sync(0xffffffffu,ss,o); }
    __shared__ float sm[8], sm2[8];
    int wid = tid>>5, lane = tid&31;
    if (lane==0){ sm[wid]=s; sm2[wid]=ss; }
    __syncthreads();
    if (tid==0){
        float a=0.f, c=0.f;
        #pragma unroll
        for (int i=0;i<8;i++){ a+=sm[i]; c+=sm2[i]; }
        float mean = a*(1.0f/DD);
        float var  = c*(1.0f/DD) - mean*mean;
        sm[0]=mean; sm2[0]=rsqrtf(var+1e-5f);
    }
    __syncthreads();
    float mean=sm[0], rinv=sm2[0];
    float4 wv=((const float4*)w2)[tid];
    float4 bv=((const float4*)b2)[tid];
    float4 sc=((const float4*)(embout + (size_t)b*(2*DD)))[tid];
    float4 sh=((const float4*)(embout + (size_t)b*(2*DD) + DD))[tid];
    float4 o;
    float h;
    h=(v.x-mean)*rinv*wv.x+bv.x; h=h*(1.0f+sc.x)+sh.x; o.x=h/(1.0f+expf(-h));
    h=(v.y-mean)*rinv*wv.y+bv.y; h=h*(1.0f+sc.y)+sh.y; o.y=h/(1.0f+expf(-h));
    h=(v.z-mean)*rinv*wv.z+bv.z; h=h*(1.0f+sc.z)+sh.z; o.z=h/(1.0f+expf(-h));
    h=(v.w-mean)*rinv*wv.w+bv.w; h=h*(1.0f+sc.w)+sh.w; o.w=h/(1.0f+expf(-h));
    split_store4(acth + (size_t)row*DD + tid*4, actl + (size_t)row*DD + tid*4, o);
}

// ======================= launch =======================
extern "C" void kernel_launch(void* const* d_in, const int* in_sizes, int n_in,
                              void* d_out, int out_size)
{
    (void)in_sizes; (void)n_in; (void)out_size;
    const float* x     = (const float*)d_in[0];
    const float* emb   = (const float*)d_in[1];
    const float* mask  = (const float*)d_in[2];
    const float* ln_w  = (const float*)d_in[4];
    const float* ln_b  = (const float*)d_in[5];
    const float* Wq    = (const float*)d_in[6];
    const float* bq    = (const float*)d_in[7];
    const float* Wk    = (const float*)d_in[8];
    const float* bk    = (const float*)d_in[9];
    const float* Wv    = (const float*)d_in[10];
    const float* bv    = (const float*)d_in[11];
    const float* W_emb = (const float*)d_in[12];
    const float* b_emb = (const float*)d_in[13];
    const float* ln2_w = (const float*)d_in[14];
    const float* ln2_b = (const float*)d_in[15];
    const float* W_out = (const float*)d_in[16];
    const float* b_out = (const float*)d_in[17];
    float* out = (float*)d_out;

    __nv_bfloat16 *p_xnh, *p_xnl, *p_acth, *p_actl, *p_wth, *p_wtl;
    __nv_bfloat16 *p_qh, *p_ql, *p_kTh, *p_kTl, *p_vTh, *p_vTl, *p_ath, *p_atl;
    float *p_q, *p_k, *p_v, *p_y, *p_attp, *p_emba, *p_embout;
    cudaGetSymbolAddress((void**)&p_xnh,    g_xnhi);
    cudaGetSymbolAddress((void**)&p_xnl,    g_xnlo);
    cudaGetSymbolAddress((void**)&p_acth,   g_acthi);
    cudaGetSymbolAddress((void**)&p_actl,   g_actlo);
    cudaGetSymbolAddress((void**)&p_wth,    g_wthi);
    cudaGetSymbolAddress((void**)&p_wtl,    g_wtlo);
    cudaGetSymbolAddress((void**)&p_q,      g_q);
    cudaGetSymbolAddress((void**)&p_k,      g_k);
    cudaGetSymbolAddress((void**)&p_v,      g_v);
    cudaGetSymbolAddress((void**)&p_y,      g_y);
    cudaGetSymbolAddress((void**)&p_qh,     g_qhi);
    cudaGetSymbolAddress((void**)&p_ql,     g_qlo);
    cudaGetSymbolAddress((void**)&p_kTh,    g_kThi);
    cudaGetSymbolAddress((void**)&p_kTl,    g_kTlo);
    cudaGetSymbolAddress((void**)&p_vTh,    g_vThi);
    cudaGetSymbolAddress((void**)&p_vTl,    g_vTlo);
    cudaGetSymbolAddress((void**)&p_ath,    g_attThi);
    cudaGetSymbolAddress((void**)&p_atl,    g_attTlo);
    cudaGetSymbolAddress((void**)&p_attp,   g_att_part);
    cudaGetSymbolAddress((void**)&p_emba,   g_emb_act);
    cudaGetSymbolAddress((void**)&p_embout, g_embout);

    cudaFuncSetAttribute(hgemm_k, cudaFuncAttributeMaxDynamicSharedMemorySize, HG_SMEM);
    cudaFuncSetAttribute(att1_k,  cudaFuncAttributeMaxDynamicSharedMemorySize, ATT_SMEM);
    cudaFuncSetAttribute(att2_k,  cudaFuncAttributeMaxDynamicSharedMemorySize, ATT_SMEM);

    wsplit4_k<<<dim3(32,32,4), dim3(32,32)>>>(Wq, Wk, Wv, W_out, p_wth, p_wtl);
    ln_kernel<<<MM, 256>>>(x, ln_w, ln_b, p_xnh, p_xnl);
    silu_emb_k<<<(BB*TEE)/256, 256>>>(emb, p_emba);

    dim3 ggrid(DD/128, MM/128);
    hgemm_k<<<ggrid, 512, HG_SMEM>>>(p_xnh, p_xnl, p_wth + 0*(size_t)DD*DD, p_wtl + 0*(size_t)DD*DD,
                                     bq, nullptr, nullptr, p_q, 0);
    hgemm_k<<<ggrid, 512, HG_SMEM>>>(p_xnh, p_xnl, p_wth + 1*(size_t)DD*DD, p_wtl + 1*(size_t)DD*DD,
                                     bk, mask, nullptr, p_k, 1);
    hgemm_k<<<ggrid, 512, HG_SMEM>>>(p_xnh, p_xnl, p_wth + 2*(size_t)DD*DD, p_wtl + 2*(size_t)DD*DD,
                                     bv, mask, nullptr, p_v, 2);

    qsoftmax_k<<<(MM*HH)/8, 256>>>(p_q, p_qh, p_ql);
    ksoftmaxT_k<<<BB*32, dim3(32,8)>>>(p_k, p_kTh, p_kTl);
    vsplitT_k<<<dim3(TT/32, DHH/32, BB*HH), dim3(32,32)>>>(p_v, p_vTh, p_vTl);

    att1_k<<<dim3(NCHUNK, BB*HH), 512, ATT_SMEM>>>(p_vTh, p_vTl, p_kTh, p_kTl, p_attp);
    att_reduce_k<<<(BB*HH*DHH*DHH)/256, 256>>>(p_attp, p_ath, p_atl);

    emb_gemm_k<<<dim3((2*DD)/256, BB), 256>>>(p_emba, W_emb, b_emb, p_embout);

    att2_k<<<dim3(MM/128, HH), 512, ATT_SMEM>>>(p_qh, p_ql, p_ath, p_atl, p_y);

    film_k<<<MM, 256>>>(p_y, ln2_w, ln2_b, p_embout, p_acth, p_actl);

    hgemm_k<<<ggrid, 512, HG_SMEM>>>(p_acth, p_actl, p_wth + 3*(size_t)DD*DD, p_wtl + 3*(size_t)DD*DD,
                                     b_out, nullptr, x, out, 3);
}

// round 5
// speedup vs baseline: 2.1531x; 1.0841x over previous
#include <cuda_runtime.h>
#include <cuda_bf16.h>
#include <math.h>
#include <stdint.h>

#define BB 4
#define TT 2048
#define DD 1024
#define HH 8
#define DHH 128
#define TEE 2048
#define MM (BB*TT)          // 8192 rows
#define NCHUNK 16

__device__ __forceinline__ uint32_t smem_to_u32(const void* p) {
    uint32_t a;
    asm("{ .reg .u64 t; cvta.to.shared.u64 t, %1; cvt.u32.u64 %0, t; }" : "=r"(a) : "l"(p));
    return a;
}

#define LDSM4(R, addr) \
    asm volatile("ldmatrix.sync.aligned.m8n8.x4.shared.b16 {%0,%1,%2,%3}, [%4];" \
        : "=r"((R)[0]), "=r"((R)[1]), "=r"((R)[2]), "=r"((R)[3]) : "r"(addr))

#define MMA_BF16(c, a, b0, b1) \
    asm volatile("mma.sync.aligned.m16n8k16.row.col.f32.bf16.bf16.f32 " \
        "{%0,%1,%2,%3}, {%4,%5,%6,%7}, {%8,%9}, {%0,%1,%2,%3};" \
        : "+f"((c)[0]), "+f"((c)[1]), "+f"((c)[2]), "+f"((c)[3]) \
        : "r"((a)[0]), "r"((a)[1]), "r"((a)[2]), "r"((a)[3]), "r"(b0), "r"(b1))

#define CP16(dst, src) \
    asm volatile("cp.async.cg.shared.global [%0], [%1], 16;" :: "r"(dst), "l"(src))
#define CP_COMMIT() asm volatile("cp.async.commit_group;")
#define CP_WAIT2()  asm volatile("cp.async.wait_group 2;")

// ======================= device scratch =======================
__device__ __nv_bfloat16 g_xnhi[MM*DD];
__device__ __nv_bfloat16 g_xnlo[MM*DD];
__device__ __nv_bfloat16 g_acthi[MM*DD];
__device__ __nv_bfloat16 g_actlo[MM*DD];
__device__ __nv_bfloat16 g_wthi[4][DD*DD];
__device__ __nv_bfloat16 g_wtlo[4][DD*DD];
__device__ float g_k [MM*DD];
__device__ float g_v [MM*DD];
__device__ float g_y [MM*DD];
__device__ __nv_bfloat16 g_qhi[MM*DD];
__device__ __nv_bfloat16 g_qlo[MM*DD];
__device__ __nv_bfloat16 g_kThi[MM*DD];
__device__ __nv_bfloat16 g_kTlo[MM*DD];
__device__ __nv_bfloat16 g_vThi[MM*DD];
__device__ __nv_bfloat16 g_vTlo[MM*DD];
__device__ float g_att_part[NCHUNK*BB*HH*DHH*DHH];
__device__ __nv_bfloat16 g_attThi[BB*HH*DHH*DHH];
__device__ __nv_bfloat16 g_attTlo[BB*HH*DHH*DHH];
__device__ float g_emb_act[BB*TEE];
__device__ float g_embout[BB*2*DD];

__device__ __forceinline__ void split_store4(__nv_bfloat16* ph, __nv_bfloat16* pl, float4 v) {
    __nv_bfloat162 h0 = __floats2bfloat162_rn(v.x, v.y);
    __nv_bfloat162 h1 = __floats2bfloat162_rn(v.z, v.w);
    float rx = v.x - __bfloat162float(h0.x);
    float ry = v.y - __bfloat162float(h0.y);
    float rz = v.z - __bfloat162float(h1.x);
    float rw = v.w - __bfloat162float(h1.y);
    __nv_bfloat162 l0 = __floats2bfloat162_rn(rx, ry);
    __nv_bfloat162 l1 = __floats2bfloat162_rn(rz, rw);
    uint2 uh; uh.x = *(uint32_t*)&h0; uh.y = *(uint32_t*)&h1;
    uint2 ul; ul.x = *(uint32_t*)&l0; ul.y = *(uint32_t*)&l1;
    *(uint2*)ph = uh;
    *(uint2*)pl = ul;
}

// ======================= LayerNorm -> bf16 hi/lo =======================
__global__ __launch_bounds__(256) void ln_kernel(const float* __restrict__ x,
                                                 const float* __restrict__ w,
                                                 const float* __restrict__ b,
                                                 __nv_bfloat16* __restrict__ outh,
                                                 __nv_bfloat16* __restrict__ outl)
{
    int row = blockIdx.x;
    int tid = threadIdx.x;
    const float4* xr = (const float4*)(x + (size_t)row*DD);
    float4 v = xr[tid];
    float s  = v.x+v.y+v.z+v.w;
    float ss = v.x*v.x+v.y*v.y+v.z*v.z+v.w*v.w;
    #pragma unroll
    for (int o=16;o>0;o>>=1){ s += __shfl_down_sync(0xffffffffu,s,o); ss += __shfl_down_sync(0xffffffffu,ss,o); }
    __shared__ float sm[8], sm2[8];
    int wid = tid>>5, lane = tid&31;
    if (lane==0){ sm[wid]=s; sm2[wid]=ss; }
    __syncthreads();
    if (tid==0){
        float a=0.f, c=0.f;
        #pragma unroll
        for (int i=0;i<8;i++){ a+=sm[i]; c+=sm2[i]; }
        float mean = a*(1.0f/DD);
        float var  = c*(1.0f/DD) - mean*mean;
        sm[0]=mean; sm2[0]=rsqrtf(var+1e-5f);
    }
    __syncthreads();
    float mean=sm[0], rinv=sm2[0];
    float4 wv=((const float4*)w)[tid];
    float4 bv=((const float4*)b)[tid];
    float4 o;
    o.x=(v.x-mean)*rinv*wv.x+bv.x;
    o.y=(v.y-mean)*rinv*wv.y+bv.y;
    o.z=(v.z-mean)*rinv*wv.z+bv.z;
    o.w=(v.w-mean)*rinv*wv.w+bv.w;
    split_store4(outh + (size_t)row*DD + tid*4, outl + (size_t)row*DD + tid*4, o);
}

// ======================= weight transpose + bf16 split (4 weights) ==========
__global__ __launch_bounds__(1024) void wsplit4_k(const float* __restrict__ W0,
                                                  const float* __restrict__ W1,
                                                  const float* __restrict__ W2,
                                                  const float* __restrict__ W3,
                                                  __nv_bfloat16* __restrict__ Thi,
                                                  __nv_bfloat16* __restrict__ Tlo)
{
    __shared__ float t[32][33];
    int tx = threadIdx.x, ty = threadIdx.y;
    int wsel = blockIdx.z;
    const float* W = (wsel==0)?W0:(wsel==1)?W1:(wsel==2)?W2:W3;
    t[ty][tx] = W[(size_t)(blockIdx.y*32+ty)*DD + blockIdx.x*32+tx];
    __syncthreads();
    int n = blockIdx.x*32 + ty;
    int k = blockIdx.y*32 + tx;
    float v = t[tx][ty];
    __nv_bfloat16 h = __float2bfloat16(v);
    size_t base = (size_t)wsel*DD*DD;
    Thi[base + (size_t)n*DD + k] = h;
    Tlo[base + (size_t)n*DD + k] = __float2bfloat16(v - __bfloat162float(h));
}

// ======================= HMMA GEMM with cp.async 4-stage pipeline ===========
// mode 0: softmax-over-dh epilogue -> Qh/Ql (bf16 hi/lo)
// mode 1: +bias+(1-mask)*-1e6 -> C
// mode 2: (+bias)*mask -> C
// mode 3: +bias+resid -> C
#define LDSE    40                        // smem row stride (elements)
#define TILE_B  (128*LDSE*2)              // 10240 bytes per tile
#define STAGE_B (4*TILE_B)                // 40960 bytes per stage
#define HG_SMEM (4*STAGE_B)               // 163840 bytes

__global__ __launch_bounds__(512, 1) void hgemm_k(
        const __nv_bfloat16* __restrict__ Ahi, const __nv_bfloat16* __restrict__ Alo,
        const __nv_bfloat16* __restrict__ Bhi, const __nv_bfloat16* __restrict__ Blo,
        const float* __restrict__ bias, const float* __restrict__ mask,
        const float* __restrict__ resid, float* __restrict__ C,
        __nv_bfloat16* __restrict__ Qh, __nv_bfloat16* __restrict__ Ql, int mode)
{
    extern __shared__ __nv_bfloat16 smbuf[];
    const int tid  = threadIdx.x;
    const int lane = tid & 31;
    const int w    = tid >> 5;
    const int wm   = w >> 2;
    const int wn   = w & 3;
    const int m0 = blockIdx.y * 128;
    const int n0 = blockIdx.x * 128;

    const uint32_t smb = smem_to_u32(smbuf);
    // copy mapping: thread -> (row, 16B chunk), one chunk per tile per stage
    const int lr = tid >> 2;
    const int lc = (tid & 3) * 8;
    const __nv_bfloat16* gA0 = Ahi + (size_t)(m0+lr)*DD + lc;
    const __nv_bfloat16* gA1 = Alo + (size_t)(m0+lr)*DD + lc;
    const __nv_bfloat16* gB0 = Bhi + (size_t)(n0+lr)*DD + lc;
    const __nv_bfloat16* gB1 = Blo + (size_t)(n0+lr)*DD + lc;
    const uint32_t sdst = smb + (lr*LDSE + lc)*2;

    const int arow  = wm*32 + (lane & 7) + ((lane >> 3) & 1) * 8;
    const int akoff = ((lane >> 4) & 1) * 8;
    const int brow  = wn*32 + (lane & 7) + ((lane >> 4) & 1) * 8;
    const int bkoff = ((lane >> 3) & 1) * 8;

    float acc[2][4][4];
    #pragma unroll
    for (int i=0;i<2;i++)
        #pragma unroll
        for (int j=0;j<4;j++)
            #pragma unroll
            for (int l=0;l<4;l++) acc[i][j][l]=0.f;

    // prologue: stages 0..2
    #pragma unroll
    for (int s = 0; s < 3; s++) {
        uint32_t d = sdst + s*STAGE_B;
        int k0 = s*32;
        CP16(d + 0*TILE_B, gA0 + k0);
        CP16(d + 1*TILE_B, gA1 + k0);
        CP16(d + 2*TILE_B, gB0 + k0);
        CP16(d + 3*TILE_B, gB1 + k0);
        CP_COMMIT();
    }

    for (int kc = 0; kc < 32; kc++) {
        CP_WAIT2();
        __syncthreads();
        if (kc + 3 < 32) {
            uint32_t d = sdst + ((kc+3)&3)*STAGE_B;
            int k0 = (kc+3)*32;
            CP16(d + 0*TILE_B, gA0 + k0);
            CP16(d + 1*TILE_B, gA1 + k0);
            CP16(d + 2*TILE_B, gB0 + k0);
            CP16(d + 3*TILE_B, gB1 + k0);
        }
        CP_COMMIT();

        uint32_t base = smb + (kc & 3)*STAGE_B;
        #pragma unroll
        for (int ks = 0; ks < 2; ks++) {
            uint32_t ah[2][4], al[2][4];
            #pragma unroll
            for (int mt = 0; mt < 2; mt++) {
                uint32_t ra = base + ((arow + mt*16)*LDSE + ks*16 + akoff) * 2;
                LDSM4(ah[mt], ra);
                LDSM4(al[mt], ra + TILE_B);
            }
            uint32_t bh[2][4], bl[2][4];
            #pragma unroll
            for (int nb = 0; nb < 2; nb++) {
                uint32_t rb = base + 2*TILE_B + ((brow + nb*16)*LDSE + ks*16 + bkoff) * 2;
                LDSM4(bh[nb], rb);
                LDSM4(bl[nb], rb + TILE_B);
            }
            #pragma unroll
            for (int mt = 0; mt < 2; mt++) {
                #pragma unroll
                for (int nt = 0; nt < 4; nt++) {
                    int nb = nt >> 1, sub = (nt & 1) * 2;
                    MMA_BF16(acc[mt][nt], ah[mt], bh[nb][sub], bh[nb][sub+1]);
                    MMA_BF16(acc[mt][nt], ah[mt], bl[nb][sub], bl[nb][sub+1]);
                    MMA_BF16(acc[mt][nt], al[mt], bh[nb][sub], bh[nb][sub+1]);
                }
            }
        }
    }

    const int t4 = lane >> 2;
    const int t2 = (lane & 3) * 2;

    // add bias (all modes)
    #pragma unroll
    for (int mt = 0; mt < 2; mt++)
        #pragma unroll
        for (int nt = 0; nt < 4; nt++) {
            int col = n0 + wn*32 + nt*8 + t2;
            float2 bi = *(const float2*)(bias + col);
            acc[mt][nt][0] += bi.x; acc[mt][nt][1] += bi.y;
            acc[mt][nt][2] += bi.x; acc[mt][nt][3] += bi.y;
        }

    if (mode == 0) {
        // fused softmax over the 128 cols (one head) per row, emit bf16 hi/lo
        __syncthreads();                       // smem reuse for reductions
        float* red  = (float*)smbuf;           // [128][4]
        float* red2 = red + 512;
        // --- row max ---
        float mrow[2][2];
        #pragma unroll
        for (int mt = 0; mt < 2; mt++) {
            float a0 = -1e30f, a1 = -1e30f;
            #pragma unroll
            for (int nt = 0; nt < 4; nt++) {
                a0 = fmaxf(a0, fmaxf(acc[mt][nt][0], acc[mt][nt][1]));
                a1 = fmaxf(a1, fmaxf(acc[mt][nt][2], acc[mt][nt][3]));
            }
            a0 = fmaxf(a0, __shfl_xor_sync(0xffffffffu, a0, 1));
            a0 = fmaxf(a0, __shfl_xor_sync(0xffffffffu, a0, 2));
            a1 = fmaxf(a1, __shfl_xor_sync(0xffffffffu, a1, 1));
            a1 = fmaxf(a1, __shfl_xor_sync(0xffffffffu, a1, 2));
            mrow[mt][0] = a0; mrow[mt][1] = a1;
            if ((lane & 3) == 0) {
                int r = wm*32 + mt*16 + t4;
                red[r*4 + wn] = a0;
                red[(r+8)*4 + wn] = a1;
            }
        }
        __syncthreads();
        #pragma unroll
        for (int mt = 0; mt < 2; mt++) {
            int r = wm*32 + mt*16 + t4;
            mrow[mt][0] = fmaxf(fmaxf(red[r*4+0], red[r*4+1]), fmaxf(red[r*4+2], red[r*4+3]));
            mrow[mt][1] = fmaxf(fmaxf(red[(r+8)*4+0], red[(r+8)*4+1]), fmaxf(red[(r+8)*4+2], red[(r+8)*4+3]));
        }
        // --- exp + row sum ---
        float srow[2][2];
        #pragma unroll
        for (int mt = 0; mt < 2; mt++) {
            float s0 = 0.f, s1 = 0.f;
            #pragma unroll
            for (int nt = 0; nt < 4; nt++) {
                acc[mt][nt][0] = expf(acc[mt][nt][0] - mrow[mt][0]);
                acc[mt][nt][1] = expf(acc[mt][nt][1] - mrow[mt][0]);
                acc[mt][nt][2] = expf(acc[mt][nt][2] - mrow[mt][1]);
                acc[mt][nt][3] = expf(acc[mt][nt][3] - mrow[mt][1]);
                s0 += acc[mt][nt][0] + acc[mt][nt][1];
                s1 += acc[mt][nt][2] + acc[mt][nt][3];
            }
            s0 += __shfl_xor_sync(0xffffffffu, s0, 1);
            s0 += __shfl_xor_sync(0xffffffffu, s0, 2);
            s1 += __shfl_xor_sync(0xffffffffu, s1, 1);
            s1 += __shfl_xor_sync(0xffffffffu, s1, 2);
            if ((lane & 3) == 0) {
                int r = wm*32 + mt*16 + t4;
                red2[r*4 + wn] = s0;
                red2[(r+8)*4 + wn] = s1;
            }
        }
        __syncthreads();
        #pragma unroll
        for (int mt = 0; mt < 2; mt++) {
            int r = wm*32 + mt*16 + t4;
            srow[mt][0] = 1.0f / (red2[r*4+0] + red2[r*4+1] + red2[r*4+2] + red2[r*4+3]);
            srow[mt][1] = 1.0f / (red2[(r+8)*4+0] + red2[(r+8)*4+1] + red2[(r+8)*4+2] + red2[(r+8)*4+3]);
        }
        // --- scale, split, store ---
        #pragma unroll
        for (int mt = 0; mt < 2; mt++) {
            int row0 = m0 + wm*32 + mt*16 + t4;
            int row1 = row0 + 8;
            #pragma unroll
            for (int nt = 0; nt < 4; nt++) {
                int col = n0 + wn*32 + nt*8 + t2;
                float v0 = acc[mt][nt][0] * srow[mt][0];
                float v1 = acc[mt][nt][1] * srow[mt][0];
                float v2 = acc[mt][nt][2] * srow[mt][1];
                float v3 = acc[mt][nt][3] * srow[mt][1];
                __nv_bfloat162 h0 = __floats2bfloat162_rn(v0, v1);
                __nv_bfloat162 h1 = __floats2bfloat162_rn(v2, v3);
                __nv_bfloat162 l0 = __floats2bfloat162_rn(v0 - __bfloat162float(h0.x), v1 - __bfloat162float(h0.y));
                __nv_bfloat162 l1 = __floats2bfloat162_rn(v2 - __bfloat162float(h1.x), v3 - __bfloat162float(h1.y));
                *(uint32_t*)(Qh + (size_t)row0*DD + col) = *(uint32_t*)&h0;
                *(uint32_t*)(Qh + (size_t)row1*DD + col) = *(uint32_t*)&h1;
                *(uint32_t*)(Ql + (size_t)row0*DD + col) = *(uint32_t*)&l0;
                *(uint32_t*)(Ql + (size_t)row1*DD + col) = *(uint32_t*)&l1;
            }
        }
        return;
    }

    #pragma unroll
    for (int mt = 0; mt < 2; mt++) {
        int row0 = m0 + wm*32 + mt*16 + t4;
        int row1 = row0 + 8;
        float m0v = 0.f, m1v = 0.f;
        if (mode == 1 || mode == 2) { m0v = mask[row0]; m1v = mask[row1]; }
        float add0 = (mode==1) ? (1.0f-m0v)*(-1000000.0f) : 0.f;
        float add1 = (mode==1) ? (1.0f-m1v)*(-1000000.0f) : 0.f;
        float mul0 = (mode==2) ? m0v : 1.f;
        float mul1 = (mode==2) ? m1v : 1.f;
        #pragma unroll
        for (int nt = 0; nt < 4; nt++) {
            int col = n0 + wn*32 + nt*8 + t2;
            float a0 = acc[mt][nt][0];
            float a1 = acc[mt][nt][1];
            float a2 = acc[mt][nt][2];
            float a3 = acc[mt][nt][3];
            if (mode == 1) { a0 += add0; a1 += add0; a2 += add1; a3 += add1; }
            else if (mode == 2) { a0 *= mul0; a1 *= mul0; a2 *= mul1; a3 *= mul1; }
            else if (mode == 3) {
                float2 r0 = *(const float2*)(resid + (size_t)row0*DD + col);
                float2 r1 = *(const float2*)(resid + (size_t)row1*DD + col);
                a0 += r0.x; a1 += r0.y; a2 += r1.x; a3 += r1.y;
            }
            *(float2*)(C + (size_t)row0*DD + col) = make_float2(a0, a1);
            *(float2*)(C + (size_t)row1*DD + col) = make_float2(a2, a3);
        }
    }
}

// ======================= softmax over time -> transposed bf16 hi/lo =========
__global__ void ksoftmaxT_k(const float* __restrict__ k,
                            __nv_bfloat16* __restrict__ kTh,
                            __nv_bfloat16* __restrict__ kTl)
{
    int b = blockIdx.x >> 5;
    int g = blockIdx.x & 31;
    int tx = threadIdx.x, ty = threadIdx.y;
    int d = g*32 + tx;
    float m = -INFINITY, s = 0.f;
    for (int t=ty; t<TT; t+=8){
        float val = k[((size_t)b*TT + t)*DD + d];
        float nm = fmaxf(m, val);
        s = s*expf(m-nm) + expf(val-nm);
        m = nm;
    }
    __shared__ float smax[8][32], ssum[8][32];
    smax[ty][tx]=m; ssum[ty][tx]=s;
    __syncthreads();
    if (ty==0){
        float M=smax[0][tx], S=ssum[0][tx];
        #pragma unroll
        for (int i=1;i<8;i++){
            float m2=smax[i][tx], s2=ssum[i][tx];
            float nm=fmaxf(M,m2);
            S = S*expf(M-nm) + s2*expf(m2-nm);
            M = nm;
        }
        smax[0][tx]=M; ssum[0][tx]=1.0f/S;
    }
    __syncthreads();
    float M=smax[0][tx], R=ssum[0][tx];
    __syncthreads();

    __shared__ __nv_bfloat16 sh[32][33], sl[32][33];
    int dg0 = g*32;
    int h = dg0 >> 7;
    int dl0 = dg0 & 127;
    size_t kbase = ((size_t)(b*HH + h))*DHH + dl0;

    for (int t0 = 0; t0 < TT; t0 += 32) {
        #pragma unroll
        for (int i = 0; i < 4; i++) {
            int t = t0 + ty + i*8;
            float val = expf(k[((size_t)b*TT + t)*DD + d] - M) * R;
            __nv_bfloat16 hv = __float2bfloat16(val);
            sh[tx][ty + i*8] = hv;
            sl[tx][ty + i*8] = __float2bfloat16(val - __bfloat162float(hv));
        }
        __syncthreads();
        #pragma unroll
        for (int i = 0; i < 4; i++) {
            int row = ty + i*8;
            kTh[(kbase + row)*TT + t0 + tx] = sh[row][tx];
            kTl[(kbase + row)*TT + t0 + tx] = sl[row][tx];
        }
        __syncthreads();
    }
}

// ======================= v transpose + split =======================
__global__ __launch_bounds__(1024) void vsplitT_k(const float* __restrict__ v,
                                                  __nv_bfloat16* __restrict__ vTh,
                                                  __nv_bfloat16* __restrict__ vTl)
{
    __shared__ float t[32][33];
    int tx = threadIdx.x, ty = threadIdx.y;
    int bh = blockIdx.z;
    int b = bh >> 3, h = bh & 7;
    int t0 = blockIdx.x * 32;
    int l0 = blockIdx.y * 32;
    t[ty][tx] = v[((size_t)(b*TT) + t0 + ty)*DD + h*DHH + l0 + tx];
    __syncthreads();
    float val = t[tx][ty];
    __nv_bfloat16 hv = __float2bfloat16(val);
    size_t idx = ((size_t)bh*DHH + l0 + ty)*TT + t0 + tx;
    vTh[idx] = hv;
    vTl[idx] = __float2bfloat16(val - __bfloat162float(hv));
}

// ======================= attention core HMMA ================================
#define LD2    136
#define ATE    (128*LD2)
#define ATT_SMEM (4*ATE*2)

__global__ __launch_bounds__(512, 1) void att1_k(
        const __nv_bfloat16* __restrict__ vTh, const __nv_bfloat16* __restrict__ vTl,
        const __nv_bfloat16* __restrict__ kTh, const __nv_bfloat16* __restrict__ kTl,
        float* __restrict__ part)
{
    extern __shared__ __nv_bfloat16 smbuf[];
    const int tid  = threadIdx.x;
    const int lane = tid & 31;
    const int w    = tid >> 5;
    const int wm   = w >> 2;
    const int wn   = w & 3;
    const int chunk = blockIdx.x;
    const int bh    = blockIdx.y;
    const int t0 = chunk * 128;

    #pragma unroll
    for (int i = 0; i < 4; i++) {
        int c = tid + i*512;
        int r = c >> 4;
        int c16 = (c & 15) * 8;
        size_t g = ((size_t)bh*DHH + r)*TT + t0 + c16;
        __nv_bfloat16* d = smbuf + r*LD2 + c16;
        *(uint4*)(d + 0*ATE) = *(const uint4*)(vTh + g);
        *(uint4*)(d + 1*ATE) = *(const uint4*)(vTl + g);
        *(uint4*)(d + 2*ATE) = *(const uint4*)(kTh + g);
        *(uint4*)(d + 3*ATE) = *(const uint4*)(kTl + g);
    }
    __syncthreads();

    const uint32_t smb = smem_to_u32(smbuf);
    const int arow  = wm*32 + (lane & 7) + ((lane >> 3) & 1) * 8;
    const int akoff = ((lane >> 4) & 1) * 8;
    const int brow  = wn*32 + (lane & 7) + ((lane >> 4) & 1) * 8;
    const int bkoff = ((lane >> 3) & 1) * 8;

    float acc[2][4][4];
    #pragma unroll
    for (int i=0;i<2;i++)
        #pragma unroll
        for (int j=0;j<4;j++)
            #pragma unroll
            for (int l=0;l<4;l++) acc[i][j][l]=0.f;

    #pragma unroll
    for (int ks = 0; ks < 8; ks++) {
        uint32_t ah[2][4], al[2][4];
        #pragma unroll
        for (int mt = 0; mt < 2; mt++) {
            uint32_t ra = smb + ((arow + mt*16)*LD2 + ks*16 + akoff) * 2;
            LDSM4(ah[mt], ra);
            LDSM4(al[mt], ra + ATE*2);
        }
        uint32_t bhf[2][4], blf[2][4];
        #pragma unroll
        for (int nb = 0; nb < 2; nb++) {
            uint32_t rb = smb + 2*ATE*2 + ((brow + nb*16)*LD2 + ks*16 + bkoff) * 2;
            LDSM4(bhf[nb], rb);
            LDSM4(blf[nb], rb + ATE*2);
        }
        #pragma unroll
        for (int mt = 0; mt < 2; mt++) {
            #pragma unroll
            for (int nt = 0; nt < 4; nt++) {
                int nb = nt >> 1, sub = (nt & 1) * 2;
                MMA_BF16(acc[mt][nt], ah[mt], bhf[nb][sub], bhf[nb][sub+1]);
                MMA_BF16(acc[mt][nt], ah[mt], blf[nb][sub], blf[nb][sub+1]);
                MMA_BF16(acc[mt][nt], al[mt], bhf[nb][sub], bhf[nb][sub+1]);
            }
        }
    }

    float* dst = part + ((size_t)(chunk*(BB*HH) + bh))*(DHH*DHH);
    const int t4 = lane >> 2;
    const int t2 = (lane & 3) * 2;
    #pragma unroll
    for (int mt = 0; mt < 2; mt++) {
        int row0 = wm*32 + mt*16 + t4;
        int row1 = row0 + 8;
        #pragma unroll
        for (int nt = 0; nt < 4; nt++) {
            int col = wn*32 + nt*8 + t2;
            *(float2*)(dst + row0*DHH + col) = make_float2(acc[mt][nt][0], acc[mt][nt][1]);
            *(float2*)(dst + row1*DHH + col) = make_float2(acc[mt][nt][2], acc[mt][nt][3]);
        }
    }
}

__global__ void att_reduce_k(const float* __restrict__ part,
                             __nv_bfloat16* __restrict__ ath,
                             __nv_bfloat16* __restrict__ atl)
{
    int i = blockIdx.x*256 + threadIdx.x;
    float s = 0.f;
    #pragma unroll
    for (int c=0;c<NCHUNK;c++) s += part[(size_t)c*(BB*HH*DHH*DHH) + i];
    __nv_bfloat16 h = __float2bfloat16(s);
    ath[i] = h;
    atl[i] = __float2bfloat16(s - __bfloat162float(h));
}

__global__ __launch_bounds__(512, 1) void att2_k(
        const __nv_bfloat16* __restrict__ qh, const __nv_bfloat16* __restrict__ ql,
        const __nv_bfloat16* __restrict__ ath, const __nv_bfloat16* __restrict__ atl,
        float* __restrict__ y)
{
    extern __shared__ __nv_bfloat16 smbuf[];
    const int tid  = threadIdx.x;
    const int lane = tid & 31;
    const int w    = tid >> 5;
    const int wm   = w >> 2;
    const int wn   = w & 3;
    const int m0 = blockIdx.x * 128;
    const int h  = blockIdx.y;
    const int bh = (m0 >> 11) * HH + h;

    #pragma unroll
    for (int i = 0; i < 4; i++) {
        int c = tid + i*512;
        int r = c >> 4;
        int c16 = (c & 15) * 8;
        size_t ga = (size_t)(m0 + r)*DD + h*DHH + c16;
        size_t gb = ((size_t)bh*DHH + r)*DHH + c16;
        __nv_bfloat16* d = smbuf + r*LD2 + c16;
        *(uint4*)(d + 0*ATE) = *(const uint4*)(qh + ga);
        *(uint4*)(d + 1*ATE) = *(const uint4*)(ql + ga);
        *(uint4*)(d + 2*ATE) = *(const uint4*)(ath + gb);
        *(uint4*)(d + 3*ATE) = *(const uint4*)(atl + gb);
    }
    __syncthreads();

    const uint32_t smb = smem_to_u32(smbuf);
    const int arow  = wm*32 + (lane & 7) + ((lane >> 3) & 1) * 8;
    const int akoff = ((lane >> 4) & 1) * 8;
    const int brow  = wn*32 + (lane & 7) + ((lane >> 4) & 1) * 8;
    const int bkoff = ((lane >> 3) & 1) * 8;

    float acc[2][4][4];
    #pragma unroll
    for (int i=0;i<2;i++)
        #pragma unroll
        for (int j=0;j<4;j++)
            #pragma unroll
            for (int l=0;l<4;l++) acc[i][j][l]=0.f;

    #pragma unroll
    for (int ks = 0; ks < 8; ks++) {
        uint32_t ah[2][4], al[2][4];
        #pragma unroll
        for (int mt = 0; mt < 2; mt++) {
            uint32_t ra = smb + ((arow + mt*16)*LD2 + ks*16 + akoff) * 2;
            LDSM4(ah[mt], ra);
            LDSM4(al[mt], ra + ATE*2);
        }
        uint32_t bhf[2][4], blf[2][4];
        #pragma unroll
        for (int nb = 0; nb < 2; nb++) {
            uint32_t rb = smb + 2*ATE*2 + ((brow + nb*16)*LD2 + ks*16 + bkoff) * 2;
            LDSM4(bhf[nb], rb);
            LDSM4(blf[nb], rb + ATE*2);
        }
        #pragma unroll
        for (int mt = 0; mt < 2; mt++) {
            #pragma unroll
            for (int nt = 0; nt < 4; nt++) {
                int nb = nt >> 1, sub = (nt & 1) * 2;
                MMA_BF16(acc[mt][nt], ah[mt], bhf[nb][sub], bhf[nb][sub+1]);
                MMA_BF16(acc[mt][nt], ah[mt], blf[nb][sub], blf[nb][sub+1]);
                MMA_BF16(acc[mt][nt], al[mt], bhf[nb][sub], bhf[nb][sub+1]);
            }
        }
    }

    const int t4 = lane >> 2;
    const int t2 = (lane & 3) * 2;
    #pragma unroll
    for (int mt = 0; mt < 2; mt++) {
        int row0 = m0 + wm*32 + mt*16 + t4;
        int row1 = row0 + 8;
        #pragma unroll
        for (int nt = 0; nt < 4; nt++) {
            int col = h*DHH + wn*32 + nt*8 + t2;
            *(float2*)(y + (size_t)row0*DD + col) = make_float2(acc[mt][nt][0], acc[mt][nt][1]);
            *(float2*)(y + (size_t)row1*DD + col) = make_float2(acc[mt][nt][2], acc[mt][nt][3]);
        }
    }
}

// ======================= emb path =======================
__global__ void silu_emb_k(const float* __restrict__ emb, float* __restrict__ out)
{
    int i = blockIdx.x*256 + threadIdx.x;
    float e = emb[i];
    out[i] = e / (1.0f + expf(-e));
}

__global__ __launch_bounds__(256) void emb_gemm_k(const float* __restrict__ ea,
                                                  const float* __restrict__ W,
                                                  const float* __restrict__ bias,
                                                  float* __restrict__ out)
{
    int n = blockIdx.x*256 + threadIdx.x;
    int b = blockIdx.y;
    const float* e = ea + b*TEE;
    float acc = 0.f;
    #pragma unroll 8
    for (int t=0;t<TEE;t++)
        acc = fmaf(e[t], W[(size_t)t*(2*DD) + n], acc);
    out[b*(2*DD) + n] = acc + bias[n];
}

// ======================= LN2 + FiLM + SiLU -> bf16 hi/lo =======================
__global__ __launch_bounds__(256) void film_k(const float* __restrict__ y,
                                              const float* __restrict__ w2,
                                              const float* __restrict__ b2,
                                              const float* __restrict__ embout,
                                              __nv_bfloat16* __restrict__ acth,
                                              __nv_bfloat16* __restrict__ actl)
{
    int row = blockIdx.x;
    int b = row / TT;
    int tid = threadIdx.x;
    const float4* yr = (const float4*)(y + (size_t)row*DD);
    float4 v = yr[tid];
    float s  = v.x+v.y+v.z+v.w;
    float ss = v.x*v.x+v.y*v.y+v.z*v.z+v.w*v.w;
    #pragma unroll
    for (int o=16;o>0;o>>=1){ s += __shfl_down_sync(0xffffffffu,s,o); ss += __shfl_down_sync(0xffffffffu,ss,o); }
    __shared__ float sm[8], sm2[8];
    int wid = tid>>5, lane = tid&31;
    if (lane==0){ sm[wid]=s; sm2[wid]=ss; }
    __syncthreads();
    if (tid==0){
        float a=0.f, c=0.f;
        #pragma unroll
        for (int i=0;i<8;i++){ a+=sm[i]; c+=sm2[i]; }
        float mean = a*(1.0f/DD);
        float var  = c*(1.0f/DD) - mean*mean;
        sm[0]=mean; sm2[0]=rsqrtf(var+1e-5f);
    }
    __syncthreads();
    float mean=sm[0], rinv=sm2[0];
    float4 wv=((const float4*)w2)[tid];
    float4 bv=((const float4*)b2)[tid];
    float4 sc=((const float4*)(embout + (size_t)b*(2*DD)))[tid];
    float4 sh=((const float4*)(embout + (size_t)b*(2*DD) + DD))[tid];
    float4 o;
    float h;
    h=(v.x-mean)*rinv*wv.x+bv.x; h=h*(1.0f+sc.x)+sh.x; o.x=h/(1.0f+expf(-h));
    h=(v.y-mean)*rinv*wv.y+bv.y; h=h*(1.0f+sc.y)+sh.y; o.y=h/(1.0f+expf(-h));
    h=(v.z-mean)*rinv*wv.z+bv.z; h=h*(1.0f+sc.z)+sh.z; o.z=h/(1.0f+expf(-h));
    h=(v.w-mean)*rinv*wv.w+bv.w; h=h*(1.0f+sc.w)+sh.w; o.w=h/(1.0f+expf(-h));
    split_store4(acth + (size_t)row*DD + tid*4, actl + (size_t)row*DD + tid*4, o);
}

// ======================= launch =======================
extern "C" void kernel_launch(void* const* d_in, const int* in_sizes, int n_in,
                              void* d_out, int out_size)
{
    (void)in_sizes; (void)n_in; (void)out_size;
    const float* x     = (const float*)d_in[0];
    const float* emb   = (const float*)d_in[1];
    const float* mask  = (const float*)d_in[2];
    const float* ln_w  = (const float*)d_in[4];
    const float* ln_b  = (const float*)d_in[5];
    const float* Wq    = (const float*)d_in[6];
    const float* bq    = (const float*)d_in[7];
    const float* Wk    = (const float*)d_in[8];
    const float* bk    = (const float*)d_in[9];
    const float* Wv    = (const float*)d_in[10];
    const float* bv    = (const float*)d_in[11];
    const float* W_emb = (const float*)d_in[12];
    const float* b_emb = (const float*)d_in[13];
    const float* ln2_w = (const float*)d_in[14];
    const float* ln2_b = (const float*)d_in[15];
    const float* W_out = (const float*)d_in[16];
    const float* b_out = (const float*)d_in[17];
    float* out = (float*)d_out;

    __nv_bfloat16 *p_xnh, *p_xnl, *p_acth, *p_actl, *p_wth, *p_wtl;
    __nv_bfloat16 *p_qh, *p_ql, *p_kTh, *p_kTl, *p_vTh, *p_vTl, *p_ath, *p_atl;
    float *p_k, *p_v, *p_y, *p_attp, *p_emba, *p_embout;
    cudaGetSymbolAddress((void**)&p_xnh,    g_xnhi);
    cudaGetSymbolAddress((void**)&p_xnl,    g_xnlo);
    cudaGetSymbolAddress((void**)&p_acth,   g_acthi);
    cudaGetSymbolAddress((void**)&p_actl,   g_actlo);
    cudaGetSymbolAddress((void**)&p_wth,    g_wthi);
    cudaGetSymbolAddress((void**)&p_wtl,    g_wtlo);
    cudaGetSymbolAddress((void**)&p_k,      g_k);
    cudaGetSymbolAddress((void**)&p_v,      g_v);
    cudaGetSymbolAddress((void**)&p_y,      g_y);
    cudaGetSymbolAddress((void**)&p_qh,     g_qhi);
    cudaGetSymbolAddress((void**)&p_ql,     g_qlo);
    cudaGetSymbolAddress((void**)&p_kTh,    g_kThi);
    cudaGetSymbolAddress((void**)&p_kTl,    g_kTlo);
    cudaGetSymbolAddress((void**)&p_vTh,    g_vThi);
    cudaGetSymbolAddress((void**)&p_vTl,    g_vTlo);
    cudaGetSymbolAddress((void**)&p_ath,    g_attThi);
    cudaGetSymbolAddress((void**)&p_atl,    g_attTlo);
    cudaGetSymbolAddress((void**)&p_attp,   g_att_part);
    cudaGetSymbolAddress((void**)&p_emba,   g_emb_act);
    cudaGetSymbolAddress((void**)&p_embout, g_embout);

    cudaFuncSetAttribute(hgemm_k, cudaFuncAttributeMaxDynamicSharedMemorySize, HG_SMEM);
    cudaFuncSetAttribute(att1_k,  cudaFuncAttributeMaxDynamicSharedMemorySize, ATT_SMEM);
    cudaFuncSetAttribute(att2_k,  cudaFuncAttributeMaxDynamicSharedMemorySize, ATT_SMEM);

    wsplit4_k<<<dim3(32,32,4), dim3(32,32)>>>(Wq, Wk, Wv, W_out, p_wth, p_wtl);
    ln_kernel<<<MM, 256>>>(x, ln_w, ln_b, p_xnh, p_xnl);
    silu_emb_k<<<(BB*TEE)/256, 256>>>(emb, p_emba);

    dim3 ggrid(DD/128, MM/128);
    // Q projection with fused softmax epilogue -> qh/ql
    hgemm_k<<<ggrid, 512, HG_SMEM>>>(p_xnh, p_xnl, p_wth + 0*(size_t)DD*DD, p_wtl + 0*(size_t)DD*DD,
                                     bq, nullptr, nullptr, nullptr, p_qh, p_ql, 0);
    hgemm_k<<<ggrid, 512, HG_SMEM>>>(p_xnh, p_xnl, p_wth + 1*(size_t)DD*DD, p_wtl + 1*(size_t)DD*DD,
                                     bk, mask, nullptr, p_k, nullptr, nullptr, 1);
    hgemm_k<<<ggrid, 512, HG_SMEM>>>(p_xnh, p_xnl, p_wth + 2*(size_t)DD*DD, p_wtl + 2*(size_t)DD*DD,
                                     bv, mask, nullptr, p_v, nullptr, nullptr, 2);

    ksoftmaxT_k<<<BB*32, dim3(32,8)>>>(p_k, p_kTh, p_kTl);
    vsplitT_k<<<dim3(TT/32, DHH/32, BB*HH), dim3(32,32)>>>(p_v, p_vTh, p_vTl);

    att1_k<<<dim3(NCHUNK, BB*HH), 512, ATT_SMEM>>>(p_vTh, p_vTl, p_kTh, p_kTl, p_attp);
    att_reduce_k<<<(BB*HH*DHH*DHH)/256, 256>>>(p_attp, p_ath, p_atl);

    emb_gemm_k<<<dim3((2*DD)/256, BB), 256>>>(p_emba, W_emb, b_emb, p_embout);

    att2_k<<<dim3(MM/128, HH), 512, ATT_SMEM>>>(p_qh, p_ql, p_ath, p_atl, p_y);

    film_k<<<MM, 256>>>(p_y, ln2_w, ln2_b, p_embout, p_acth, p_actl);

    hgemm_k<<<ggrid, 512, HG_SMEM>>>(p_acth, p_actl, p_wth + 3*(size_t)DD*DD, p_wtl + 3*(size_t)DD*DD,
                                     b_out, nullptr, x, out, nullptr, nullptr, 3);
}

// round 6
// speedup vs baseline: 2.1545x; 1.0006x over previous
#include <cuda_runtime.h>
#include <cuda_bf16.h>
#include <math.h>
#include <stdint.h>

#define BB 4
#define TT 2048
#define DD 1024
#define HH 8
#define DHH 128
#define TEE 2048
#define MM (BB*TT)          // 8192 rows
#define NCHUNK 16

__device__ __forceinline__ uint32_t smem_to_u32(const void* p) {
    uint32_t a;
    asm("{ .reg .u64 t; cvta.to.shared.u64 t, %1; cvt.u32.u64 %0, t; }" : "=r"(a) : "l"(p));
    return a;
}

#define LDSM4(R, addr) \
    asm volatile("ldmatrix.sync.aligned.m8n8.x4.shared.b16 {%0,%1,%2,%3}, [%4];" \
        : "=r"((R)[0]), "=r"((R)[1]), "=r"((R)[2]), "=r"((R)[3]) : "r"(addr))

#define MMA_BF16(c, a, b0, b1) \
    asm volatile("mma.sync.aligned.m16n8k16.row.col.f32.bf16.bf16.f32 " \
        "{%0,%1,%2,%3}, {%4,%5,%6,%7}, {%8,%9}, {%0,%1,%2,%3};" \
        : "+f"((c)[0]), "+f"((c)[1]), "+f"((c)[2]), "+f"((c)[3]) \
        : "r"((a)[0]), "r"((a)[1]), "r"((a)[2]), "r"((a)[3]), "r"(b0), "r"(b1))

#define CP16(dst, src) \
    asm volatile("cp.async.cg.shared.global [%0], [%1], 16;" :: "r"(dst), "l"(src))
#define CP_COMMIT() asm volatile("cp.async.commit_group;")
#define CP_WAIT2()  asm volatile("cp.async.wait_group 2;")

// ======================= device scratch =======================
__device__ __nv_bfloat16 g_xnhi[MM*DD];
__device__ __nv_bfloat16 g_xnlo[MM*DD];
__device__ __nv_bfloat16 g_acthi[MM*DD];
__device__ __nv_bfloat16 g_actlo[MM*DD];
__device__ __nv_bfloat16 g_wthi[4][DD*DD];
__device__ __nv_bfloat16 g_wtlo[4][DD*DD];
__device__ float g_k [MM*DD];
__device__ float g_v [MM*DD];
__device__ float g_y [MM*DD];
__device__ __nv_bfloat16 g_qhi[MM*DD];
__device__ __nv_bfloat16 g_qlo[MM*DD];
__device__ __nv_bfloat16 g_kThi[MM*DD];
__device__ __nv_bfloat16 g_kTlo[MM*DD];
__device__ __nv_bfloat16 g_vThi[MM*DD];
__device__ __nv_bfloat16 g_vTlo[MM*DD];
__device__ float g_att_part[NCHUNK*BB*HH*DHH*DHH];
__device__ __nv_bfloat16 g_attThi[BB*HH*DHH*DHH];
__device__ __nv_bfloat16 g_attTlo[BB*HH*DHH*DHH];
__device__ float g_emb_act[BB*TEE];
__device__ float g_embout[BB*2*DD];

__device__ __forceinline__ void split_store4(__nv_bfloat16* ph, __nv_bfloat16* pl, float4 v) {
    __nv_bfloat162 h0 = __floats2bfloat162_rn(v.x, v.y);
    __nv_bfloat162 h1 = __floats2bfloat162_rn(v.z, v.w);
    float rx = v.x - __bfloat162float(h0.x);
    float ry = v.y - __bfloat162float(h0.y);
    float rz = v.z - __bfloat162float(h1.x);
    float rw = v.w - __bfloat162float(h1.y);
    __nv_bfloat162 l0 = __floats2bfloat162_rn(rx, ry);
    __nv_bfloat162 l1 = __floats2bfloat162_rn(rz, rw);
    uint2 uh; uh.x = *(uint32_t*)&h0; uh.y = *(uint32_t*)&h1;
    uint2 ul; ul.x = *(uint32_t*)&l0; ul.y = *(uint32_t*)&l1;
    *(uint2*)ph = uh;
    *(uint2*)pl = ul;
}

// ======================= LayerNorm -> bf16 hi/lo =======================
__global__ __launch_bounds__(256) void ln_kernel(const float* __restrict__ x,
                                                 const float* __restrict__ w,
                                                 const float* __restrict__ b,
                                                 __nv_bfloat16* __restrict__ outh,
                                                 __nv_bfloat16* __restrict__ outl)
{
    int row = blockIdx.x;
    int tid = threadIdx.x;
    const float4* xr = (const float4*)(x + (size_t)row*DD);
    float4 v = xr[tid];
    float s  = v.x+v.y+v.z+v.w;
    float ss = v.x*v.x+v.y*v.y+v.z*v.z+v.w*v.w;
    #pragma unroll
    for (int o=16;o>0;o>>=1){ s += __shfl_down_sync(0xffffffffu,s,o); ss += __shfl_down_sync(0xffffffffu,ss,o); }
    __shared__ float sm[8], sm2[8];
    int wid = tid>>5, lane = tid&31;
    if (lane==0){ sm[wid]=s; sm2[wid]=ss; }
    __syncthreads();
    if (tid==0){
        float a=0.f, c=0.f;
        #pragma unroll
        for (int i=0;i<8;i++){ a+=sm[i]; c+=sm2[i]; }
        float mean = a*(1.0f/DD);
        float var  = c*(1.0f/DD) - mean*mean;
        sm[0]=mean; sm2[0]=rsqrtf(var+1e-5f);
    }
    __syncthreads();
    float mean=sm[0], rinv=sm2[0];
    float4 wv=((const float4*)w)[tid];
    float4 bv=((const float4*)b)[tid];
    float4 o;
    o.x=(v.x-mean)*rinv*wv.x+bv.x;
    o.y=(v.y-mean)*rinv*wv.y+bv.y;
    o.z=(v.z-mean)*rinv*wv.z+bv.z;
    o.w=(v.w-mean)*rinv*wv.w+bv.w;
    split_store4(outh + (size_t)row*DD + tid*4, outl + (size_t)row*DD + tid*4, o);
}

// ======================= weight transpose + bf16 split (4 weights) ==========
__global__ __launch_bounds__(1024) void wsplit4_k(const float* __restrict__ W0,
                                                  const float* __restrict__ W1,
                                                  const float* __restrict__ W2,
                                                  const float* __restrict__ W3,
                                                  __nv_bfloat16* __restrict__ Thi,
                                                  __nv_bfloat16* __restrict__ Tlo)
{
    __shared__ float t[32][33];
    int tx = threadIdx.x, ty = threadIdx.y;
    int wsel = blockIdx.z;
    const float* W = (wsel==0)?W0:(wsel==1)?W1:(wsel==2)?W2:W3;
    t[ty][tx] = W[(size_t)(blockIdx.y*32+ty)*DD + blockIdx.x*32+tx];
    __syncthreads();
    int n = blockIdx.x*32 + ty;
    int k = blockIdx.y*32 + tx;
    float v = t[tx][ty];
    __nv_bfloat16 h = __float2bfloat16(v);
    size_t base = (size_t)wsel*DD*DD;
    Thi[base + (size_t)n*DD + k] = h;
    Tlo[base + (size_t)n*DD + k] = __float2bfloat16(v - __bfloat162float(h));
}

// ======================= HMMA GEMM with cp.async 4-stage pipeline ===========
// mode 0: softmax-over-dh epilogue -> Qh/Ql (bf16 hi/lo)
// mode 1: +bias+(1-mask)*-1e6 -> C
// mode 2: (+bias)*mask -> C
// mode 3: +bias+resid -> C
#define LDSE    40                        // smem row stride (elements)
#define TILE_B  (128*LDSE*2)              // 10240 bytes per tile
#define STAGE_B (4*TILE_B)                // 40960 bytes per stage
#define HG_SMEM (4*STAGE_B)               // 163840 bytes

__global__ __launch_bounds__(512, 1) void hgemm_k(
        const __nv_bfloat16* __restrict__ Ahi, const __nv_bfloat16* __restrict__ Alo,
        const __nv_bfloat16* __restrict__ Bhi, const __nv_bfloat16* __restrict__ Blo,
        const float* __restrict__ bias, const float* __restrict__ mask,
        const float* __restrict__ resid, float* __restrict__ C,
        __nv_bfloat16* __restrict__ Qh, __nv_bfloat16* __restrict__ Ql, int mode)
{
    extern __shared__ __nv_bfloat16 smbuf[];
    const int tid  = threadIdx.x;
    const int lane = tid & 31;
    const int w    = tid >> 5;
    const int wm   = w >> 2;
    const int wn   = w & 3;
    const int m0 = blockIdx.y * 128;
    const int n0 = blockIdx.x * 128;

    const uint32_t smb = smem_to_u32(smbuf);
    const int lr = tid >> 2;
    const int lc = (tid & 3) * 8;
    const __nv_bfloat16* gA0 = Ahi + (size_t)(m0+lr)*DD + lc;
    const __nv_bfloat16* gA1 = Alo + (size_t)(m0+lr)*DD + lc;
    const __nv_bfloat16* gB0 = Bhi + (size_t)(n0+lr)*DD + lc;
    const __nv_bfloat16* gB1 = Blo + (size_t)(n0+lr)*DD + lc;
    const uint32_t sdst = smb + (lr*LDSE + lc)*2;

    const int arow  = wm*32 + (lane & 7) + ((lane >> 3) & 1) * 8;
    const int akoff = ((lane >> 4) & 1) * 8;
    const int brow  = wn*32 + (lane & 7) + ((lane >> 4) & 1) * 8;
    const int bkoff = ((lane >> 3) & 1) * 8;

    float acc[2][4][4];
    #pragma unroll
    for (int i=0;i<2;i++)
        #pragma unroll
        for (int j=0;j<4;j++)
            #pragma unroll
            for (int l=0;l<4;l++) acc[i][j][l]=0.f;

    // prologue: stages 0..2
    #pragma unroll
    for (int s = 0; s < 3; s++) {
        uint32_t d = sdst + s*STAGE_B;
        int k0 = s*32;
        CP16(d + 0*TILE_B, gA0 + k0);
        CP16(d + 1*TILE_B, gA1 + k0);
        CP16(d + 2*TILE_B, gB0 + k0);
        CP16(d + 3*TILE_B, gB1 + k0);
        CP_COMMIT();
    }

    for (int kc = 0; kc < 32; kc++) {
        CP_WAIT2();
        __syncthreads();
        if (kc + 3 < 32) {
            uint32_t d = sdst + ((kc+3)&3)*STAGE_B;
            int k0 = (kc+3)*32;
            CP16(d + 0*TILE_B, gA0 + k0);
            CP16(d + 1*TILE_B, gA1 + k0);
            CP16(d + 2*TILE_B, gB0 + k0);
            CP16(d + 3*TILE_B, gB1 + k0);
        }
        CP_COMMIT();

        uint32_t base = smb + (kc & 3)*STAGE_B;
        #pragma unroll
        for (int ks = 0; ks < 2; ks++) {
            uint32_t ah[2][4], al[2][4];
            #pragma unroll
            for (int mt = 0; mt < 2; mt++) {
                uint32_t ra = base + ((arow + mt*16)*LDSE + ks*16 + akoff) * 2;
                LDSM4(ah[mt], ra);
                LDSM4(al[mt], ra + TILE_B);
            }
            uint32_t bh[2][4], bl[2][4];
            #pragma unroll
            for (int nb = 0; nb < 2; nb++) {
                uint32_t rb = base + 2*TILE_B + ((brow + nb*16)*LDSE + ks*16 + bkoff) * 2;
                LDSM4(bh[nb], rb);
                LDSM4(bl[nb], rb + TILE_B);
            }
            // term-major ordering: 8 independent MMAs between same-acc reuses
            #pragma unroll
            for (int mt = 0; mt < 2; mt++)
                #pragma unroll
                for (int nt = 0; nt < 4; nt++) {
                    int nb = nt >> 1, sub = (nt & 1) * 2;
                    MMA_BF16(acc[mt][nt], ah[mt], bh[nb][sub], bh[nb][sub+1]);
                }
            #pragma unroll
            for (int mt = 0; mt < 2; mt++)
                #pragma unroll
                for (int nt = 0; nt < 4; nt++) {
                    int nb = nt >> 1, sub = (nt & 1) * 2;
                    MMA_BF16(acc[mt][nt], ah[mt], bl[nb][sub], bl[nb][sub+1]);
                }
            #pragma unroll
            for (int mt = 0; mt < 2; mt++)
                #pragma unroll
                for (int nt = 0; nt < 4; nt++) {
                    int nb = nt >> 1, sub = (nt & 1) * 2;
                    MMA_BF16(acc[mt][nt], al[mt], bh[nb][sub], bh[nb][sub+1]);
                }
        }
    }

    const int t4 = lane >> 2;
    const int t2 = (lane & 3) * 2;

    #pragma unroll
    for (int mt = 0; mt < 2; mt++)
        #pragma unroll
        for (int nt = 0; nt < 4; nt++) {
            int col = n0 + wn*32 + nt*8 + t2;
            float2 bi = *(const float2*)(bias + col);
            acc[mt][nt][0] += bi.x; acc[mt][nt][1] += bi.y;
            acc[mt][nt][2] += bi.x; acc[mt][nt][3] += bi.y;
        }

    if (mode == 0) {
        __syncthreads();
        float* red  = (float*)smbuf;
        float* red2 = red + 512;
        float mrow[2][2];
        #pragma unroll
        for (int mt = 0; mt < 2; mt++) {
            float a0 = -1e30f, a1 = -1e30f;
            #pragma unroll
            for (int nt = 0; nt < 4; nt++) {
                a0 = fmaxf(a0, fmaxf(acc[mt][nt][0], acc[mt][nt][1]));
                a1 = fmaxf(a1, fmaxf(acc[mt][nt][2], acc[mt][nt][3]));
            }
            a0 = fmaxf(a0, __shfl_xor_sync(0xffffffffu, a0, 1));
            a0 = fmaxf(a0, __shfl_xor_sync(0xffffffffu, a0, 2));
            a1 = fmaxf(a1, __shfl_xor_sync(0xffffffffu, a1, 1));
            a1 = fmaxf(a1, __shfl_xor_sync(0xffffffffu, a1, 2));
            mrow[mt][0] = a0; mrow[mt][1] = a1;
            if ((lane & 3) == 0) {
                int r = wm*32 + mt*16 + t4;
                red[r*4 + wn] = a0;
                red[(r+8)*4 + wn] = a1;
            }
        }
        __syncthreads();
        #pragma unroll
        for (int mt = 0; mt < 2; mt++) {
            int r = wm*32 + mt*16 + t4;
            mrow[mt][0] = fmaxf(fmaxf(red[r*4+0], red[r*4+1]), fmaxf(red[r*4+2], red[r*4+3]));
            mrow[mt][1] = fmaxf(fmaxf(red[(r+8)*4+0], red[(r+8)*4+1]), fmaxf(red[(r+8)*4+2], red[(r+8)*4+3]));
        }
        float srow[2][2];
        #pragma unroll
        for (int mt = 0; mt < 2; mt++) {
            float s0 = 0.f, s1 = 0.f;
            #pragma unroll
            for (int nt = 0; nt < 4; nt++) {
                acc[mt][nt][0] = expf(acc[mt][nt][0] - mrow[mt][0]);
                acc[mt][nt][1] = expf(acc[mt][nt][1] - mrow[mt][0]);
                acc[mt][nt][2] = expf(acc[mt][nt][2] - mrow[mt][1]);
                acc[mt][nt][3] = expf(acc[mt][nt][3] - mrow[mt][1]);
                s0 += acc[mt][nt][0] + acc[mt][nt][1];
                s1 += acc[mt][nt][2] + acc[mt][nt][3];
            }
            s0 += __shfl_xor_sync(0xffffffffu, s0, 1);
            s0 += __shfl_xor_sync(0xffffffffu, s0, 2);
            s1 += __shfl_xor_sync(0xffffffffu, s1, 1);
            s1 += __shfl_xor_sync(0xffffffffu, s1, 2);
            if ((lane & 3) == 0) {
                int r = wm*32 + mt*16 + t4;
                red2[r*4 + wn] = s0;
                red2[(r+8)*4 + wn] = s1;
            }
        }
        __syncthreads();
        #pragma unroll
        for (int mt = 0; mt < 2; mt++) {
            int r = wm*32 + mt*16 + t4;
            srow[mt][0] = 1.0f / (red2[r*4+0] + red2[r*4+1] + red2[r*4+2] + red2[r*4+3]);
            srow[mt][1] = 1.0f / (red2[(r+8)*4+0] + red2[(r+8)*4+1] + red2[(r+8)*4+2] + red2[(r+8)*4+3]);
        }
        #pragma unroll
        for (int mt = 0; mt < 2; mt++) {
            int row0 = m0 + wm*32 + mt*16 + t4;
            int row1 = row0 + 8;
            #pragma unroll
            for (int nt = 0; nt < 4; nt++) {
                int col = n0 + wn*32 + nt*8 + t2;
                float v0 = acc[mt][nt][0] * srow[mt][0];
                float v1 = acc[mt][nt][1] * srow[mt][0];
                float v2 = acc[mt][nt][2] * srow[mt][1];
                float v3 = acc[mt][nt][3] * srow[mt][1];
                __nv_bfloat162 h0 = __floats2bfloat162_rn(v0, v1);
                __nv_bfloat162 h1 = __floats2bfloat162_rn(v2, v3);
                __nv_bfloat162 l0 = __floats2bfloat162_rn(v0 - __bfloat162float(h0.x), v1 - __bfloat162float(h0.y));
                __nv_bfloat162 l1 = __floats2bfloat162_rn(v2 - __bfloat162float(h1.x), v3 - __bfloat162float(h1.y));
                *(uint32_t*)(Qh + (size_t)row0*DD + col) = *(uint32_t*)&h0;
                *(uint32_t*)(Qh + (size_t)row1*DD + col) = *(uint32_t*)&h1;
                *(uint32_t*)(Ql + (size_t)row0*DD + col) = *(uint32_t*)&l0;
                *(uint32_t*)(Ql + (size_t)row1*DD + col) = *(uint32_t*)&l1;
            }
        }
        return;
    }

    #pragma unroll
    for (int mt = 0; mt < 2; mt++) {
        int row0 = m0 + wm*32 + mt*16 + t4;
        int row1 = row0 + 8;
        float m0v = 0.f, m1v = 0.f;
        if (mode == 1 || mode == 2) { m0v = mask[row0]; m1v = mask[row1]; }
        float add0 = (mode==1) ? (1.0f-m0v)*(-1000000.0f) : 0.f;
        float add1 = (mode==1) ? (1.0f-m1v)*(-1000000.0f) : 0.f;
        float mul0 = (mode==2) ? m0v : 1.f;
        float mul1 = (mode==2) ? m1v : 1.f;
        #pragma unroll
        for (int nt = 0; nt < 4; nt++) {
            int col = n0 + wn*32 + nt*8 + t2;
            float a0 = acc[mt][nt][0];
            float a1 = acc[mt][nt][1];
            float a2 = acc[mt][nt][2];
            float a3 = acc[mt][nt][3];
            if (mode == 1) { a0 += add0; a1 += add0; a2 += add1; a3 += add1; }
            else if (mode == 2) { a0 *= mul0; a1 *= mul0; a2 *= mul1; a3 *= mul1; }
            else if (mode == 3) {
                float2 r0 = *(const float2*)(resid + (size_t)row0*DD + col);
                float2 r1 = *(const float2*)(resid + (size_t)row1*DD + col);
                a0 += r0.x; a1 += r0.y; a2 += r1.x; a3 += r1.y;
            }
            *(float2*)(C + (size_t)row0*DD + col) = make_float2(a0, a1);
            *(float2*)(C + (size_t)row1*DD + col) = make_float2(a2, a3);
        }
    }
}

// ======================= softmax over time -> transposed bf16 hi/lo =========
__global__ void ksoftmaxT_k(const float* __restrict__ k,
                            __nv_bfloat16* __restrict__ kTh,
                            __nv_bfloat16* __restrict__ kTl)
{
    int b = blockIdx.x >> 5;
    int g = blockIdx.x & 31;
    int tx = threadIdx.x, ty = threadIdx.y;
    int d = g*32 + tx;
    float m = -INFINITY, s = 0.f;
    for (int t=ty; t<TT; t+=8){
        float val = k[((size_t)b*TT + t)*DD + d];
        float nm = fmaxf(m, val);
        s = s*expf(m-nm) + expf(val-nm);
        m = nm;
    }
    __shared__ float smax[8][32], ssum[8][32];
    smax[ty][tx]=m; ssum[ty][tx]=s;
    __syncthreads();
    if (ty==0){
        float M=smax[0][tx], S=ssum[0][tx];
        #pragma unroll
        for (int i=1;i<8;i++){
            float m2=smax[i][tx], s2=ssum[i][tx];
            float nm=fmaxf(M,m2);
            S = S*expf(M-nm) + s2*expf(m2-nm);
            M = nm;
        }
        smax[0][tx]=M; ssum[0][tx]=1.0f/S;
    }
    __syncthreads();
    float M=smax[0][tx], R=ssum[0][tx];
    __syncthreads();

    __shared__ __nv_bfloat16 sh[32][33], sl[32][33];
    int dg0 = g*32;
    int h = dg0 >> 7;
    int dl0 = dg0 & 127;
    size_t kbase = ((size_t)(b*HH + h))*DHH + dl0;

    for (int t0 = 0; t0 < TT; t0 += 32) {
        #pragma unroll
        for (int i = 0; i < 4; i++) {
            int t = t0 + ty + i*8;
            float val = expf(k[((size_t)b*TT + t)*DD + d] - M) * R;
            __nv_bfloat16 hv = __float2bfloat16(val);
            sh[tx][ty + i*8] = hv;
            sl[tx][ty + i*8] = __float2bfloat16(val - __bfloat162float(hv));
        }
        __syncthreads();
        #pragma unroll
        for (int i = 0; i < 4; i++) {
            int row = ty + i*8;
            kTh[(kbase + row)*TT + t0 + tx] = sh[row][tx];
            kTl[(kbase + row)*TT + t0 + tx] = sl[row][tx];
        }
        __syncthreads();
    }
}

// ======================= v transpose + split =======================
__global__ __launch_bounds__(1024) void vsplitT_k(const float* __restrict__ v,
                                                  __nv_bfloat16* __restrict__ vTh,
                                                  __nv_bfloat16* __restrict__ vTl)
{
    __shared__ float t[32][33];
    int tx = threadIdx.x, ty = threadIdx.y;
    int bh = blockIdx.z;
    int b = bh >> 3, h = bh & 7;
    int t0 = blockIdx.x * 32;
    int l0 = blockIdx.y * 32;
    t[ty][tx] = v[((size_t)(b*TT) + t0 + ty)*DD + h*DHH + l0 + tx];
    __syncthreads();
    float val = t[tx][ty];
    __nv_bfloat16 hv = __float2bfloat16(val);
    size_t idx = ((size_t)bh*DHH + l0 + ty)*TT + t0 + tx;
    vTh[idx] = hv;
    vTl[idx] = __float2bfloat16(val - __bfloat162float(hv));
}

// ======================= attention core HMMA ================================
#define LD2    136
#define ATE    (128*LD2)
#define ATT_SMEM (4*ATE*2)

__global__ __launch_bounds__(512, 1) void att1_k(
        const __nv_bfloat16* __restrict__ vTh, const __nv_bfloat16* __restrict__ vTl,
        const __nv_bfloat16* __restrict__ kTh, const __nv_bfloat16* __restrict__ kTl,
        float* __restrict__ part)
{
    extern __shared__ __nv_bfloat16 smbuf[];
    const int tid  = threadIdx.x;
    const int lane = tid & 31;
    const int w    = tid >> 5;
    const int wm   = w >> 2;
    const int wn   = w & 3;
    const int chunk = blockIdx.x;
    const int bh    = blockIdx.y;
    const int t0 = chunk * 128;

    #pragma unroll
    for (int i = 0; i < 4; i++) {
        int c = tid + i*512;
        int r = c >> 4;
        int c16 = (c & 15) * 8;
        size_t g = ((size_t)bh*DHH + r)*TT + t0 + c16;
        __nv_bfloat16* d = smbuf + r*LD2 + c16;
        *(uint4*)(d + 0*ATE) = *(const uint4*)(vTh + g);
        *(uint4*)(d + 1*ATE) = *(const uint4*)(vTl + g);
        *(uint4*)(d + 2*ATE) = *(const uint4*)(kTh + g);
        *(uint4*)(d + 3*ATE) = *(const uint4*)(kTl + g);
    }
    __syncthreads();

    const uint32_t smb = smem_to_u32(smbuf);
    const int arow  = wm*32 + (lane & 7) + ((lane >> 3) & 1) * 8;
    const int akoff = ((lane >> 4) & 1) * 8;
    const int brow  = wn*32 + (lane & 7) + ((lane >> 4) & 1) * 8;
    const int bkoff = ((lane >> 3) & 1) * 8;

    float acc[2][4][4];
    #pragma unroll
    for (int i=0;i<2;i++)
        #pragma unroll
        for (int j=0;j<4;j++)
            #pragma unroll
            for (int l=0;l<4;l++) acc[i][j][l]=0.f;

    #pragma unroll
    for (int ks = 0; ks < 8; ks++) {
        uint32_t ah[2][4], al[2][4];
        #pragma unroll
        for (int mt = 0; mt < 2; mt++) {
            uint32_t ra = smb + ((arow + mt*16)*LD2 + ks*16 + akoff) * 2;
            LDSM4(ah[mt], ra);
            LDSM4(al[mt], ra + ATE*2);
        }
        uint32_t bhf[2][4], blf[2][4];
        #pragma unroll
        for (int nb = 0; nb < 2; nb++) {
            uint32_t rb = smb + 2*ATE*2 + ((brow + nb*16)*LD2 + ks*16 + bkoff) * 2;
            LDSM4(bhf[nb], rb);
            LDSM4(blf[nb], rb + ATE*2);
        }
        #pragma unroll
        for (int mt = 0; mt < 2; mt++)
            #pragma unroll
            for (int nt = 0; nt < 4; nt++) {
                int nb = nt >> 1, sub = (nt & 1) * 2;
                MMA_BF16(acc[mt][nt], ah[mt], bhf[nb][sub], bhf[nb][sub+1]);
            }
        #pragma unroll
        for (int mt = 0; mt < 2; mt++)
            #pragma unroll
            for (int nt = 0; nt < 4; nt++) {
                int nb = nt >> 1, sub = (nt & 1) * 2;
                MMA_BF16(acc[mt][nt], ah[mt], blf[nb][sub], blf[nb][sub+1]);
            }
        #pragma unroll
        for (int mt = 0; mt < 2; mt++)
            #pragma unroll
            for (int nt = 0; nt < 4; nt++) {
                int nb = nt >> 1, sub = (nt & 1) * 2;
                MMA_BF16(acc[mt][nt], al[mt], bhf[nb][sub], bhf[nb][sub+1]);
            }
    }

    float* dst = part + ((size_t)(chunk*(BB*HH) + bh))*(DHH*DHH);
    const int t4 = lane >> 2;
    const int t2 = (lane & 3) * 2;
    #pragma unroll
    for (int mt = 0; mt < 2; mt++) {
        int row0 = wm*32 + mt*16 + t4;
        int row1 = row0 + 8;
        #pragma unroll
        for (int nt = 0; nt < 4; nt++) {
            int col = wn*32 + nt*8 + t2;
            *(float2*)(dst + row0*DHH + col) = make_float2(acc[mt][nt][0], acc[mt][nt][1]);
            *(float2*)(dst + row1*DHH + col) = make_float2(acc[mt][nt][2], acc[mt][nt][3]);
        }
    }
}

__global__ void att_reduce_k(const float* __restrict__ part,
                             __nv_bfloat16* __restrict__ ath,
                             __nv_bfloat16* __restrict__ atl)
{
    int i = blockIdx.x*256 + threadIdx.x;
    float s = 0.f;
    #pragma unroll
    for (int c=0;c<NCHUNK;c++) s += part[(size_t)c*(BB*HH*DHH*DHH) + i];
    __nv_bfloat16 h = __float2bfloat16(s);
    ath[i] = h;
    atl[i] = __float2bfloat16(s - __bfloat162float(h));
}

__global__ __launch_bounds__(512, 1) void att2_k(
        const __nv_bfloat16* __restrict__ qh, const __nv_bfloat16* __restrict__ ql,
        const __nv_bfloat16* __restrict__ ath, const __nv_bfloat16* __restrict__ atl,
        float* __restrict__ y)
{
    extern __shared__ __nv_bfloat16 smbuf[];
    const int tid  = threadIdx.x;
    const int lane = tid & 31;
    const int w    = tid >> 5;
    const int wm   = w >> 2;
    const int wn   = w & 3;
    const int m0 = blockIdx.x * 128;
    const int h  = blockIdx.y;
    const int bh = (m0 >> 11) * HH + h;

    #pragma unroll
    for (int i = 0; i < 4; i++) {
        int c = tid + i*512;
        int r = c >> 4;
        int c16 = (c & 15) * 8;
        size_t ga = (size_t)(m0 + r)*DD + h*DHH + c16;
        size_t gb = ((size_t)bh*DHH + r)*DHH + c16;
        __nv_bfloat16* d = smbuf + r*LD2 + c16;
        *(uint4*)(d + 0*ATE) = *(const uint4*)(qh + ga);
        *(uint4*)(d + 1*ATE) = *(const uint4*)(ql + ga);
        *(uint4*)(d + 2*ATE) = *(const uint4*)(ath + gb);
        *(uint4*)(d + 3*ATE) = *(const uint4*)(atl + gb);
    }
    __syncthreads();

    const uint32_t smb = smem_to_u32(smbuf);
    const int arow  = wm*32 + (lane & 7) + ((lane >> 3) & 1) * 8;
    const int akoff = ((lane >> 4) & 1) * 8;
    const int brow  = wn*32 + (lane & 7) + ((lane >> 4) & 1) * 8;
    const int bkoff = ((lane >> 3) & 1) * 8;

    float acc[2][4][4];
    #pragma unroll
    for (int i=0;i<2;i++)
        #pragma unroll
        for (int j=0;j<4;j++)
            #pragma unroll
            for (int l=0;l<4;l++) acc[i][j][l]=0.f;

    #pragma unroll
    for (int ks = 0; ks < 8; ks++) {
        uint32_t ah[2][4], al[2][4];
        #pragma unroll
        for (int mt = 0; mt < 2; mt++) {
            uint32_t ra = smb + ((arow + mt*16)*LD2 + ks*16 + akoff) * 2;
            LDSM4(ah[mt], ra);
            LDSM4(al[mt], ra + ATE*2);
        }
        uint32_t bhf[2][4], blf[2][4];
        #pragma unroll
        for (int nb = 0; nb < 2; nb++) {
            uint32_t rb = smb + 2*ATE*2 + ((brow + nb*16)*LD2 + ks*16 + bkoff) * 2;
            LDSM4(bhf[nb], rb);
            LDSM4(blf[nb], rb + ATE*2);
        }
        #pragma unroll
        for (int mt = 0; mt < 2; mt++)
            #pragma unroll
            for (int nt = 0; nt < 4; nt++) {
                int nb = nt >> 1, sub = (nt & 1) * 2;
                MMA_BF16(acc[mt][nt], ah[mt], bhf[nb][sub], bhf[nb][sub+1]);
            }
        #pragma unroll
        for (int mt = 0; mt < 2; mt++)
            #pragma unroll
            for (int nt = 0; nt < 4; nt++) {
                int nb = nt >> 1, sub = (nt & 1) * 2;
                MMA_BF16(acc[mt][nt], ah[mt], blf[nb][sub], blf[nb][sub+1]);
            }
        #pragma unroll
        for (int mt = 0; mt < 2; mt++)
            #pragma unroll
            for (int nt = 0; nt < 4; nt++) {
                int nb = nt >> 1, sub = (nt & 1) * 2;
                MMA_BF16(acc[mt][nt], al[mt], bhf[nb][sub], bhf[nb][sub+1]);
            }
    }

    const int t4 = lane >> 2;
    const int t2 = (lane & 3) * 2;
    #pragma unroll
    for (int mt = 0; mt < 2; mt++) {
        int row0 = m0 + wm*32 + mt*16 + t4;
        int row1 = row0 + 8;
        #pragma unroll
        for (int nt = 0; nt < 4; nt++) {
            int col = h*DHH + wn*32 + nt*8 + t2;
            *(float2*)(y + (size_t)row0*DD + col) = make_float2(acc[mt][nt][0], acc[mt][nt][1]);
            *(float2*)(y + (size_t)row1*DD + col) = make_float2(acc[mt][nt][2], acc[mt][nt][3]);
        }
    }
}

// ======================= emb path =======================
__global__ void silu_emb_k(const float* __restrict__ emb, float* __restrict__ out)
{
    int i = blockIdx.x*256 + threadIdx.x;
    float e = emb[i];
    out[i] = e / (1.0f + expf(-e));
}

__global__ __launch_bounds__(256) void emb_gemm_k(const float* __restrict__ ea,
                                                  const float* __restrict__ W,
                                                  const float* __restrict__ bias,
                                                  float* __restrict__ out)
{
    int n = blockIdx.x*256 + threadIdx.x;
    int b = blockIdx.y;
    const float* e = ea + b*TEE;
    float acc = 0.f;
    #pragma unroll 8
    for (int t=0;t<TEE;t++)
        acc = fmaf(e[t], W[(size_t)t*(2*DD) + n], acc);
    out[b*(2*DD) + n] = acc + bias[n];
}

// ======================= LN2 + FiLM + SiLU -> bf16 hi/lo =======================
__global__ __launch_bounds__(256) void film_k(const float* __restrict__ y,
                                              const float* __restrict__ w2,
                                              const float* __restrict__ b2,
                                              const float* __restrict__ embout,
                                              __nv_bfloat16* __restrict__ acth,
                                              __nv_bfloat16* __restrict__ actl)
{
    int row = blockIdx.x;
    int b = row / TT;
    int tid = threadIdx.x;
    const float4* yr = (const float4*)(y + (size_t)row*DD);
    float4 v = yr[tid];
    float s  = v.x+v.y+v.z+v.w;
    float ss = v.x*v.x+v.y*v.y+v.z*v.z+v.w*v.w;
    #pragma unroll
    for (int o=16;o>0;o>>=1){ s += __shfl_down_sync(0xffffffffu,s,o); ss += __shfl_down_sync(0xffffffffu,ss,o); }
    __shared__ float sm[8], sm2[8];
    int wid = tid>>5, lane = tid&31;
    if (lane==0){ sm[wid]=s; sm2[wid]=ss; }
    __syncthreads();
    if (tid==0){
        float a=0.f, c=0.f;
        #pragma unroll
        for (int i=0;i<8;i++){ a+=sm[i]; c+=sm2[i]; }
        float mean = a*(1.0f/DD);
        float var  = c*(1.0f/DD) - mean*mean;
        sm[0]=mean; sm2[0]=rsqrtf(var+1e-5f);
    }
    __syncthreads();
    float mean=sm[0], rinv=sm2[0];
    float4 wv=((const float4*)w2)[tid];
    float4 bv=((const float4*)b2)[tid];
    float4 sc=((const float4*)(embout + (size_t)b*(2*DD)))[tid];
    float4 sh=((const float4*)(embout + (size_t)b*(2*DD) + DD))[tid];
    float4 o;
    float h;
    h=(v.x-mean)*rinv*wv.x+bv.x; h=h*(1.0f+sc.x)+sh.x; o.x=h/(1.0f+expf(-h));
    h=(v.y-mean)*rinv*wv.y+bv.y; h=h*(1.0f+sc.y)+sh.y; o.y=h/(1.0f+expf(-h));
    h=(v.z-mean)*rinv*wv.z+bv.z; h=h*(1.0f+sc.z)+sh.z; o.z=h/(1.0f+expf(-h));
    h=(v.w-mean)*rinv*wv.w+bv.w; h=h*(1.0f+sc.w)+sh.w; o.w=h/(1.0f+expf(-h));
    split_store4(acth + (size_t)row*DD + tid*4, actl + (size_t)row*DD + tid*4, o);
}

// ======================= launch =======================
extern "C" void kernel_launch(void* const* d_in, const int* in_sizes, int n_in,
                              void* d_out, int out_size)
{
    (void)in_sizes; (void)n_in; (void)out_size;
    const float* x     = (const float*)d_in[0];
    const float* emb   = (const float*)d_in[1];
    const float* mask  = (const float*)d_in[2];
    const float* ln_w  = (const float*)d_in[4];
    const float* ln_b  = (const float*)d_in[5];
    const float* Wq    = (const float*)d_in[6];
    const float* bq    = (const float*)d_in[7];
    const float* Wk    = (const float*)d_in[8];
    const float* bk    = (const float*)d_in[9];
    const float* Wv    = (const float*)d_in[10];
    const float* bv    = (const float*)d_in[11];
    const float* W_emb = (const float*)d_in[12];
    const float* b_emb = (const float*)d_in[13];
    const float* ln2_w = (const float*)d_in[14];
    const float* ln2_b = (const float*)d_in[15];
    const float* W_out = (const float*)d_in[16];
    const float* b_out = (const float*)d_in[17];
    float* out = (float*)d_out;

    __nv_bfloat16 *p_xnh, *p_xnl, *p_acth, *p_actl, *p_wth, *p_wtl;
    __nv_bfloat16 *p_qh, *p_ql, *p_kTh, *p_kTl, *p_vTh, *p_vTl, *p_ath, *p_atl;
    float *p_k, *p_v, *p_y, *p_attp, *p_emba, *p_embout;
    cudaGetSymbolAddress((void**)&p_xnh,    g_xnhi);
    cudaGetSymbolAddress((void**)&p_xnl,    g_xnlo);
    cudaGetSymbolAddress((void**)&p_acth,   g_acthi);
    cudaGetSymbolAddress((void**)&p_actl,   g_actlo);
    cudaGetSymbolAddress((void**)&p_wth,    g_wthi);
    cudaGetSymbolAddress((void**)&p_wtl,    g_wtlo);
    cudaGetSymbolAddress((void**)&p_k,      g_k);
    cudaGetSymbolAddress((void**)&p_v,      g_v);
    cudaGetSymbolAddress((void**)&p_y,      g_y);
    cudaGetSymbolAddress((void**)&p_qh,     g_qhi);
    cudaGetSymbolAddress((void**)&p_ql,     g_qlo);
    cudaGetSymbolAddress((void**)&p_kTh,    g_kThi);
    cudaGetSymbolAddress((void**)&p_kTl,    g_kTlo);
    cudaGetSymbolAddress((void**)&p_vTh,    g_vThi);
    cudaGetSymbolAddress((void**)&p_vTl,    g_vTlo);
    cudaGetSymbolAddress((void**)&p_ath,    g_attThi);
    cudaGetSymbolAddress((void**)&p_atl,    g_attTlo);
    cudaGetSymbolAddress((void**)&p_attp,   g_att_part);
    cudaGetSymbolAddress((void**)&p_emba,   g_emb_act);
    cudaGetSymbolAddress((void**)&p_embout, g_embout);

    cudaFuncSetAttribute(hgemm_k, cudaFuncAttributeMaxDynamicSharedMemorySize, HG_SMEM);
    cudaFuncSetAttribute(att1_k,  cudaFuncAttributeMaxDynamicSharedMemorySize, ATT_SMEM);
    cudaFuncSetAttribute(att2_k,  cudaFuncAttributeMaxDynamicSharedMemorySize, ATT_SMEM);

    wsplit4_k<<<dim3(32,32,4), dim3(32,32)>>>(Wq, Wk, Wv, W_out, p_wth, p_wtl);
    ln_kernel<<<MM, 256>>>(x, ln_w, ln_b, p_xnh, p_xnl);
    silu_emb_k<<<(BB*TEE)/256, 256>>>(emb, p_emba);

    dim3 ggrid(DD/128, MM/128);
    hgemm_k<<<ggrid, 512, HG_SMEM>>>(p_xnh, p_xnl, p_wth + 0*(size_t)DD*DD, p_wtl + 0*(size_t)DD*DD,
                                     bq, nullptr, nullptr, nullptr, p_qh, p_ql, 0);
    hgemm_k<<<ggrid, 512, HG_SMEM>>>(p_xnh, p_xnl, p_wth + 1*(size_t)DD*DD, p_wtl + 1*(size_t)DD*DD,
                                     bk, mask, nullptr, p_k, nullptr, nullptr, 1);
    hgemm_k<<<ggrid, 512, HG_SMEM>>>(p_xnh, p_xnl, p_wth + 2*(size_t)DD*DD, p_wtl + 2*(size_t)DD*DD,
                                     bv, mask, nullptr, p_v, nullptr, nullptr, 2);

    ksoftmaxT_k<<<BB*32, dim3(32,8)>>>(p_k, p_kTh, p_kTl);
    vsplitT_k<<<dim3(TT/32, DHH/32, BB*HH), dim3(32,32)>>>(p_v, p_vTh, p_vTl);

    att1_k<<<dim3(NCHUNK, BB*HH), 512, ATT_SMEM>>>(p_vTh, p_vTl, p_kTh, p_kTl, p_attp);
    att_reduce_k<<<(BB*HH*DHH*DHH)/256, 256>>>(p_attp, p_ath, p_atl);

    emb_gemm_k<<<dim3((2*DD)/256, BB), 256>>>(p_emba, W_emb, b_emb, p_embout);

    att2_k<<<dim3(MM/128, HH), 512, ATT_SMEM>>>(p_qh, p_ql, p_ath, p_atl, p_y);

    film_k<<<MM, 256>>>(p_y, ln2_w, ln2_b, p_embout, p_acth, p_actl);

    hgemm_k<<<ggrid, 512, HG_SMEM>>>(p_acth, p_actl, p_wth + 3*(size_t)DD*DD, p_wtl + 3*(size_t)DD*DD,
                                     b_out, nullptr, x, out, nullptr, nullptr, 3);
}

// round 7
// speedup vs baseline: 2.3160x; 1.0750x over previous
#include <cuda_runtime.h>
#include <cuda_bf16.h>
#include <math.h>
#include <stdint.h>

#define BB 4
#define TT 2048
#define DD 1024
#define HH 8
#define DHH 128
#define TEE 2048
#define MM (BB*TT)          // 8192 rows
#define NCHUNK 16

__device__ __forceinline__ uint32_t smem_to_u32(const void* p) {
    uint32_t a;
    asm("{ .reg .u64 t; cvta.to.shared.u64 t, %1; cvt.u32.u64 %0, t; }" : "=r"(a) : "l"(p));
    return a;
}

#define LDSM4(R, addr) \
    asm volatile("ldmatrix.sync.aligned.m8n8.x4.shared.b16 {%0,%1,%2,%3}, [%4];" \
        : "=r"((R)[0]), "=r"((R)[1]), "=r"((R)[2]), "=r"((R)[3]) : "r"(addr))

#define MMA_BF16(c, a, b0, b1) \
    asm volatile("mma.sync.aligned.m16n8k16.row.col.f32.bf16.bf16.f32 " \
        "{%0,%1,%2,%3}, {%4,%5,%6,%7}, {%8,%9}, {%0,%1,%2,%3};" \
        : "+f"((c)[0]), "+f"((c)[1]), "+f"((c)[2]), "+f"((c)[3]) \
        : "r"((a)[0]), "r"((a)[1]), "r"((a)[2]), "r"((a)[3]), "r"(b0), "r"(b1))

#define CP16(dst, src) \
    asm volatile("cp.async.cg.shared.global [%0], [%1], 16;" :: "r"(dst), "l"(src))
#define CP_COMMIT() asm volatile("cp.async.commit_group;")
#define CP_WAIT1()  asm volatile("cp.async.wait_group 1;")

// ======================= device scratch =======================
__device__ __nv_bfloat16 g_xnhi[MM*DD];
__device__ __nv_bfloat16 g_xnlo[MM*DD];
__device__ __nv_bfloat16 g_acthi[MM*DD];
__device__ __nv_bfloat16 g_actlo[MM*DD];
__device__ __nv_bfloat16 g_wthi[4][DD*DD];
__device__ __nv_bfloat16 g_wtlo[4][DD*DD];
__device__ float g_k [MM*DD];
__device__ float g_v [MM*DD];
__device__ float g_y [MM*DD];
__device__ __nv_bfloat16 g_qhi[MM*DD];
__device__ __nv_bfloat16 g_qlo[MM*DD];
__device__ __nv_bfloat16 g_kThi[MM*DD];
__device__ __nv_bfloat16 g_kTlo[MM*DD];
__device__ __nv_bfloat16 g_vThi[MM*DD];
__device__ __nv_bfloat16 g_vTlo[MM*DD];
__device__ float g_att_part[NCHUNK*BB*HH*DHH*DHH];
__device__ __nv_bfloat16 g_attThi[BB*HH*DHH*DHH];
__device__ __nv_bfloat16 g_attTlo[BB*HH*DHH*DHH];
__device__ float g_emb_act[BB*TEE];
__device__ float g_embout[BB*2*DD];

__device__ __forceinline__ void split_store4(__nv_bfloat16* ph, __nv_bfloat16* pl, float4 v) {
    __nv_bfloat162 h0 = __floats2bfloat162_rn(v.x, v.y);
    __nv_bfloat162 h1 = __floats2bfloat162_rn(v.z, v.w);
    float rx = v.x - __bfloat162float(h0.x);
    float ry = v.y - __bfloat162float(h0.y);
    float rz = v.z - __bfloat162float(h1.x);
    float rw = v.w - __bfloat162float(h1.y);
    __nv_bfloat162 l0 = __floats2bfloat162_rn(rx, ry);
    __nv_bfloat162 l1 = __floats2bfloat162_rn(rz, rw);
    uint2 uh; uh.x = *(uint32_t*)&h0; uh.y = *(uint32_t*)&h1;
    uint2 ul; ul.x = *(uint32_t*)&l0; ul.y = *(uint32_t*)&l1;
    *(uint2*)ph = uh;
    *(uint2*)pl = ul;
}

// ======================= LayerNorm -> bf16 hi/lo =======================
__global__ __launch_bounds__(256) void ln_kernel(const float* __restrict__ x,
                                                 const float* __restrict__ w,
                                                 const float* __restrict__ b,
                                                 __nv_bfloat16* __restrict__ outh,
                                                 __nv_bfloat16* __restrict__ outl)
{
    int row = blockIdx.x;
    int tid = threadIdx.x;
    const float4* xr = (const float4*)(x + (size_t)row*DD);
    float4 v = xr[tid];
    float s  = v.x+v.y+v.z+v.w;
    float ss = v.x*v.x+v.y*v.y+v.z*v.z+v.w*v.w;
    #pragma unroll
    for (int o=16;o>0;o>>=1){ s += __shfl_down_sync(0xffffffffu,s,o); ss += __shfl_down_sync(0xffffffffu,ss,o); }
    __shared__ float sm[8], sm2[8];
    int wid = tid>>5, lane = tid&31;
    if (lane==0){ sm[wid]=s; sm2[wid]=ss; }
    __syncthreads();
    if (tid==0){
        float a=0.f, c=0.f;
        #pragma unroll
        for (int i=0;i<8;i++){ a+=sm[i]; c+=sm2[i]; }
        float mean = a*(1.0f/DD);
        float var  = c*(1.0f/DD) - mean*mean;
        sm[0]=mean; sm2[0]=rsqrtf(var+1e-5f);
    }
    __syncthreads();
    float mean=sm[0], rinv=sm2[0];
    float4 wv=((const float4*)w)[tid];
    float4 bv=((const float4*)b)[tid];
    float4 o;
    o.x=(v.x-mean)*rinv*wv.x+bv.x;
    o.y=(v.y-mean)*rinv*wv.y+bv.y;
    o.z=(v.z-mean)*rinv*wv.z+bv.z;
    o.w=(v.w-mean)*rinv*wv.w+bv.w;
    split_store4(outh + (size_t)row*DD + tid*4, outl + (size_t)row*DD + tid*4, o);
}

// ======================= weight transpose + bf16 split (4 weights) ==========
__global__ __launch_bounds__(1024) void wsplit4_k(const float* __restrict__ W0,
                                                  const float* __restrict__ W1,
                                                  const float* __restrict__ W2,
                                                  const float* __restrict__ W3,
                                                  __nv_bfloat16* __restrict__ Thi,
                                                  __nv_bfloat16* __restrict__ Tlo)
{
    __shared__ float t[32][33];
    int tx = threadIdx.x, ty = threadIdx.y;
    int wsel = blockIdx.z;
    const float* W = (wsel==0)?W0:(wsel==1)?W1:(wsel==2)?W2:W3;
    t[ty][tx] = W[(size_t)(blockIdx.y*32+ty)*DD + blockIdx.x*32+tx];
    __syncthreads();
    int n = blockIdx.x*32 + ty;
    int k = blockIdx.y*32 + tx;
    float v = t[tx][ty];
    __nv_bfloat16 h = __float2bfloat16(v);
    size_t base = (size_t)wsel*DD*DD;
    Thi[base + (size_t)n*DD + k] = h;
    Tlo[base + (size_t)n*DD + k] = __float2bfloat16(v - __bfloat162float(h));
}

// ======================= HMMA GEMM, BM=64 BN=128, 2 CTAs/SM =================
// mode 0: softmax-over-dh epilogue -> Qh/Ql (bf16 hi/lo)
// mode 1: +bias+(1-mask)*-1e6 -> C
// mode 2: (+bias)*mask -> C
// mode 3: +bias+resid -> C
#define LDSE    40                        // smem row stride (elements)
#define TA_B    (64*LDSE*2)               // 5120 bytes (A tile, 64 rows)
#define TB_B    (128*LDSE*2)              // 10240 bytes (B tile, 128 rows)
#define STAGE_B (2*TA_B + 2*TB_B)         // 30720 bytes per stage
#define HG_SMEM (3*STAGE_B)               // 92160 bytes

__global__ __launch_bounds__(256, 2) void hgemm_k(
        const __nv_bfloat16* __restrict__ Ahi, const __nv_bfloat16* __restrict__ Alo,
        const __nv_bfloat16* __restrict__ Bhi, const __nv_bfloat16* __restrict__ Blo,
        const float* __restrict__ bias, const float* __restrict__ mask,
        const float* __restrict__ resid, float* __restrict__ C,
        __nv_bfloat16* __restrict__ Qh, __nv_bfloat16* __restrict__ Ql, int mode)
{
    extern __shared__ __nv_bfloat16 smbuf[];
    const int tid  = threadIdx.x;
    const int lane = tid & 31;
    const int w    = tid >> 5;      // 0..7
    const int wm   = w >> 2;        // 0..1 (M)
    const int wn   = w & 3;         // 0..3 (N)
    const int m0 = blockIdx.y * 64;
    const int n0 = blockIdx.x * 128;

    const uint32_t smb = smem_to_u32(smbuf);
    // A loader: 64 rows x 4 chunks = 256 chunks, 1 per thread
    const int ra = tid >> 2;            // 0..63
    const int ca = (tid & 3) * 8;       // elem col
    const __nv_bfloat16* gA0 = Ahi + (size_t)(m0+ra)*DD + ca;
    const __nv_bfloat16* gA1 = Alo + (size_t)(m0+ra)*DD + ca;
    const uint32_t dA = smb + (ra*LDSE + ca)*2;
    // B loader: 128 rows x 4 chunks = 512 chunks, 2 per thread (rows r, r+64)
    const __nv_bfloat16* gB0a = Bhi + (size_t)(n0+ra)*DD + ca;
    const __nv_bfloat16* gB0b = Bhi + (size_t)(n0+64+ra)*DD + ca;
    const __nv_bfloat16* gB1a = Blo + (size_t)(n0+ra)*DD + ca;
    const __nv_bfloat16* gB1b = Blo + (size_t)(n0+64+ra)*DD + ca;
    const uint32_t dBa = smb + 2*TA_B + (ra*LDSE + ca)*2;
    const uint32_t dBb = smb + 2*TA_B + ((64+ra)*LDSE + ca)*2;

    const int arow  = wm*32 + (lane & 7) + ((lane >> 3) & 1) * 8;   // 0..63
    const int akoff = ((lane >> 4) & 1) * 8;
    const int brow  = wn*32 + (lane & 7) + ((lane >> 4) & 1) * 8;   // 0..127
    const int bkoff = ((lane >> 3) & 1) * 8;

    float acc[2][4][4];
    #pragma unroll
    for (int i=0;i<2;i++)
        #pragma unroll
        for (int j=0;j<4;j++)
            #pragma unroll
            for (int l=0;l<4;l++) acc[i][j][l]=0.f;

    // prologue: stages 0,1
    #pragma unroll
    for (int s = 0; s < 2; s++) {
        int k0 = s*32;
        uint32_t so = s*STAGE_B;
        CP16(dA  + so,        gA0  + k0);
        CP16(dA  + so + TA_B, gA1  + k0);
        CP16(dBa + so,        gB0a + k0);
        CP16(dBb + so,        gB0b + k0);
        CP16(dBa + so + TB_B, gB1a + k0);
        CP16(dBb + so + TB_B, gB1b + k0);
        CP_COMMIT();
    }

    int st_r = 0, st_w = 2;
    for (int kc = 0; kc < 32; kc++) {
        CP_WAIT1();
        __syncthreads();
        if (kc + 2 < 32) {
            int k0 = (kc+2)*32;
            uint32_t so = st_w*STAGE_B;
            CP16(dA  + so,        gA0  + k0);
            CP16(dA  + so + TA_B, gA1  + k0);
            CP16(dBa + so,        gB0a + k0);
            CP16(dBb + so,        gB0b + k0);
            CP16(dBa + so + TB_B, gB1a + k0);
            CP16(dBb + so + TB_B, gB1b + k0);
        }
        CP_COMMIT();

        uint32_t base = smb + st_r*STAGE_B;
        #pragma unroll
        for (int ks = 0; ks < 2; ks++) {
            uint32_t ah[2][4], al[2][4];
            #pragma unroll
            for (int mt = 0; mt < 2; mt++) {
                uint32_t raddr = base + ((arow + mt*16)*LDSE + ks*16 + akoff) * 2;
                LDSM4(ah[mt], raddr);
                LDSM4(al[mt], raddr + TA_B);
            }
            uint32_t bh[2][4], bl[2][4];
            #pragma unroll
            for (int nb = 0; nb < 2; nb++) {
                uint32_t rb = base + 2*TA_B + ((brow + nb*16)*LDSE + ks*16 + bkoff) * 2;
                LDSM4(bh[nb], rb);
                LDSM4(bl[nb], rb + TB_B);
            }
            #pragma unroll
            for (int mt = 0; mt < 2; mt++)
                #pragma unroll
                for (int nt = 0; nt < 4; nt++) {
                    int nb = nt >> 1, sub = (nt & 1) * 2;
                    MMA_BF16(acc[mt][nt], ah[mt], bh[nb][sub], bh[nb][sub+1]);
                }
            #pragma unroll
            for (int mt = 0; mt < 2; mt++)
                #pragma unroll
                for (int nt = 0; nt < 4; nt++) {
                    int nb = nt >> 1, sub = (nt & 1) * 2;
                    MMA_BF16(acc[mt][nt], ah[mt], bl[nb][sub], bl[nb][sub+1]);
                }
            #pragma unroll
            for (int mt = 0; mt < 2; mt++)
                #pragma unroll
                for (int nt = 0; nt < 4; nt++) {
                    int nb = nt >> 1, sub = (nt & 1) * 2;
                    MMA_BF16(acc[mt][nt], al[mt], bh[nb][sub], bh[nb][sub+1]);
                }
        }
        if (++st_r == 3) st_r = 0;
        if (++st_w == 3) st_w = 0;
    }

    const int t4 = lane >> 2;
    const int t2 = (lane & 3) * 2;

    #pragma unroll
    for (int mt = 0; mt < 2; mt++)
        #pragma unroll
        for (int nt = 0; nt < 4; nt++) {
            int col = n0 + wn*32 + nt*8 + t2;
            float2 bi = *(const float2*)(bias + col);
            acc[mt][nt][0] += bi.x; acc[mt][nt][1] += bi.y;
            acc[mt][nt][2] += bi.x; acc[mt][nt][3] += bi.y;
        }

    if (mode == 0) {
        // fused softmax over 128 cols (one head), 64 rows in this block
        __syncthreads();
        float* red  = (float*)smbuf;    // [64][4]
        float* red2 = red + 256;
        float mrow[2][2];
        #pragma unroll
        for (int mt = 0; mt < 2; mt++) {
            float a0 = -1e30f, a1 = -1e30f;
            #pragma unroll
            for (int nt = 0; nt < 4; nt++) {
                a0 = fmaxf(a0, fmaxf(acc[mt][nt][0], acc[mt][nt][1]));
                a1 = fmaxf(a1, fmaxf(acc[mt][nt][2], acc[mt][nt][3]));
            }
            a0 = fmaxf(a0, __shfl_xor_sync(0xffffffffu, a0, 1));
            a0 = fmaxf(a0, __shfl_xor_sync(0xffffffffu, a0, 2));
            a1 = fmaxf(a1, __shfl_xor_sync(0xffffffffu, a1, 1));
            a1 = fmaxf(a1, __shfl_xor_sync(0xffffffffu, a1, 2));
            if ((lane & 3) == 0) {
                int r = wm*32 + mt*16 + t4;
                red[r*4 + wn] = a0;
                red[(r+8)*4 + wn] = a1;
            }
        }
        __syncthreads();
        #pragma unroll
        for (int mt = 0; mt < 2; mt++) {
            int r = wm*32 + mt*16 + t4;
            mrow[mt][0] = fmaxf(fmaxf(red[r*4+0], red[r*4+1]), fmaxf(red[r*4+2], red[r*4+3]));
            mrow[mt][1] = fmaxf(fmaxf(red[(r+8)*4+0], red[(r+8)*4+1]), fmaxf(red[(r+8)*4+2], red[(r+8)*4+3]));
        }
        float srow[2][2];
        #pragma unroll
        for (int mt = 0; mt < 2; mt++) {
            float s0 = 0.f, s1 = 0.f;
            #pragma unroll
            for (int nt = 0; nt < 4; nt++) {
                acc[mt][nt][0] = expf(acc[mt][nt][0] - mrow[mt][0]);
                acc[mt][nt][1] = expf(acc[mt][nt][1] - mrow[mt][0]);
                acc[mt][nt][2] = expf(acc[mt][nt][2] - mrow[mt][1]);
                acc[mt][nt][3] = expf(acc[mt][nt][3] - mrow[mt][1]);
                s0 += acc[mt][nt][0] + acc[mt][nt][1];
                s1 += acc[mt][nt][2] + acc[mt][nt][3];
            }
            s0 += __shfl_xor_sync(0xffffffffu, s0, 1);
            s0 += __shfl_xor_sync(0xffffffffu, s0, 2);
            s1 += __shfl_xor_sync(0xffffffffu, s1, 1);
            s1 += __shfl_xor_sync(0xffffffffu, s1, 2);
            if ((lane & 3) == 0) {
                int r = wm*32 + mt*16 + t4;
                red2[r*4 + wn] = s0;
                red2[(r+8)*4 + wn] = s1;
            }
        }
        __syncthreads();
        #pragma unroll
        for (int mt = 0; mt < 2; mt++) {
            int r = wm*32 + mt*16 + t4;
            srow[mt][0] = 1.0f / (red2[r*4+0] + red2[r*4+1] + red2[r*4+2] + red2[r*4+3]);
            srow[mt][1] = 1.0f / (red2[(r+8)*4+0] + red2[(r+8)*4+1] + red2[(r+8)*4+2] + red2[(r+8)*4+3]);
        }
        #pragma unroll
        for (int mt = 0; mt < 2; mt++) {
            int row0 = m0 + wm*32 + mt*16 + t4;
            int row1 = row0 + 8;
            #pragma unroll
            for (int nt = 0; nt < 4; nt++) {
                int col = n0 + wn*32 + nt*8 + t2;
                float v0 = acc[mt][nt][0] * srow[mt][0];
                float v1 = acc[mt][nt][1] * srow[mt][0];
                float v2 = acc[mt][nt][2] * srow[mt][1];
                float v3 = acc[mt][nt][3] * srow[mt][1];
                __nv_bfloat162 h0 = __floats2bfloat162_rn(v0, v1);
                __nv_bfloat162 h1 = __floats2bfloat162_rn(v2, v3);
                __nv_bfloat162 l0 = __floats2bfloat162_rn(v0 - __bfloat162float(h0.x), v1 - __bfloat162float(h0.y));
                __nv_bfloat162 l1 = __floats2bfloat162_rn(v2 - __bfloat162float(h1.x), v3 - __bfloat162float(h1.y));
                *(uint32_t*)(Qh + (size_t)row0*DD + col) = *(uint32_t*)&h0;
                *(uint32_t*)(Qh + (size_t)row1*DD + col) = *(uint32_t*)&h1;
                *(uint32_t*)(Ql + (size_t)row0*DD + col) = *(uint32_t*)&l0;
                *(uint32_t*)(Ql + (size_t)row1*DD + col) = *(uint32_t*)&l1;
            }
        }
        return;
    }

    #pragma unroll
    for (int mt = 0; mt < 2; mt++) {
        int row0 = m0 + wm*32 + mt*16 + t4;
        int row1 = row0 + 8;
        float m0v = 0.f, m1v = 0.f;
        if (mode == 1 || mode == 2) { m0v = mask[row0]; m1v = mask[row1]; }
        float add0 = (mode==1) ? (1.0f-m0v)*(-1000000.0f) : 0.f;
        float add1 = (mode==1) ? (1.0f-m1v)*(-1000000.0f) : 0.f;
        float mul0 = (mode==2) ? m0v : 1.f;
        float mul1 = (mode==2) ? m1v : 1.f;
        #pragma unroll
        for (int nt = 0; nt < 4; nt++) {
            int col = n0 + wn*32 + nt*8 + t2;
            float a0 = acc[mt][nt][0];
            float a1 = acc[mt][nt][1];
            float a2 = acc[mt][nt][2];
            float a3 = acc[mt][nt][3];
            if (mode == 1) { a0 += add0; a1 += add0; a2 += add1; a3 += add1; }
            else if (mode == 2) { a0 *= mul0; a1 *= mul0; a2 *= mul1; a3 *= mul1; }
            else if (mode == 3) {
                float2 r0 = *(const float2*)(resid + (size_t)row0*DD + col);
                float2 r1 = *(const float2*)(resid + (size_t)row1*DD + col);
                a0 += r0.x; a1 += r0.y; a2 += r1.x; a3 += r1.y;
            }
            *(float2*)(C + (size_t)row0*DD + col) = make_float2(a0, a1);
            *(float2*)(C + (size_t)row1*DD + col) = make_float2(a2, a3);
        }
    }
}

// ======================= softmax over time -> transposed bf16 hi/lo =========
__global__ void ksoftmaxT_k(const float* __restrict__ k,
                            __nv_bfloat16* __restrict__ kTh,
                            __nv_bfloat16* __restrict__ kTl)
{
    int b = blockIdx.x >> 5;
    int g = blockIdx.x & 31;
    int tx = threadIdx.x, ty = threadIdx.y;
    int d = g*32 + tx;
    float m = -INFINITY, s = 0.f;
    for (int t=ty; t<TT; t+=8){
        float val = k[((size_t)b*TT + t)*DD + d];
        float nm = fmaxf(m, val);
        s = s*expf(m-nm) + expf(val-nm);
        m = nm;
    }
    __shared__ float smax[8][32], ssum[8][32];
    smax[ty][tx]=m; ssum[ty][tx]=s;
    __syncthreads();
    if (ty==0){
        float M=smax[0][tx], S=ssum[0][tx];
        #pragma unroll
        for (int i=1;i<8;i++){
            float m2=smax[i][tx], s2=ssum[i][tx];
            float nm=fmaxf(M,m2);
            S = S*expf(M-nm) + s2*expf(m2-nm);
            M = nm;
        }
        smax[0][tx]=M; ssum[0][tx]=1.0f/S;
    }
    __syncthreads();
    float M=smax[0][tx], R=ssum[0][tx];
    __syncthreads();

    __shared__ __nv_bfloat16 sh[32][33], sl[32][33];
    int dg0 = g*32;
    int h = dg0 >> 7;
    int dl0 = dg0 & 127;
    size_t kbase = ((size_t)(b*HH + h))*DHH + dl0;

    for (int t0 = 0; t0 < TT; t0 += 32) {
        #pragma unroll
        for (int i = 0; i < 4; i++) {
            int t = t0 + ty + i*8;
            float val = expf(k[((size_t)b*TT + t)*DD + d] - M) * R;
            __nv_bfloat16 hv = __float2bfloat16(val);
            sh[tx][ty + i*8] = hv;
            sl[tx][ty + i*8] = __float2bfloat16(val - __bfloat162float(hv));
        }
        __syncthreads();
        #pragma unroll
        for (int i = 0; i < 4; i++) {
            int row = ty + i*8;
            kTh[(kbase + row)*TT + t0 + tx] = sh[row][tx];
            kTl[(kbase + row)*TT + t0 + tx] = sl[row][tx];
        }
        __syncthreads();
    }
}

// ======================= v transpose + split =======================
__global__ __launch_bounds__(1024) void vsplitT_k(const float* __restrict__ v,
                                                  __nv_bfloat16* __restrict__ vTh,
                                                  __nv_bfloat16* __restrict__ vTl)
{
    __shared__ float t[32][33];
    int tx = threadIdx.x, ty = threadIdx.y;
    int bh = blockIdx.z;
    int b = bh >> 3, h = bh & 7;
    int t0 = blockIdx.x * 32;
    int l0 = blockIdx.y * 32;
    t[ty][tx] = v[((size_t)(b*TT) + t0 + ty)*DD + h*DHH + l0 + tx];
    __syncthreads();
    float val = t[tx][ty];
    __nv_bfloat16 hv = __float2bfloat16(val);
    size_t idx = ((size_t)bh*DHH + l0 + ty)*TT + t0 + tx;
    vTh[idx] = hv;
    vTl[idx] = __float2bfloat16(val - __bfloat162float(hv));
}

// ======================= attention core HMMA ================================
#define LD2    136
#define ATE    (128*LD2)
#define ATT_SMEM (4*ATE*2)

__global__ __launch_bounds__(512, 1) void att1_k(
        const __nv_bfloat16* __restrict__ vTh, const __nv_bfloat16* __restrict__ vTl,
        const __nv_bfloat16* __restrict__ kTh, const __nv_bfloat16* __restrict__ kTl,
        float* __restrict__ part)
{
    extern __shared__ __nv_bfloat16 smbuf[];
    const int tid  = threadIdx.x;
    const int lane = tid & 31;
    const int w    = tid >> 5;
    const int wm   = w >> 2;
    const int wn   = w & 3;
    const int chunk = blockIdx.x;
    const int bh    = blockIdx.y;
    const int t0 = chunk * 128;

    #pragma unroll
    for (int i = 0; i < 4; i++) {
        int c = tid + i*512;
        int r = c >> 4;
        int c16 = (c & 15) * 8;
        size_t g = ((size_t)bh*DHH + r)*TT + t0 + c16;
        __nv_bfloat16* d = smbuf + r*LD2 + c16;
        *(uint4*)(d + 0*ATE) = *(const uint4*)(vTh + g);
        *(uint4*)(d + 1*ATE) = *(const uint4*)(vTl + g);
        *(uint4*)(d + 2*ATE) = *(const uint4*)(kTh + g);
        *(uint4*)(d + 3*ATE) = *(const uint4*)(kTl + g);
    }
    __syncthreads();

    const uint32_t smb = smem_to_u32(smbuf);
    const int arow  = wm*32 + (lane & 7) + ((lane >> 3) & 1) * 8;
    const int akoff = ((lane >> 4) & 1) * 8;
    const int brow  = wn*32 + (lane & 7) + ((lane >> 4) & 1) * 8;
    const int bkoff = ((lane >> 3) & 1) * 8;

    float acc[2][4][4];
    #pragma unroll
    for (int i=0;i<2;i++)
        #pragma unroll
        for (int j=0;j<4;j++)
            #pragma unroll
            for (int l=0;l<4;l++) acc[i][j][l]=0.f;

    #pragma unroll
    for (int ks = 0; ks < 8; ks++) {
        uint32_t ah[2][4], al[2][4];
        #pragma unroll
        for (int mt = 0; mt < 2; mt++) {
            uint32_t ra = smb + ((arow + mt*16)*LD2 + ks*16 + akoff) * 2;
            LDSM4(ah[mt], ra);
            LDSM4(al[mt], ra + ATE*2);
        }
        uint32_t bhf[2][4], blf[2][4];
        #pragma unroll
        for (int nb = 0; nb < 2; nb++) {
            uint32_t rb = smb + 2*ATE*2 + ((brow + nb*16)*LD2 + ks*16 + bkoff) * 2;
            LDSM4(bhf[nb], rb);
            LDSM4(blf[nb], rb + ATE*2);
        }
        #pragma unroll
        for (int mt = 0; mt < 2; mt++)
            #pragma unroll
            for (int nt = 0; nt < 4; nt++) {
                int nb = nt >> 1, sub = (nt & 1) * 2;
                MMA_BF16(acc[mt][nt], ah[mt], bhf[nb][sub], bhf[nb][sub+1]);
            }
        #pragma unroll
        for (int mt = 0; mt < 2; mt++)
            #pragma unroll
            for (int nt = 0; nt < 4; nt++) {
                int nb = nt >> 1, sub = (nt & 1) * 2;
                MMA_BF16(acc[mt][nt], ah[mt], blf[nb][sub], blf[nb][sub+1]);
            }
        #pragma unroll
        for (int mt = 0; mt < 2; mt++)
            #pragma unroll
            for (int nt = 0; nt < 4; nt++) {
                int nb = nt >> 1, sub = (nt & 1) * 2;
                MMA_BF16(acc[mt][nt], al[mt], bhf[nb][sub], bhf[nb][sub+1]);
            }
    }

    float* dst = part + ((size_t)(chunk*(BB*HH) + bh))*(DHH*DHH);
    const int t4 = lane >> 2;
    const int t2 = (lane & 3) * 2;
    #pragma unroll
    for (int mt = 0; mt < 2; mt++) {
        int row0 = wm*32 + mt*16 + t4;
        int row1 = row0 + 8;
        #pragma unroll
        for (int nt = 0; nt < 4; nt++) {
            int col = wn*32 + nt*8 + t2;
            *(float2*)(dst + row0*DHH + col) = make_float2(acc[mt][nt][0], acc[mt][nt][1]);
            *(float2*)(dst + row1*DHH + col) = make_float2(acc[mt][nt][2], acc[mt][nt][3]);
        }
    }
}

__global__ void att_reduce_k(const float* __restrict__ part,
                             __nv_bfloat16* __restrict__ ath,
                             __nv_bfloat16* __restrict__ atl)
{
    int i = blockIdx.x*256 + threadIdx.x;
    float s = 0.f;
    #pragma unroll
    for (int c=0;c<NCHUNK;c++) s += part[(size_t)c*(BB*HH*DHH*DHH) + i];
    __nv_bfloat16 h = __float2bfloat16(s);
    ath[i] = h;
    atl[i] = __float2bfloat16(s - __bfloat162float(h));
}

__global__ __launch_bounds__(512, 1) void att2_k(
        const __nv_bfloat16* __restrict__ qh, const __nv_bfloat16* __restrict__ ql,
        const __nv_bfloat16* __restrict__ ath, const __nv_bfloat16* __restrict__ atl,
        float* __restrict__ y)
{
    extern __shared__ __nv_bfloat16 smbuf[];
    const int tid  = threadIdx.x;
    const int lane = tid & 31;
    const int w    = tid >> 5;
    const int wm   = w >> 2;
    const int wn   = w & 3;
    const int m0 = blockIdx.x * 128;
    const int h  = blockIdx.y;
    const int bh = (m0 >> 11) * HH + h;

    #pragma unroll
    for (int i = 0; i < 4; i++) {
        int c = tid + i*512;
        int r = c >> 4;
        int c16 = (c & 15) * 8;
        size_t ga = (size_t)(m0 + r)*DD + h*DHH + c16;
        size_t gb = ((size_t)bh*DHH + r)*DHH + c16;
        __nv_bfloat16* d = smbuf + r*LD2 + c16;
        *(uint4*)(d + 0*ATE) = *(const uint4*)(qh + ga);
        *(uint4*)(d + 1*ATE) = *(const uint4*)(ql + ga);
        *(uint4*)(d + 2*ATE) = *(const uint4*)(ath + gb);
        *(uint4*)(d + 3*ATE) = *(const uint4*)(atl + gb);
    }
    __syncthreads();

    const uint32_t smb = smem_to_u32(smbuf);
    const int arow  = wm*32 + (lane & 7) + ((lane >> 3) & 1) * 8;
    const int akoff = ((lane >> 4) & 1) * 8;
    const int brow  = wn*32 + (lane & 7) + ((lane >> 4) & 1) * 8;
    const int bkoff = ((lane >> 3) & 1) * 8;

    float acc[2][4][4];
    #pragma unroll
    for (int i=0;i<2;i++)
        #pragma unroll
        for (int j=0;j<4;j++)
            #pragma unroll
            for (int l=0;l<4;l++) acc[i][j][l]=0.f;

    #pragma unroll
    for (int ks = 0; ks < 8; ks++) {
        uint32_t ah[2][4], al[2][4];
        #pragma unroll
        for (int mt = 0; mt < 2; mt++) {
            uint32_t ra = smb + ((arow + mt*16)*LD2 + ks*16 + akoff) * 2;
            LDSM4(ah[mt], ra);
            LDSM4(al[mt], ra + ATE*2);
        }
        uint32_t bhf[2][4], blf[2][4];
        #pragma unroll
        for (int nb = 0; nb < 2; nb++) {
            uint32_t rb = smb + 2*ATE*2 + ((brow + nb*16)*LD2 + ks*16 + bkoff) * 2;
            LDSM4(bhf[nb], rb);
            LDSM4(blf[nb], rb + ATE*2);
        }
        #pragma unroll
        for (int mt = 0; mt < 2; mt++)
            #pragma unroll
            for (int nt = 0; nt < 4; nt++) {
                int nb = nt >> 1, sub = (nt & 1) * 2;
                MMA_BF16(acc[mt][nt], ah[mt], bhf[nb][sub], bhf[nb][sub+1]);
            }
        #pragma unroll
        for (int mt = 0; mt < 2; mt++)
            #pragma unroll
            for (int nt = 0; nt < 4; nt++) {
                int nb = nt >> 1, sub = (nt & 1) * 2;
                MMA_BF16(acc[mt][nt], ah[mt], blf[nb][sub], blf[nb][sub+1]);
            }
        #pragma unroll
        for (int mt = 0; mt < 2; mt++)
            #pragma unroll
            for (int nt = 0; nt < 4; nt++) {
                int nb = nt >> 1, sub = (nt & 1) * 2;
                MMA_BF16(acc[mt][nt], al[mt], bhf[nb][sub], bhf[nb][sub+1]);
            }
    }

    const int t4 = lane >> 2;
    const int t2 = (lane & 3) * 2;
    #pragma unroll
    for (int mt = 0; mt < 2; mt++) {
        int row0 = m0 + wm*32 + mt*16 + t4;
        int row1 = row0 + 8;
        #pragma unroll
        for (int nt = 0; nt < 4; nt++) {
            int col = h*DHH + wn*32 + nt*8 + t2;
            *(float2*)(y + (size_t)row0*DD + col) = make_float2(acc[mt][nt][0], acc[mt][nt][1]);
            *(float2*)(y + (size_t)row1*DD + col) = make_float2(acc[mt][nt][2], acc[mt][nt][3]);
        }
    }
}

// ======================= emb path =======================
__global__ void silu_emb_k(const float* __restrict__ emb, float* __restrict__ out)
{
    int i = blockIdx.x*256 + threadIdx.x;
    float e = emb[i];
    out[i] = e / (1.0f + expf(-e));
}

__global__ __launch_bounds__(256) void emb_gemm_k(const float* __restrict__ ea,
                                                  const float* __restrict__ W,
                                                  const float* __restrict__ bias,
                                                  float* __restrict__ out)
{
    int n = blockIdx.x*256 + threadIdx.x;
    int b = blockIdx.y;
    const float* e = ea + b*TEE;
    float acc = 0.f;
    #pragma unroll 8
    for (int t=0;t<TEE;t++)
        acc = fmaf(e[t], W[(size_t)t*(2*DD) + n], acc);
    out[b*(2*DD) + n] = acc + bias[n];
}

// ======================= LN2 + FiLM + SiLU -> bf16 hi/lo =======================
__global__ __launch_bounds__(256) void film_k(const float* __restrict__ y,
                                              const float* __restrict__ w2,
                                              const float* __restrict__ b2,
                                              const float* __restrict__ embout,
                                              __nv_bfloat16* __restrict__ acth,
                                              __nv_bfloat16* __restrict__ actl)
{
    int row = blockIdx.x;
    int b = row / TT;
    int tid = threadIdx.x;
    const float4* yr = (const float4*)(y + (size_t)row*DD);
    float4 v = yr[tid];
    float s  = v.x+v.y+v.z+v.w;
    float ss = v.x*v.x+v.y*v.y+v.z*v.z+v.w*v.w;
    #pragma unroll
    for (int o=16;o>0;o>>=1){ s += __shfl_down_sync(0xffffffffu,s,o); ss += __shfl_down_sync(0xffffffffu,ss,o); }
    __shared__ float sm[8], sm2[8];
    int wid = tid>>5, lane = tid&31;
    if (lane==0){ sm[wid]=s; sm2[wid]=ss; }
    __syncthreads();
    if (tid==0){
        float a=0.f, c=0.f;
        #pragma unroll
        for (int i=0;i<8;i++){ a+=sm[i]; c+=sm2[i]; }
        float mean = a*(1.0f/DD);
        float var  = c*(1.0f/DD) - mean*mean;
        sm[0]=mean; sm2[0]=rsqrtf(var+1e-5f);
    }
    __syncthreads();
    float mean=sm[0], rinv=sm2[0];
    float4 wv=((const float4*)w2)[tid];
    float4 bv=((const float4*)b2)[tid];
    float4 sc=((const float4*)(embout + (size_t)b*(2*DD)))[tid];
    float4 sh=((const float4*)(embout + (size_t)b*(2*DD) + DD))[tid];
    float4 o;
    float h;
    h=(v.x-mean)*rinv*wv.x+bv.x; h=h*(1.0f+sc.x)+sh.x; o.x=h/(1.0f+expf(-h));
    h=(v.y-mean)*rinv*wv.y+bv.y; h=h*(1.0f+sc.y)+sh.y; o.y=h/(1.0f+expf(-h));
    h=(v.z-mean)*rinv*wv.z+bv.z; h=h*(1.0f+sc.z)+sh.z; o.z=h/(1.0f+expf(-h));
    h=(v.w-mean)*rinv*wv.w+bv.w; h=h*(1.0f+sc.w)+sh.w; o.w=h/(1.0f+expf(-h));
    split_store4(acth + (size_t)row*DD + tid*4, actl + (size_t)row*DD + tid*4, o);
}

// ======================= launch =======================
extern "C" void kernel_launch(void* const* d_in, const int* in_sizes, int n_in,
                              void* d_out, int out_size)
{
    (void)in_sizes; (void)n_in; (void)out_size;
    const float* x     = (const float*)d_in[0];
    const float* emb   = (const float*)d_in[1];
    const float* mask  = (const float*)d_in[2];
    const float* ln_w  = (const float*)d_in[4];
    const float* ln_b  = (const float*)d_in[5];
    const float* Wq    = (const float*)d_in[6];
    const float* bq    = (const float*)d_in[7];
    const float* Wk    = (const float*)d_in[8];
    const float* bk    = (const float*)d_in[9];
    const float* Wv    = (const float*)d_in[10];
    const float* bv    = (const float*)d_in[11];
    const float* W_emb = (const float*)d_in[12];
    const float* b_emb = (const float*)d_in[13];
    const float* ln2_w = (const float*)d_in[14];
    const float* ln2_b = (const float*)d_in[15];
    const float* W_out = (const float*)d_in[16];
    const float* b_out = (const float*)d_in[17];
    float* out = (float*)d_out;

    __nv_bfloat16 *p_xnh, *p_xnl, *p_acth, *p_actl, *p_wth, *p_wtl;
    __nv_bfloat16 *p_qh, *p_ql, *p_kTh, *p_kTl, *p_vTh, *p_vTl, *p_ath, *p_atl;
    float *p_k, *p_v, *p_y, *p_attp, *p_emba, *p_embout;
    cudaGetSymbolAddress((void**)&p_xnh,    g_xnhi);
    cudaGetSymbolAddress((void**)&p_xnl,    g_xnlo);
    cudaGetSymbolAddress((void**)&p_acth,   g_acthi);
    cudaGetSymbolAddress((void**)&p_actl,   g_actlo);
    cudaGetSymbolAddress((void**)&p_wth,    g_wthi);
    cudaGetSymbolAddress((void**)&p_wtl,    g_wtlo);
    cudaGetSymbolAddress((void**)&p_k,      g_k);
    cudaGetSymbolAddress((void**)&p_v,      g_v);
    cudaGetSymbolAddress((void**)&p_y,      g_y);
    cudaGetSymbolAddress((void**)&p_qh,     g_qhi);
    cudaGetSymbolAddress((void**)&p_ql,     g_qlo);
    cudaGetSymbolAddress((void**)&p_kTh,    g_kThi);
    cudaGetSymbolAddress((void**)&p_kTl,    g_kTlo);
    cudaGetSymbolAddress((void**)&p_vTh,    g_vThi);
    cudaGetSymbolAddress((void**)&p_vTl,    g_vTlo);
    cudaGetSymbolAddress((void**)&p_ath,    g_attThi);
    cudaGetSymbolAddress((void**)&p_atl,    g_attTlo);
    cudaGetSymbolAddress((void**)&p_attp,   g_att_part);
    cudaGetSymbolAddress((void**)&p_emba,   g_emb_act);
    cudaGetSymbolAddress((void**)&p_embout, g_embout);

    cudaFuncSetAttribute(hgemm_k, cudaFuncAttributeMaxDynamicSharedMemorySize, HG_SMEM);
    cudaFuncSetAttribute(att1_k,  cudaFuncAttributeMaxDynamicSharedMemorySize, ATT_SMEM);
    cudaFuncSetAttribute(att2_k,  cudaFuncAttributeMaxDynamicSharedMemorySize, ATT_SMEM);

    wsplit4_k<<<dim3(32,32,4), dim3(32,32)>>>(Wq, Wk, Wv, W_out, p_wth, p_wtl);
    ln_kernel<<<MM, 256>>>(x, ln_w, ln_b, p_xnh, p_xnl);
    silu_emb_k<<<(BB*TEE)/256, 256>>>(emb, p_emba);

    dim3 ggrid(DD/128, MM/64);    // (8, 128) = 1024 blocks, 256 threads
    hgemm_k<<<ggrid, 256, HG_SMEM>>>(p_xnh, p_xnl, p_wth + 0*(size_t)DD*DD, p_wtl + 0*(size_t)DD*DD,
                                     bq, nullptr, nullptr, nullptr, p_qh, p_ql, 0);
    hgemm_k<<<ggrid, 256, HG_SMEM>>>(p_xnh, p_xnl, p_wth + 1*(size_t)DD*DD, p_wtl + 1*(size_t)DD*DD,
                                     bk, mask, nullptr, p_k, nullptr, nullptr, 1);
    hgemm_k<<<ggrid, 256, HG_SMEM>>>(p_xnh, p_xnl, p_wth + 2*(size_t)DD*DD, p_wtl + 2*(size_t)DD*DD,
                                     bv, mask, nullptr, p_v, nullptr, nullptr, 2);

    ksoftmaxT_k<<<BB*32, dim3(32,8)>>>(p_k, p_kTh, p_kTl);
    vsplitT_k<<<dim3(TT/32, DHH/32, BB*HH), dim3(32,32)>>>(p_v, p_vTh, p_vTl);

    att1_k<<<dim3(NCHUNK, BB*HH), 512, ATT_SMEM>>>(p_vTh, p_vTl, p_kTh, p_kTl, p_attp);
    att_reduce_k<<<(BB*HH*DHH*DHH)/256, 256>>>(p_attp, p_ath, p_atl);

    emb_gemm_k<<<dim3((2*DD)/256, BB), 256>>>(p_emba, W_emb, b_emb, p_embout);

    att2_k<<<dim3(MM/128, HH), 512, ATT_SMEM>>>(p_qh, p_ql, p_ath, p_atl, p_y);

    film_k<<<MM, 256>>>(p_y, ln2_w, ln2_b, p_embout, p_acth, p_actl);

    hgemm_k<<<ggrid, 256, HG_SMEM>>>(p_acth, p_actl, p_wth + 3*(size_t)DD*DD, p_wtl + 3*(size_t)DD*DD,
                                     b_out, nullptr, x, out, nullptr, nullptr, 3);
}